// round 8
// baseline (speedup 1.0000x reference)
#include <cuda_runtime.h>

#define DEV_INLINE __device__ __forceinline__
typedef unsigned long long u64;

static constexpr int V  = 32000;
static constexpr int H  = 512;
static constexpr int Bz = 64;
static constexpr int S  = 128;
static constexpr int H2 = 1024;
static constexpr int G4 = 2048;
static constexpr int G8 = 4096;
static constexpr int R  = S * Bz;

// ---------------- scratch ---------------------------------------------------
__device__ float g_X   [R * H];
__device__ float g_GF  [R * G4];
__device__ float g_GB  [R * G4];
__device__ float g_XIN [R * H2];          // row-major, operand of phase D
__device__ float g_XINT[R * H2];          // per t transposed: [t][k][b]
__device__ float g_G1  [R * G8];
__device__ float g_H0T [2 * H * Bz];      // transposed h0f|h0b
__device__ float g_H1T [2 * H2 * Bz];     // ping-pong transposed
__device__ float g_H2T [2 * H2 * Bz];
__device__ float g_H2R [Bz * H2];         // final h2 row-major
__device__ unsigned g_bar0, g_bar1;

// ---------------- helpers ---------------------------------------------------
DEV_INLINE u64 pk2(float x, float y) {
    u64 r; asm("mov.b64 %0, {%1, %2};" : "=l"(r) : "f"(x), "f"(y)); return r;
}
DEV_INLINE float2 upk2(u64 v) {
    float2 r; asm("mov.b64 {%0, %1}, %2;" : "=f"(r.x), "=f"(r.y) : "l"(v)); return r;
}
#define FMA2(d, a, b) asm("fma.rn.f32x2 %0, %1, %2, %0;" : "+l"(d) : "l"(a), "l"(b))
DEV_INLINE float sigf(float x) { return 1.f / (1.f + expf(-x)); }
DEV_INLINE float4 ldcg4(const float* p) { return __ldcg((const float4*)p); }

DEV_INLINE void gbar(unsigned* cnt, unsigned target) {
    __threadfence();
    __syncthreads();
    if (threadIdx.x == 0) {
        atomicAdd(cnt, 1u);
        while (atomicAdd(cnt, 0u) < target) __nanosleep(64);
    }
    __syncthreads();
}

// ---------------- embedding gather ------------------------------------------
__global__ void k_embed(const int* __restrict__ x, const float* __restrict__ emb) {
    int r = blockIdx.x;
    int tok = x[r];
    float4 v = make_float4(0.f, 0.f, 0.f, 0.f);
    if (tok != 0) v = *(const float4*)(emb + (size_t)tok * H + threadIdx.x * 4);
    *(float4*)(g_X + (size_t)r * H + threadIdx.x * 4) = v;
}

// ---------------- init: transpose states, zero barriers ----------------------
__global__ void k_init(const float* __restrict__ h01, const float* __restrict__ h02,
                       const float* __restrict__ h0f, const float* __restrict__ h0b) {
    int i = blockIdx.x * blockDim.x + threadIdx.x;   // 768*256 = 196608
    if (i == 0) { g_bar0 = 0u; g_bar1 = 0u; }
    if (i < 65536) {
        int b = i >> 10, k = i & 1023;
        g_H1T[k * Bz + b] = h01[i];
    } else if (i < 131072) {
        int j = i - 65536, b = j >> 10, k = j & 1023;
        g_H2T[k * Bz + b] = h02[j];
    } else {
        int j = i - 131072, d = j >> 15, r = j & 32767;
        int b = r >> 9, k = r & 511;
        g_H0T[d * (H * Bz) + k * Bz + b] = (d ? h0b : h0f)[r];
    }
}

// ---------------- big batched GEMM (proven) ----------------------------------
template <int BM>
__global__ void k_gemm_bias(const float* __restrict__ A, const float* __restrict__ Wt,
                            const float* __restrict__ b1, const float* __restrict__ b2,
                            float* __restrict__ C, int K, int N) {
    constexpr int BN = 64, BK = 16, RPT = BM / 16;
    __shared__ float As[BK][BM + 4];
    __shared__ float Bs[BK][BN + 4];
    const int tid = threadIdx.x;
    const int bm = blockIdx.y * BM, bn = blockIdx.x * BN;
    const int tx = tid & 15, ty = tid >> 4;
    u64 acc[RPT][2];
#pragma unroll
    for (int r = 0; r < RPT; r++) { acc[r][0] = 0ull; acc[r][1] = 0ull; }
    for (int k0 = 0; k0 < K; k0 += BK) {
#pragma unroll
        for (int i = tid; i < BM * 4; i += 256) {
            int m = i >> 2, kq = i & 3;
            float4 v = *(const float4*)(A + (size_t)(bm + m) * K + k0 + kq * 4);
            As[kq * 4 + 0][m] = v.x; As[kq * 4 + 1][m] = v.y;
            As[kq * 4 + 2][m] = v.z; As[kq * 4 + 3][m] = v.w;
        }
        {
            int n = tid >> 2, kq = tid & 3;
            float4 v = *(const float4*)(Wt + (size_t)(bn + n) * K + k0 + kq * 4);
            Bs[kq * 4 + 0][n] = v.x; Bs[kq * 4 + 1][n] = v.y;
            Bs[kq * 4 + 2][n] = v.z; Bs[kq * 4 + 3][n] = v.w;
        }
        __syncthreads();
#pragma unroll
        for (int kk = 0; kk < BK; kk++) {
            float2 bv0 = *(const float2*)&Bs[kk][tx * 4];
            float2 bv1 = *(const float2*)&Bs[kk][tx * 4 + 2];
            u64 bp0 = pk2(bv0.x, bv0.y), bp1 = pk2(bv1.x, bv1.y);
#pragma unroll
            for (int r = 0; r < RPT; r++) {
                float a = As[kk][ty * RPT + r];
                u64 ap = pk2(a, a);
                FMA2(acc[r][0], ap, bp0);
                FMA2(acc[r][1], ap, bp1);
            }
        }
        __syncthreads();
    }
    const int ncol = bn + tx * 4;
    float bb0 = b1[ncol + 0] + (b2 ? b2[ncol + 0] : 0.f);
    float bb1 = b1[ncol + 1] + (b2 ? b2[ncol + 1] : 0.f);
    float bb2 = b1[ncol + 2] + (b2 ? b2[ncol + 2] : 0.f);
    float bb3 = b1[ncol + 3] + (b2 ? b2[ncol + 3] : 0.f);
#pragma unroll
    for (int r = 0; r < RPT; r++) {
        float2 v0 = upk2(acc[r][0]);
        float2 v1 = upk2(acc[r][1]);
        float4 o = make_float4(v0.x + bb0, v0.y + bb1, v1.x + bb2, v1.y + bb3);
        *(float4*)(C + (size_t)(bm + ty * RPT + r) * N + ncol) = o;
    }
}

// ---------------- persistent layer-0 (512 threads) ---------------------------
// 128 blocks = 64 j-slices x 2 dirs; W slice resident in SMEM; c in a register.
// Each thread: 1 batch row (tid>>3) x 1 j-col (tid&7) x 4 gates.
__global__ void __launch_bounds__(512, 1) k_l0_persist(
        const float* __restrict__ c0f, const float* __restrict__ c0b,
        const float* __restrict__ whh_f, const float* __restrict__ whh_b) {
    extern __shared__ float sm[];
    float* Ws = sm;                 // [512][32]
    float* Hs = sm + 512 * 32;      // [2][64][68]
    const int tid = threadIdx.x;
    const int dir = blockIdx.x >> 6;
    const int j0  = (blockIdx.x & 63) * 8;
    const int tx = tid & 7, b = tid >> 3;
    const int jg = j0 + tx;
    const float* Whh  = dir ? whh_b : whh_f;
    const float* preB = dir ? g_GB  : g_GF;
    const float* c0   = dir ? c0b   : c0f;

    {   // cache W slice once: Ws[k][gj], gj = j*4 + gate
        const int gj = tid & 31, kq = tid >> 5;   // kq in [0,16)
        const float* wr = Whh + (size_t)((gj & 3) * H + j0 + (gj >> 2)) * H + kq * 32;
#pragma unroll
        for (int i = 0; i < 8; i++) {
            float4 v = __ldg((const float4*)(wr + i * 4));
            int k = kq * 32 + i * 4;
            Ws[(k + 0) * 32 + gj] = v.x; Ws[(k + 1) * 32 + gj] = v.y;
            Ws[(k + 2) * 32 + gj] = v.z; Ws[(k + 3) * 32 + gj] = v.w;
        }
    }
    float cst = c0[b * H + jg];
    __syncthreads();

    for (int t = 0; t < S; t++) {
        const float* hT = (t == 0) ? (g_H0T + dir * (H * Bz))
                                   : (g_XINT + ((size_t)(t - 1) * H2 + dir * H) * Bz);
        u64 acc0 = 0ull, acc1 = 0ull;
        float4 hv[2];
#pragma unroll
        for (int i = 0; i < 2; i++) hv[i] = ldcg4(hT + (i * 512 + tid) * 4);
#pragma unroll
        for (int i = 0; i < 2; i++) {
            int f4 = i * 512 + tid;
            *(float4*)&Hs[(f4 >> 4) * 68 + (f4 & 15) * 4] = hv[i];
        }
        __syncthreads();
        for (int kt = 0; kt < 8; kt++) {
            int cur = kt & 1;
            if (kt < 7) {
#pragma unroll
                for (int i = 0; i < 2; i++)
                    hv[i] = ldcg4(hT + ((kt + 1) * 1024 + i * 512 + tid) * 4);
            }
            const float* Hc = Hs + cur * (64 * 68);
            const float* Wk = Ws + kt * 64 * 32;
#pragma unroll 8
            for (int kk = 0; kk < 64; kk++) {
                float a = Hc[kk * 68 + b];
                ulonglong2 w = *(const ulonglong2*)&Wk[kk * 32 + tx * 4];
                u64 ap = pk2(a, a);
                FMA2(acc0, ap, w.x); FMA2(acc1, ap, w.y);
            }
            if (kt < 7) {
                float* Hn = Hs + (cur ^ 1) * (64 * 68);
#pragma unroll
                for (int i = 0; i < 2; i++) {
                    int f4 = i * 512 + tid;
                    *(float4*)&Hn[(f4 >> 4) * 68 + (f4 & 15) * 4] = hv[i];
                }
            }
            __syncthreads();
        }
        // fused gate epilogue (1 row)
        const float* pb = preB + ((size_t)(dir ? (S - 1 - t) : t) * Bz + b) * G4;
        {
            float2 if_ = upk2(acc0);
            float2 go_ = upk2(acc1);
            float gi = if_.x + pb[0 * H + jg];
            float gf = if_.y + pb[1 * H + jg];
            float gg = go_.x + pb[2 * H + jg];
            float go = go_.y + pb[3 * H + jg];
            float c2 = sigf(gf) * cst + sigf(gi) * tanhf(gg);
            cst = c2;
            float h = sigf(go) * tanhf(c2);
            g_XIN [((size_t)t * Bz + b) * H2 + dir * H + jg] = h;
            g_XINT[((size_t)t * H2 + dir * H + jg) * Bz + b] = h;
        }
        gbar(&g_bar0, 128u * (t + 1));
    }
}

// ---------------- layer-1 streaming tile GEMM (K=1024, 512 threads) ----------
DEV_INLINE void l1_gemm(const float* __restrict__ hT, const float* __restrict__ W,
                        int j0, int tid, u64& acc0, u64& acc1,
                        float* Hs, float* Ws) {
    const int tx = tid & 7, b = tid >> 3;
    const int gj = tid & 31, kq = tid >> 5;     // kq in [0,16)
    const float* wrow = W + (size_t)((gj & 3) * H2 + j0 + (gj >> 2)) * H2 + kq * 4;
    float4 hv[2], wv;
#pragma unroll
    for (int i = 0; i < 2; i++) hv[i] = ldcg4(hT + (i * 512 + tid) * 4);
    wv = __ldg((const float4*)wrow);
#pragma unroll
    for (int i = 0; i < 2; i++) {
        int f4 = i * 512 + tid;
        *(float4*)&Hs[(f4 >> 4) * 68 + (f4 & 15) * 4] = hv[i];
    }
    {
        int k = kq * 4;
        Ws[(k + 0) * 32 + gj] = wv.x; Ws[(k + 1) * 32 + gj] = wv.y;
        Ws[(k + 2) * 32 + gj] = wv.z; Ws[(k + 3) * 32 + gj] = wv.w;
    }
    __syncthreads();
    for (int kt = 0; kt < 16; kt++) {
        int cur = kt & 1;
        if (kt < 15) {
#pragma unroll
            for (int i = 0; i < 2; i++)
                hv[i] = ldcg4(hT + ((kt + 1) * 1024 + i * 512 + tid) * 4);
            wv = __ldg((const float4*)(wrow + (kt + 1) * 64));
        }
        const float* Hc = Hs + cur * (64 * 68);
        const float* Wc = Ws + cur * (64 * 32);
#pragma unroll 8
        for (int kk = 0; kk < 64; kk++) {
            float a = Hc[kk * 68 + b];
            ulonglong2 w = *(const ulonglong2*)&Wc[kk * 32 + tx * 4];
            u64 ap = pk2(a, a);
            FMA2(acc0, ap, w.x); FMA2(acc1, ap, w.y);
        }
        if (kt < 15) {
            float* Hn = Hs + (cur ^ 1) * (64 * 68);
            float* Wn = Ws + (cur ^ 1) * (64 * 32);
#pragma unroll
            for (int i = 0; i < 2; i++) {
                int f4 = i * 512 + tid;
                *(float4*)&Hn[(f4 >> 4) * 68 + (f4 & 15) * 4] = hv[i];
            }
            {
                int k = kq * 4;
                Wn[(k + 0) * 32 + gj] = wv.x; Wn[(k + 1) * 32 + gj] = wv.y;
                Wn[(k + 2) * 32 + gj] = wv.z; Wn[(k + 3) * 32 + gj] = wv.w;
            }
        }
        __syncthreads();
    }
}

// ---------------- persistent layer-1 (512 threads, 1 barrier/step) -----------
__global__ void __launch_bounds__(512, 1) k_l1_persist(
        const float* __restrict__ c02,
        const float* __restrict__ whh1, const float* __restrict__ wih2,
        const float* __restrict__ whh2,
        const float* __restrict__ bih2, const float* __restrict__ bhh2) {
    extern __shared__ float sm[];
    float* Ws = sm;                   // [2][64][32]
    float* Hs = sm + 2 * 64 * 32;     // [2][64][68]
    const int tid = threadIdx.x;
    const int j0 = blockIdx.x * 8;
    const int tx = tid & 7, b = tid >> 3;
    const int jg = j0 + tx;

    float c2 = c02[b * H2 + jg];
    float bs[4];
#pragma unroll
    for (int g = 0; g < 4; g++) bs[g] = bih2[g * H2 + jg] + bhh2[g * H2 + jg];

    for (int t = 0; t < S; t++) {
        int p = t & 1;
        const float* h1prev = g_H1T + p * (H2 * Bz);
        float*       h1out  = g_H1T + (p ^ 1) * (H2 * Bz);
        const float* h2prev = g_H2T + p * (H2 * Bz);
        float*       h2out  = g_H2T + (p ^ 1) * (H2 * Bz);

        // ---- lstm1: whh1 @ h1prev, cell input = c2 (own cell discarded) ----
        u64 acc0 = 0ull, acc1 = 0ull;
        l1_gemm(h1prev, whh1, j0, tid, acc0, acc1, Hs, Ws);
        {
            const float* pb = g_G1 + ((size_t)t * Bz + b) * G8;
            float2 if_ = upk2(acc0);
            float2 go_ = upk2(acc1);
            float gi = if_.x + pb[0 * H2 + jg];
            float gf = if_.y + pb[1 * H2 + jg];
            float gg = go_.x + pb[2 * H2 + jg];
            float go = go_.y + pb[3 * H2 + jg];
            float cc = sigf(gf) * c2 + sigf(gi) * tanhf(gg);
            h1out[(size_t)jg * Bz + b] = sigf(go) * tanhf(cc);
        }
        // single grid barrier: publishes h1out(t) (and h2out(t-1), written
        // before this block entered step t)
        gbar(&g_bar1, 128u * (t + 1));

        // ---- lstm2: whh2 @ h2prev + wih2 @ h1new (both post-barrier) ----
        acc0 = 0ull; acc1 = 0ull;
        l1_gemm(h2prev, whh2, j0, tid, acc0, acc1, Hs, Ws);
        l1_gemm(h1out,  wih2, j0, tid, acc0, acc1, Hs, Ws);
        {
            float2 if_ = upk2(acc0);
            float2 go_ = upk2(acc1);
            float gi = if_.x + bs[0];
            float gf = if_.y + bs[1];
            float gg = go_.x + bs[2];
            float go = go_.y + bs[3];
            float cn = sigf(gf) * c2 + sigf(gi) * tanhf(gg);
            c2 = cn;
            float h2v = sigf(go) * tanhf(cn);
            h2out[(size_t)jg * Bz + b] = h2v;
            if (t == S - 1) g_H2R[(size_t)b * H2 + jg] = h2v;
        }
    }
}

// ---------------- launch -----------------------------------------------------
extern "C" void kernel_launch(void* const* d_in, const int* in_sizes, int n_in,
                              void* d_out, int out_size) {
    const int*   x     = (const int*)  d_in[0];
    const float* emb   = (const float*)d_in[1];
    const float* h0f   = (const float*)d_in[2];
    const float* c0f   = (const float*)d_in[3];
    const float* h0b   = (const float*)d_in[4];
    const float* c0b   = (const float*)d_in[5];
    const float* h01   = (const float*)d_in[6];
    const float* h02   = (const float*)d_in[7];
    const float* c02   = (const float*)d_in[8];
    const float* wih_f = (const float*)d_in[9];
    const float* whh_f = (const float*)d_in[10];
    const float* bih_f = (const float*)d_in[11];
    const float* bhh_f = (const float*)d_in[12];
    const float* wih_b = (const float*)d_in[13];
    const float* whh_b = (const float*)d_in[14];
    const float* bih_b = (const float*)d_in[15];
    const float* bhh_b = (const float*)d_in[16];
    const float* wih1  = (const float*)d_in[17];
    const float* whh1  = (const float*)d_in[18];
    const float* bih1  = (const float*)d_in[19];
    const float* bhh1  = (const float*)d_in[20];
    const float* wih2  = (const float*)d_in[21];
    const float* whh2  = (const float*)d_in[22];
    const float* bih2  = (const float*)d_in[23];
    const float* bhh2  = (const float*)d_in[24];
    const float* wlin  = (const float*)d_in[25];
    const float* blin  = (const float*)d_in[26];
    float* out = (float*)d_out;

    float *pX, *pGF, *pGB, *pXIN, *pG1, *pH2R;
    cudaGetSymbolAddress((void**)&pX,   g_X);
    cudaGetSymbolAddress((void**)&pGF,  g_GF);
    cudaGetSymbolAddress((void**)&pGB,  g_GB);
    cudaGetSymbolAddress((void**)&pXIN, g_XIN);
    cudaGetSymbolAddress((void**)&pG1,  g_G1);
    cudaGetSymbolAddress((void**)&pH2R, g_H2R);

    const int L0_SM = (512 * 32 + 2 * 64 * 68) * 4;          // 100352 B
    const int L1_SM = (2 * 64 * 32 + 2 * 64 * 68) * 4;       // 51200 B
    cudaFuncSetAttribute(k_l0_persist, cudaFuncAttributeMaxDynamicSharedMemorySize, L0_SM);
    cudaFuncSetAttribute(k_l1_persist, cudaFuncAttributeMaxDynamicSharedMemorySize, L1_SM);

    // A: gather + init (also zeroes barrier counters each replay)
    k_embed<<<R, 128>>>(x, emb);
    k_init<<<768, 256>>>(h01, h02, h0f, h0b);

    // B: hoisted input-side gate GEMMs for layer 0
    k_gemm_bias<128><<<dim3(G4 / 64, R / 128), 256>>>(pX, wih_f, bih_f, bhh_f, pGF, H, G4);
    k_gemm_bias<128><<<dim3(G4 / 64, R / 128), 256>>>(pX, wih_b, bih_b, bhh_b, pGB, H, G4);

    // C: persistent bidirectional layer-0 recurrence (one launch)
    k_l0_persist<<<128, 512, L0_SM>>>(c0f, c0b, whh_f, whh_b);

    // D: hoisted input-side GEMM for lstm1
    k_gemm_bias<128><<<dim3(G8 / 64, R / 128), 256>>>(pXIN, wih1, bih1, bhh1, pG1, H2, G8);

    // E: persistent layer-1 recurrence (one launch)
    k_l1_persist<<<128, 512, L1_SM>>>(c02, whh1, wih2, whh2, bih2, bhh2);

    // F: logits
    k_gemm_bias<64><<<dim3(V / 64, 1), 256>>>(pH2R, wlin, blin, nullptr, out, H2, V);
}

// round 9
// speedup vs baseline: 1.5213x; 1.5213x over previous
#include <cuda_runtime.h>

#define DEV_INLINE __device__ __forceinline__
typedef unsigned long long u64;

static constexpr int V  = 32000;
static constexpr int H  = 512;
static constexpr int Bz = 64;
static constexpr int S  = 128;
static constexpr int H2 = 1024;
static constexpr int G4 = 2048;
static constexpr int G8 = 4096;
static constexpr int R  = S * Bz;

// ---------------- scratch ---------------------------------------------------
__device__ float g_X   [R * H];
__device__ float g_GF  [R * G4];
__device__ float g_GB  [R * G4];
__device__ float g_XIN [R * H2];          // row-major, operand of phase D
__device__ float g_XINT[R * H2];          // per t transposed: [t][k][b]
__device__ float g_G1  [R * G8];
__device__ float g_H0T [2 * H * Bz];      // transposed h0f|h0b
__device__ float g_H1T [2 * H2 * Bz];     // ping-pong transposed
__device__ float g_H2T [2 * H2 * Bz];
__device__ float g_H2R [Bz * H2];         // final h2 row-major
__device__ unsigned g_bar0[2];            // per-direction l0 barriers
__device__ unsigned g_bar1;

// ---------------- helpers ---------------------------------------------------
DEV_INLINE u64 pk2(float x, float y) {
    u64 r; asm("mov.b64 %0, {%1, %2};" : "=l"(r) : "f"(x), "f"(y)); return r;
}
DEV_INLINE float2 upk2(u64 v) {
    float2 r; asm("mov.b64 {%0, %1}, %2;" : "=f"(r.x), "=f"(r.y) : "l"(v)); return r;
}
#define FMA2(d, a, b) asm("fma.rn.f32x2 %0, %1, %2, %0;" : "+l"(d) : "l"(a), "l"(b))
DEV_INLINE float sigf(float x) { return 1.f / (1.f + expf(-x)); }
DEV_INLINE float4 ldcg4(const float* p) { return __ldcg((const float4*)p); }

// arrival = atomic RMW; poll = plain volatile (L2-coherent) load, no RMW storm
DEV_INLINE void gbar(unsigned* cnt, unsigned target) {
    __threadfence();
    __syncthreads();
    if (threadIdx.x == 0) {
        atomicAdd(cnt, 1u);
        while (*(volatile unsigned*)cnt < target) __nanosleep(32);
    }
    __syncthreads();
}

// ---------------- embedding gather ------------------------------------------
__global__ void k_embed(const int* __restrict__ x, const float* __restrict__ emb) {
    int r = blockIdx.x;
    int tok = x[r];
    float4 v = make_float4(0.f, 0.f, 0.f, 0.f);
    if (tok != 0) v = *(const float4*)(emb + (size_t)tok * H + threadIdx.x * 4);
    *(float4*)(g_X + (size_t)r * H + threadIdx.x * 4) = v;
}

// ---------------- init: transpose states, zero barriers ----------------------
__global__ void k_init(const float* __restrict__ h01, const float* __restrict__ h02,
                       const float* __restrict__ h0f, const float* __restrict__ h0b) {
    int i = blockIdx.x * blockDim.x + threadIdx.x;   // 768*256 = 196608
    if (i == 0) { g_bar0[0] = 0u; g_bar0[1] = 0u; g_bar1 = 0u; }
    if (i < 65536) {
        int b = i >> 10, k = i & 1023;
        g_H1T[k * Bz + b] = h01[i];
    } else if (i < 131072) {
        int j = i - 65536, b = j >> 10, k = j & 1023;
        g_H2T[k * Bz + b] = h02[j];
    } else {
        int j = i - 131072, d = j >> 15, r = j & 32767;
        int b = r >> 9, k = r & 511;
        g_H0T[d * (H * Bz) + k * Bz + b] = (d ? h0b : h0f)[r];
    }
}

// ---------------- big batched GEMM (proven) ----------------------------------
template <int BM>
__global__ void k_gemm_bias(const float* __restrict__ A, const float* __restrict__ Wt,
                            const float* __restrict__ b1, const float* __restrict__ b2,
                            float* __restrict__ C, int K, int N) {
    constexpr int BN = 64, BK = 16, RPT = BM / 16;
    __shared__ float As[BK][BM + 4];
    __shared__ float Bs[BK][BN + 4];
    const int tid = threadIdx.x;
    const int bm = blockIdx.y * BM, bn = blockIdx.x * BN;
    const int tx = tid & 15, ty = tid >> 4;
    u64 acc[RPT][2];
#pragma unroll
    for (int r = 0; r < RPT; r++) { acc[r][0] = 0ull; acc[r][1] = 0ull; }
    for (int k0 = 0; k0 < K; k0 += BK) {
#pragma unroll
        for (int i = tid; i < BM * 4; i += 256) {
            int m = i >> 2, kq = i & 3;
            float4 v = *(const float4*)(A + (size_t)(bm + m) * K + k0 + kq * 4);
            As[kq * 4 + 0][m] = v.x; As[kq * 4 + 1][m] = v.y;
            As[kq * 4 + 2][m] = v.z; As[kq * 4 + 3][m] = v.w;
        }
        {
            int n = tid >> 2, kq = tid & 3;
            float4 v = *(const float4*)(Wt + (size_t)(bn + n) * K + k0 + kq * 4);
            Bs[kq * 4 + 0][n] = v.x; Bs[kq * 4 + 1][n] = v.y;
            Bs[kq * 4 + 2][n] = v.z; Bs[kq * 4 + 3][n] = v.w;
        }
        __syncthreads();
#pragma unroll
        for (int kk = 0; kk < BK; kk++) {
            float2 bv0 = *(const float2*)&Bs[kk][tx * 4];
            float2 bv1 = *(const float2*)&Bs[kk][tx * 4 + 2];
            u64 bp0 = pk2(bv0.x, bv0.y), bp1 = pk2(bv1.x, bv1.y);
#pragma unroll
            for (int r = 0; r < RPT; r++) {
                float a = As[kk][ty * RPT + r];
                u64 ap = pk2(a, a);
                FMA2(acc[r][0], ap, bp0);
                FMA2(acc[r][1], ap, bp1);
            }
        }
        __syncthreads();
    }
    const int ncol = bn + tx * 4;
    float bb0 = b1[ncol + 0] + (b2 ? b2[ncol + 0] : 0.f);
    float bb1 = b1[ncol + 1] + (b2 ? b2[ncol + 1] : 0.f);
    float bb2 = b1[ncol + 2] + (b2 ? b2[ncol + 2] : 0.f);
    float bb3 = b1[ncol + 3] + (b2 ? b2[ncol + 3] : 0.f);
#pragma unroll
    for (int r = 0; r < RPT; r++) {
        float2 v0 = upk2(acc[r][0]);
        float2 v1 = upk2(acc[r][1]);
        float4 o = make_float4(v0.x + bb0, v0.y + bb1, v1.x + bb2, v1.y + bb3);
        *(float4*)(C + (size_t)(bm + ty * RPT + r) * N + ncol) = o;
    }
}

// ---------------- persistent layer-0 ----------------------------------------
// 128 blocks = 64 j-slices x 2 dirs; W slice resident in SMEM; c in registers.
__global__ void __launch_bounds__(256, 1) k_l0_persist(
        const float* __restrict__ c0f, const float* __restrict__ c0b,
        const float* __restrict__ whh_f, const float* __restrict__ whh_b) {
    extern __shared__ float sm[];
    float* Ws = sm;                 // [512][32]
    float* Hs = sm + 512 * 32;      // [2][64][68]
    const int tid = threadIdx.x;
    const int dir = blockIdx.x >> 6;
    const int j0  = (blockIdx.x & 63) * 8;
    const int tx = tid & 7, r0 = (tid >> 3) * 2;
    const int jg = j0 + tx;
    const float* Whh  = dir ? whh_b : whh_f;
    const float* preB = dir ? g_GB  : g_GF;
    const float* c0   = dir ? c0b   : c0f;

    {   // cache W slice once: Ws[k][gj], gj = j*4 + gate
        const int gj = tid & 31, kq = tid >> 5;
        const float* wr = Whh + (size_t)((gj & 3) * H + j0 + (gj >> 2)) * H + kq * 64;
#pragma unroll
        for (int i = 0; i < 16; i++) {
            float4 v = __ldg((const float4*)(wr + i * 4));
            int k = kq * 64 + i * 4;
            Ws[(k + 0) * 32 + gj] = v.x; Ws[(k + 1) * 32 + gj] = v.y;
            Ws[(k + 2) * 32 + gj] = v.z; Ws[(k + 3) * 32 + gj] = v.w;
        }
    }
    float cst[2] = { c0[(r0 + 0) * H + jg], c0[(r0 + 1) * H + jg] };
    __syncthreads();

    for (int t = 0; t < S; t++) {
        const float* hT = (t == 0) ? (g_H0T + dir * (H * Bz))
                                   : (g_XINT + ((size_t)(t - 1) * H2 + dir * H) * Bz);
        // prefetch precomputed input gates (DRAM-latency loads) before the GEMM
        const float* pre = preB + (size_t)(dir ? (S - 1 - t) : t) * Bz * G4;
        float pg[2][4];
#pragma unroll
        for (int r = 0; r < 2; r++) {
            const float* pb = pre + (size_t)(r0 + r) * G4;
            pg[r][0] = __ldg(pb + 0 * H + jg);
            pg[r][1] = __ldg(pb + 1 * H + jg);
            pg[r][2] = __ldg(pb + 2 * H + jg);
            pg[r][3] = __ldg(pb + 3 * H + jg);
        }
        u64 acc[2][2] = {{0ull, 0ull}, {0ull, 0ull}};
        float4 hv[4];
#pragma unroll
        for (int i = 0; i < 4; i++) hv[i] = ldcg4(hT + (i * 256 + tid) * 4);
#pragma unroll
        for (int i = 0; i < 4; i++) {
            int f4 = i * 256 + tid;
            *(float4*)&Hs[(f4 >> 4) * 68 + (f4 & 15) * 4] = hv[i];
        }
        __syncthreads();
        for (int kt = 0; kt < 8; kt++) {
            int cur = kt & 1;
            if (kt < 7) {
#pragma unroll
                for (int i = 0; i < 4; i++)
                    hv[i] = ldcg4(hT + ((kt + 1) * 1024 + i * 256 + tid) * 4);
            }
            const float* Hc = Hs + cur * (64 * 68);
            const float* Wk = Ws + kt * 64 * 32;
#pragma unroll 8
            for (int kk = 0; kk < 64; kk++) {
                float2 a = *(const float2*)&Hc[kk * 68 + r0];
                ulonglong2 w = *(const ulonglong2*)&Wk[kk * 32 + tx * 4];  // LDS.128
                u64 a0 = pk2(a.x, a.x), a1 = pk2(a.y, a.y);
                FMA2(acc[0][0], a0, w.x); FMA2(acc[0][1], a0, w.y);
                FMA2(acc[1][0], a1, w.x); FMA2(acc[1][1], a1, w.y);
            }
            if (kt < 7) {
                float* Hn = Hs + (cur ^ 1) * (64 * 68);
#pragma unroll
                for (int i = 0; i < 4; i++) {
                    int f4 = i * 256 + tid;
                    *(float4*)&Hn[(f4 >> 4) * 68 + (f4 & 15) * 4] = hv[i];
                }
            }
            __syncthreads();
        }
        // fused gate epilogue (uses prefetched pg)
#pragma unroll
        for (int r = 0; r < 2; r++) {
            int b = r0 + r;
            float2 if_ = upk2(acc[r][0]);
            float2 go_ = upk2(acc[r][1]);
            float gi = if_.x + pg[r][0];
            float gf = if_.y + pg[r][1];
            float gg = go_.x + pg[r][2];
            float go = go_.y + pg[r][3];
            float c2 = sigf(gf) * cst[r] + sigf(gi) * tanhf(gg);
            cst[r] = c2;
            float h = sigf(go) * tanhf(c2);
            g_XIN [((size_t)t * Bz + b) * H2 + dir * H + jg] = h;
            g_XINT[((size_t)t * H2 + dir * H + jg) * Bz + b] = h;
        }
        // per-direction barrier: fwd and bwd chains are independent
        gbar(&g_bar0[dir], 64u * (t + 1));
    }
}

// ---------------- layer-1 streaming tile GEMM (K=1024) ------------------------
DEV_INLINE void l1_gemm(const float* __restrict__ hT, const float* __restrict__ W,
                        int j0, int tid, u64 acc[2][2], float* Hs, float* Ws) {
    const int tx = tid & 7, r0 = (tid >> 3) * 2;
    const int gj = tid & 31, kq = tid >> 5;
    const float* wrow = W + (size_t)((gj & 3) * H2 + j0 + (gj >> 2)) * H2 + kq * 8;
    float4 hv[4], wv[2];
#pragma unroll
    for (int i = 0; i < 4; i++) hv[i] = ldcg4(hT + (i * 256 + tid) * 4);
#pragma unroll
    for (int i = 0; i < 2; i++) wv[i] = __ldg((const float4*)(wrow + i * 4));
#pragma unroll
    for (int i = 0; i < 4; i++) {
        int f4 = i * 256 + tid;
        *(float4*)&Hs[(f4 >> 4) * 68 + (f4 & 15) * 4] = hv[i];
    }
#pragma unroll
    for (int i = 0; i < 2; i++) {
        int k = kq * 8 + i * 4;
        Ws[(k + 0) * 32 + gj] = wv[i].x; Ws[(k + 1) * 32 + gj] = wv[i].y;
        Ws[(k + 2) * 32 + gj] = wv[i].z; Ws[(k + 3) * 32 + gj] = wv[i].w;
    }
    __syncthreads();
    for (int kt = 0; kt < 16; kt++) {
        int cur = kt & 1;
        if (kt < 15) {
#pragma unroll
            for (int i = 0; i < 4; i++)
                hv[i] = ldcg4(hT + ((kt + 1) * 1024 + i * 256 + tid) * 4);
#pragma unroll
            for (int i = 0; i < 2; i++)
                wv[i] = __ldg((const float4*)(wrow + (kt + 1) * 64 + i * 4));
        }
        const float* Hc = Hs + cur * (64 * 68);
        const float* Wc = Ws + cur * (64 * 32);
#pragma unroll 8
        for (int kk = 0; kk < 64; kk++) {
            float2 a = *(const float2*)&Hc[kk * 68 + r0];
            ulonglong2 w = *(const ulonglong2*)&Wc[kk * 32 + tx * 4];  // LDS.128
            u64 a0 = pk2(a.x, a.x), a1 = pk2(a.y, a.y);
            FMA2(acc[0][0], a0, w.x); FMA2(acc[0][1], a0, w.y);
            FMA2(acc[1][0], a1, w.x); FMA2(acc[1][1], a1, w.y);
        }
        if (kt < 15) {
            float* Hn = Hs + (cur ^ 1) * (64 * 68);
            float* Wn = Ws + (cur ^ 1) * (64 * 32);
#pragma unroll
            for (int i = 0; i < 4; i++) {
                int f4 = i * 256 + tid;
                *(float4*)&Hn[(f4 >> 4) * 68 + (f4 & 15) * 4] = hv[i];
            }
#pragma unroll
            for (int i = 0; i < 2; i++) {
                int k = kq * 8 + i * 4;
                Wn[(k + 0) * 32 + gj] = wv[i].x; Wn[(k + 1) * 32 + gj] = wv[i].y;
                Wn[(k + 2) * 32 + gj] = wv[i].z; Wn[(k + 3) * 32 + gj] = wv[i].w;
            }
        }
        __syncthreads();
    }
}

// ---------------- persistent layer-1 (one barrier per step) ------------------
// Barrier sits right after the h1out store: it publishes h1out(t) for the
// lstm2 wih2-GEMM, and h2out(t-1)/h1-buffer WARs are all separated by it.
__global__ void __launch_bounds__(256, 1) k_l1_persist(
        const float* __restrict__ c02,
        const float* __restrict__ whh1, const float* __restrict__ wih2,
        const float* __restrict__ whh2,
        const float* __restrict__ bih2, const float* __restrict__ bhh2) {
    extern __shared__ float sm[];
    float* Ws = sm;                   // [2][64][32]
    float* Hs = sm + 2 * 64 * 32;     // [2][64][68]
    const int tid = threadIdx.x;
    const int j0 = blockIdx.x * 8;
    const int tx = tid & 7, r0 = (tid >> 3) * 2;
    const int jg = j0 + tx;

    float c2[2] = { c02[(r0 + 0) * H2 + jg], c02[(r0 + 1) * H2 + jg] };
    float bs[4];
#pragma unroll
    for (int g = 0; g < 4; g++) bs[g] = bih2[g * H2 + jg] + bhh2[g * H2 + jg];

    for (int t = 0; t < S; t++) {
        int p = t & 1;
        const float* h1prev = g_H1T + p * (H2 * Bz);
        float*       h1out  = g_H1T + (p ^ 1) * (H2 * Bz);
        const float* h2prev = g_H2T + p * (H2 * Bz);
        float*       h2out  = g_H2T + (p ^ 1) * (H2 * Bz);

        // prefetch G1 gate rows (DRAM-resident) before the GEMM
        float pg[2][4];
#pragma unroll
        for (int r = 0; r < 2; r++) {
            const float* pb = g_G1 + ((size_t)t * Bz + r0 + r) * G8;
            pg[r][0] = __ldg(pb + 0 * H2 + jg);
            pg[r][1] = __ldg(pb + 1 * H2 + jg);
            pg[r][2] = __ldg(pb + 2 * H2 + jg);
            pg[r][3] = __ldg(pb + 3 * H2 + jg);
        }
        // ---- lstm1: whh1 @ h1prev, cell input = c2 (own cell discarded) ----
        u64 acc[2][2] = {{0ull, 0ull}, {0ull, 0ull}};
        l1_gemm(h1prev, whh1, j0, tid, acc, Hs, Ws);
#pragma unroll
        for (int r = 0; r < 2; r++) {
            int b = r0 + r;
            float2 if_ = upk2(acc[r][0]);
            float2 go_ = upk2(acc[r][1]);
            float gi = if_.x + pg[r][0];
            float gf = if_.y + pg[r][1];
            float gg = go_.x + pg[r][2];
            float go = go_.y + pg[r][3];
            float cc = sigf(gf) * c2[r] + sigf(gi) * tanhf(gg);
            h1out[(size_t)jg * Bz + b] = sigf(go) * tanhf(cc);
        }
        // single grid barrier per step: publishes h1out(t) and h2out(t-1)
        gbar(&g_bar1, 128u * (t + 1));

        // ---- lstm2: whh2 @ h2prev + wih2 @ h1new (both post-barrier) ----
        acc[0][0] = acc[0][1] = acc[1][0] = acc[1][1] = 0ull;
        l1_gemm(h2prev, whh2, j0, tid, acc, Hs, Ws);
        l1_gemm(h1out,  wih2, j0, tid, acc, Hs, Ws);
#pragma unroll
        for (int r = 0; r < 2; r++) {
            int b = r0 + r;
            float2 if_ = upk2(acc[r][0]);
            float2 go_ = upk2(acc[r][1]);
            float gi = if_.x + bs[0];
            float gf = if_.y + bs[1];
            float gg = go_.x + bs[2];
            float go = go_.y + bs[3];
            float cn = sigf(gf) * c2[r] + sigf(gi) * tanhf(gg);
            c2[r] = cn;
            float h2v = sigf(go) * tanhf(cn);
            h2out[(size_t)jg * Bz + b] = h2v;
            if (t == S - 1) g_H2R[(size_t)b * H2 + jg] = h2v;
        }
    }
}

// ---------------- launch -----------------------------------------------------
extern "C" void kernel_launch(void* const* d_in, const int* in_sizes, int n_in,
                              void* d_out, int out_size) {
    const int*   x     = (const int*)  d_in[0];
    const float* emb   = (const float*)d_in[1];
    const float* h0f   = (const float*)d_in[2];
    const float* c0f   = (const float*)d_in[3];
    const float* h0b   = (const float*)d_in[4];
    const float* c0b   = (const float*)d_in[5];
    const float* h01   = (const float*)d_in[6];
    const float* h02   = (const float*)d_in[7];
    const float* c02   = (const float*)d_in[8];
    const float* wih_f = (const float*)d_in[9];
    const float* whh_f = (const float*)d_in[10];
    const float* bih_f = (const float*)d_in[11];
    const float* bhh_f = (const float*)d_in[12];
    const float* wih_b = (const float*)d_in[13];
    const float* whh_b = (const float*)d_in[14];
    const float* bih_b = (const float*)d_in[15];
    const float* bhh_b = (const float*)d_in[16];
    const float* wih1  = (const float*)d_in[17];
    const float* whh1  = (const float*)d_in[18];
    const float* bih1  = (const float*)d_in[19];
    const float* bhh1  = (const float*)d_in[20];
    const float* wih2  = (const float*)d_in[21];
    const float* whh2  = (const float*)d_in[22];
    const float* bih2  = (const float*)d_in[23];
    const float* bhh2  = (const float*)d_in[24];
    const float* wlin  = (const float*)d_in[25];
    const float* blin  = (const float*)d_in[26];
    float* out = (float*)d_out;

    float *pX, *pGF, *pGB, *pXIN, *pG1, *pH2R;
    cudaGetSymbolAddress((void**)&pX,   g_X);
    cudaGetSymbolAddress((void**)&pGF,  g_GF);
    cudaGetSymbolAddress((void**)&pGB,  g_GB);
    cudaGetSymbolAddress((void**)&pXIN, g_XIN);
    cudaGetSymbolAddress((void**)&pG1,  g_G1);
    cudaGetSymbolAddress((void**)&pH2R, g_H2R);

    const int L0_SM = (512 * 32 + 2 * 64 * 68) * 4;          // 100352 B
    const int L1_SM = (2 * 64 * 32 + 2 * 64 * 68) * 4;       // 51200 B
    cudaFuncSetAttribute(k_l0_persist, cudaFuncAttributeMaxDynamicSharedMemorySize, L0_SM);
    cudaFuncSetAttribute(k_l1_persist, cudaFuncAttributeMaxDynamicSharedMemorySize, L1_SM);

    // A: gather + init (also zeroes barrier counters each replay)
    k_embed<<<R, 128>>>(x, emb);
    k_init<<<768, 256>>>(h01, h02, h0f, h0b);

    // B: hoisted input-side gate GEMMs for layer 0
    k_gemm_bias<128><<<dim3(G4 / 64, R / 128), 256>>>(pX, wih_f, bih_f, bhh_f, pGF, H, G4);
    k_gemm_bias<128><<<dim3(G4 / 64, R / 128), 256>>>(pX, wih_b, bih_b, bhh_b, pGB, H, G4);

    // C: persistent bidirectional layer-0 recurrence (one launch)
    k_l0_persist<<<128, 256, L0_SM>>>(c0f, c0b, whh_f, whh_b);

    // D: hoisted input-side GEMM for lstm1
    k_gemm_bias<128><<<dim3(G8 / 64, R / 128), 256>>>(pXIN, wih1, bih1, bhh1, pG1, H2, G8);

    // E: persistent layer-1 recurrence (one launch)
    k_l1_persist<<<128, 256, L1_SM>>>(c02, whh1, wih2, whh2, bih2, bhh2);

    // F: logits
    k_gemm_bias<64><<<dim3(V / 64, 1), 256>>>(pH2R, wlin, blin, nullptr, out, H2, V);
}

// round 10
// speedup vs baseline: 1.5220x; 1.0004x over previous
#include <cuda_runtime.h>

#define DEV_INLINE __device__ __forceinline__
typedef unsigned long long u64;

static constexpr int V  = 32000;
static constexpr int H  = 512;
static constexpr int Bz = 64;
static constexpr int S  = 128;
static constexpr int H2 = 1024;
static constexpr int G4 = 2048;
static constexpr int G8 = 4096;
static constexpr int R  = S * Bz;

// ---------------- scratch ---------------------------------------------------
__device__ float g_X   [R * H];
__device__ float g_GF  [R * G4];
__device__ float g_GB  [R * G4];
__device__ float g_XIN [R * H2];          // row-major, operand of phase D
__device__ float g_XINT[R * H2];          // per t transposed: [t][k][b]
__device__ float g_G1  [R * G8];
__device__ float g_H0T [2 * H * Bz];      // transposed h0f|h0b
__device__ float g_H1T [2 * H2 * Bz];     // ping-pong transposed
__device__ float g_H2T [2 * H2 * Bz];
__device__ float g_H2R [Bz * H2];         // final h2 row-major
__device__ unsigned g_bar0[2];            // per-direction l0 barriers
__device__ unsigned g_bar1;

// ---------------- helpers ---------------------------------------------------
DEV_INLINE u64 pk2(float x, float y) {
    u64 r; asm("mov.b64 %0, {%1, %2};" : "=l"(r) : "f"(x), "f"(y)); return r;
}
DEV_INLINE float2 upk2(u64 v) {
    float2 r; asm("mov.b64 {%0, %1}, %2;" : "=f"(r.x), "=f"(r.y) : "l"(v)); return r;
}
#define FMA2(d, a, b) asm("fma.rn.f32x2 %0, %1, %2, %0;" : "+l"(d) : "l"(a), "l"(b))
DEV_INLINE float sigf(float x) { return 1.f / (1.f + expf(-x)); }
DEV_INLINE float4 ldcg4(const float* p) { return __ldcg((const float4*)p); }

// arrival = atomic RMW; poll = plain volatile (L2-coherent) load, no RMW storm
DEV_INLINE void gbar(unsigned* cnt, unsigned target) {
    __threadfence();
    __syncthreads();
    if (threadIdx.x == 0) {
        atomicAdd(cnt, 1u);
        while (*(volatile unsigned*)cnt < target) __nanosleep(32);
    }
    __syncthreads();
}

// ---------------- embedding gather ------------------------------------------
__global__ void k_embed(const int* __restrict__ x, const float* __restrict__ emb) {
    int r = blockIdx.x;
    int tok = x[r];
    float4 v = make_float4(0.f, 0.f, 0.f, 0.f);
    if (tok != 0) v = *(const float4*)(emb + (size_t)tok * H + threadIdx.x * 4);
    *(float4*)(g_X + (size_t)r * H + threadIdx.x * 4) = v;
}

// ---------------- init: transpose states, zero barriers ----------------------
__global__ void k_init(const float* __restrict__ h01, const float* __restrict__ h02,
                       const float* __restrict__ h0f, const float* __restrict__ h0b) {
    int i = blockIdx.x * blockDim.x + threadIdx.x;   // 768*256 = 196608
    if (i == 0) { g_bar0[0] = 0u; g_bar0[1] = 0u; g_bar1 = 0u; }
    if (i < 65536) {
        int b = i >> 10, k = i & 1023;
        g_H1T[k * Bz + b] = h01[i];
    } else if (i < 131072) {
        int j = i - 65536, b = j >> 10, k = j & 1023;
        g_H2T[k * Bz + b] = h02[j];
    } else {
        int j = i - 131072, d = j >> 15, r = j & 32767;
        int b = r >> 9, k = r & 511;
        g_H0T[d * (H * Bz) + k * Bz + b] = (d ? h0b : h0f)[r];
    }
}

// ---------------- big batched GEMM (proven) ----------------------------------
template <int BM>
__global__ void k_gemm_bias(const float* __restrict__ A, const float* __restrict__ Wt,
                            const float* __restrict__ b1, const float* __restrict__ b2,
                            float* __restrict__ C, int K, int N) {
    constexpr int BN = 64, BK = 16, RPT = BM / 16;
    __shared__ float As[BK][BM + 4];
    __shared__ float Bs[BK][BN + 4];
    const int tid = threadIdx.x;
    const int bm = blockIdx.y * BM, bn = blockIdx.x * BN;
    const int tx = tid & 15, ty = tid >> 4;
    u64 acc[RPT][2];
#pragma unroll
    for (int r = 0; r < RPT; r++) { acc[r][0] = 0ull; acc[r][1] = 0ull; }
    for (int k0 = 0; k0 < K; k0 += BK) {
#pragma unroll
        for (int i = tid; i < BM * 4; i += 256) {
            int m = i >> 2, kq = i & 3;
            float4 v = *(const float4*)(A + (size_t)(bm + m) * K + k0 + kq * 4);
            As[kq * 4 + 0][m] = v.x; As[kq * 4 + 1][m] = v.y;
            As[kq * 4 + 2][m] = v.z; As[kq * 4 + 3][m] = v.w;
        }
        {
            int n = tid >> 2, kq = tid & 3;
            float4 v = *(const float4*)(Wt + (size_t)(bn + n) * K + k0 + kq * 4);
            Bs[kq * 4 + 0][n] = v.x; Bs[kq * 4 + 1][n] = v.y;
            Bs[kq * 4 + 2][n] = v.z; Bs[kq * 4 + 3][n] = v.w;
        }
        __syncthreads();
#pragma unroll
        for (int kk = 0; kk < BK; kk++) {
            float2 bv0 = *(const float2*)&Bs[kk][tx * 4];
            float2 bv1 = *(const float2*)&Bs[kk][tx * 4 + 2];
            u64 bp0 = pk2(bv0.x, bv0.y), bp1 = pk2(bv1.x, bv1.y);
#pragma unroll
            for (int r = 0; r < RPT; r++) {
                float a = As[kk][ty * RPT + r];
                u64 ap = pk2(a, a);
                FMA2(acc[r][0], ap, bp0);
                FMA2(acc[r][1], ap, bp1);
            }
        }
        __syncthreads();
    }
    const int ncol = bn + tx * 4;
    float bb0 = b1[ncol + 0] + (b2 ? b2[ncol + 0] : 0.f);
    float bb1 = b1[ncol + 1] + (b2 ? b2[ncol + 1] : 0.f);
    float bb2 = b1[ncol + 2] + (b2 ? b2[ncol + 2] : 0.f);
    float bb3 = b1[ncol + 3] + (b2 ? b2[ncol + 3] : 0.f);
#pragma unroll
    for (int r = 0; r < RPT; r++) {
        float2 v0 = upk2(acc[r][0]);
        float2 v1 = upk2(acc[r][1]);
        float4 o = make_float4(v0.x + bb0, v0.y + bb1, v1.x + bb2, v1.y + bb3);
        *(float4*)(C + (size_t)(bm + ty * RPT + r) * N + ncol) = o;
    }
}

// ---------------- persistent layer-0 ----------------------------------------
// 128 blocks = 64 j-slices x 2 dirs; W slice resident in SMEM; c in registers.
__global__ void __launch_bounds__(256, 1) k_l0_persist(
        const float* __restrict__ c0f, const float* __restrict__ c0b,
        const float* __restrict__ whh_f, const float* __restrict__ whh_b) {
    extern __shared__ float sm[];
    float* Ws = sm;                 // [512][32]
    float* Hs = sm + 512 * 32;      // [2][64][68]
    const int tid = threadIdx.x;
    const int dir = blockIdx.x >> 6;
    const int j0  = (blockIdx.x & 63) * 8;
    const int tx = tid & 7, r0 = (tid >> 3) * 2;
    const int jg = j0 + tx;
    const float* Whh  = dir ? whh_b : whh_f;
    const float* preB = dir ? g_GB  : g_GF;
    const float* c0   = dir ? c0b   : c0f;

    {   // cache W slice once: Ws[k][gj], gj = j*4 + gate
        const int gj = tid & 31, kq = tid >> 5;
        const float* wr = Whh + (size_t)((gj & 3) * H + j0 + (gj >> 2)) * H + kq * 64;
#pragma unroll
        for (int i = 0; i < 16; i++) {
            float4 v = __ldg((const float4*)(wr + i * 4));
            int k = kq * 64 + i * 4;
            Ws[(k + 0) * 32 + gj] = v.x; Ws[(k + 1) * 32 + gj] = v.y;
            Ws[(k + 2) * 32 + gj] = v.z; Ws[(k + 3) * 32 + gj] = v.w;
        }
    }
    float cst[2] = { c0[(r0 + 0) * H + jg], c0[(r0 + 1) * H + jg] };
    __syncthreads();

    for (int t = 0; t < S; t++) {
        const float* hT = (t == 0) ? (g_H0T + dir * (H * Bz))
                                   : (g_XINT + ((size_t)(t - 1) * H2 + dir * H) * Bz);
        // prefetch precomputed input gates (DRAM-latency loads) before the GEMM
        const float* pre = preB + (size_t)(dir ? (S - 1 - t) : t) * Bz * G4;
        float pg[2][4];
#pragma unroll
        for (int r = 0; r < 2; r++) {
            const float* pb = pre + (size_t)(r0 + r) * G4;
            pg[r][0] = __ldg(pb + 0 * H + jg);
            pg[r][1] = __ldg(pb + 1 * H + jg);
            pg[r][2] = __ldg(pb + 2 * H + jg);
            pg[r][3] = __ldg(pb + 3 * H + jg);
        }
        u64 acc[2][2] = {{0ull, 0ull}, {0ull, 0ull}};
        float4 hv[4];
#pragma unroll
        for (int i = 0; i < 4; i++) hv[i] = ldcg4(hT + (i * 256 + tid) * 4);
#pragma unroll
        for (int i = 0; i < 4; i++) {
            int f4 = i * 256 + tid;
            *(float4*)&Hs[(f4 >> 4) * 68 + (f4 & 15) * 4] = hv[i];
        }
        __syncthreads();
        for (int kt = 0; kt < 8; kt++) {
            int cur = kt & 1;
            if (kt < 7) {
#pragma unroll
                for (int i = 0; i < 4; i++)
                    hv[i] = ldcg4(hT + ((kt + 1) * 1024 + i * 256 + tid) * 4);
            }
            const float* Hc = Hs + cur * (64 * 68);
            const float* Wk = Ws + kt * 64 * 32;
#pragma unroll 8
            for (int kk = 0; kk < 64; kk++) {
                float2 a = *(const float2*)&Hc[kk * 68 + r0];
                ulonglong2 w = *(const ulonglong2*)&Wk[kk * 32 + tx * 4];  // LDS.128
                u64 a0 = pk2(a.x, a.x), a1 = pk2(a.y, a.y);
                FMA2(acc[0][0], a0, w.x); FMA2(acc[0][1], a0, w.y);
                FMA2(acc[1][0], a1, w.x); FMA2(acc[1][1], a1, w.y);
            }
            if (kt < 7) {
                float* Hn = Hs + (cur ^ 1) * (64 * 68);
#pragma unroll
                for (int i = 0; i < 4; i++) {
                    int f4 = i * 256 + tid;
                    *(float4*)&Hn[(f4 >> 4) * 68 + (f4 & 15) * 4] = hv[i];
                }
            }
            __syncthreads();
        }
        // fused gate epilogue (uses prefetched pg)
#pragma unroll
        for (int r = 0; r < 2; r++) {
            int b = r0 + r;
            float2 if_ = upk2(acc[r][0]);
            float2 go_ = upk2(acc[r][1]);
            float gi = if_.x + pg[r][0];
            float gf = if_.y + pg[r][1];
            float gg = go_.x + pg[r][2];
            float go = go_.y + pg[r][3];
            float c2 = sigf(gf) * cst[r] + sigf(gi) * tanhf(gg);
            cst[r] = c2;
            float h = sigf(go) * tanhf(c2);
            g_XIN [((size_t)t * Bz + b) * H2 + dir * H + jg] = h;
            g_XINT[((size_t)t * H2 + dir * H + jg) * Bz + b] = h;
        }
        // per-direction barrier: fwd and bwd chains are independent
        gbar(&g_bar0[dir], 64u * (t + 1));
    }
}

// ---------------- layer-1 streaming tile GEMM (K=1024) ------------------------
DEV_INLINE void l1_gemm(const float* __restrict__ hT, const float* __restrict__ W,
                        int j0, int tid, u64 acc[2][2], float* Hs, float* Ws) {
    const int tx = tid & 7, r0 = (tid >> 3) * 2;
    const int gj = tid & 31, kq = tid >> 5;
    const float* wrow = W + (size_t)((gj & 3) * H2 + j0 + (gj >> 2)) * H2 + kq * 8;
    float4 hv[4], wv[2];
#pragma unroll
    for (int i = 0; i < 4; i++) hv[i] = ldcg4(hT + (i * 256 + tid) * 4);
#pragma unroll
    for (int i = 0; i < 2; i++) wv[i] = __ldg((const float4*)(wrow + i * 4));
#pragma unroll
    for (int i = 0; i < 4; i++) {
        int f4 = i * 256 + tid;
        *(float4*)&Hs[(f4 >> 4) * 68 + (f4 & 15) * 4] = hv[i];
    }
#pragma unroll
    for (int i = 0; i < 2; i++) {
        int k = kq * 8 + i * 4;
        Ws[(k + 0) * 32 + gj] = wv[i].x; Ws[(k + 1) * 32 + gj] = wv[i].y;
        Ws[(k + 2) * 32 + gj] = wv[i].z; Ws[(k + 3) * 32 + gj] = wv[i].w;
    }
    __syncthreads();
    for (int kt = 0; kt < 16; kt++) {
        int cur = kt & 1;
        if (kt < 15) {
#pragma unroll
            for (int i = 0; i < 4; i++)
                hv[i] = ldcg4(hT + ((kt + 1) * 1024 + i * 256 + tid) * 4);
#pragma unroll
            for (int i = 0; i < 2; i++)
                wv[i] = __ldg((const float4*)(wrow + (kt + 1) * 64 + i * 4));
        }
        const float* Hc = Hs + cur * (64 * 68);
        const float* Wc = Ws + cur * (64 * 32);
#pragma unroll 8
        for (int kk = 0; kk < 64; kk++) {
            float2 a = *(const float2*)&Hc[kk * 68 + r0];
            ulonglong2 w = *(const ulonglong2*)&Wc[kk * 32 + tx * 4];  // LDS.128
            u64 a0 = pk2(a.x, a.x), a1 = pk2(a.y, a.y);
            FMA2(acc[0][0], a0, w.x); FMA2(acc[0][1], a0, w.y);
            FMA2(acc[1][0], a1, w.x); FMA2(acc[1][1], a1, w.y);
        }
        if (kt < 15) {
            float* Hn = Hs + (cur ^ 1) * (64 * 68);
            float* Wn = Ws + (cur ^ 1) * (64 * 32);
#pragma unroll
            for (int i = 0; i < 4; i++) {
                int f4 = i * 256 + tid;
                *(float4*)&Hn[(f4 >> 4) * 68 + (f4 & 15) * 4] = hv[i];
            }
#pragma unroll
            for (int i = 0; i < 2; i++) {
                int k = kq * 8 + i * 4;
                Wn[(k + 0) * 32 + gj] = wv[i].x; Wn[(k + 1) * 32 + gj] = wv[i].y;
                Wn[(k + 2) * 32 + gj] = wv[i].z; Wn[(k + 3) * 32 + gj] = wv[i].w;
            }
        }
        __syncthreads();
    }
}

// ---------------- persistent layer-1 (one barrier per step) ------------------
// Barrier sits right after the h1out store: it publishes h1out(t) for the
// lstm2 wih2-GEMM, and h2out(t-1)/h1-buffer WARs are all separated by it.
__global__ void __launch_bounds__(256, 1) k_l1_persist(
        const float* __restrict__ c02,
        const float* __restrict__ whh1, const float* __restrict__ wih2,
        const float* __restrict__ whh2,
        const float* __restrict__ bih2, const float* __restrict__ bhh2) {
    extern __shared__ float sm[];
    float* Ws = sm;                   // [2][64][32]
    float* Hs = sm + 2 * 64 * 32;     // [2][64][68]
    const int tid = threadIdx.x;
    const int j0 = blockIdx.x * 8;
    const int tx = tid & 7, r0 = (tid >> 3) * 2;
    const int jg = j0 + tx;

    float c2[2] = { c02[(r0 + 0) * H2 + jg], c02[(r0 + 1) * H2 + jg] };
    float bs[4];
#pragma unroll
    for (int g = 0; g < 4; g++) bs[g] = bih2[g * H2 + jg] + bhh2[g * H2 + jg];

    for (int t = 0; t < S; t++) {
        int p = t & 1;
        const float* h1prev = g_H1T + p * (H2 * Bz);
        float*       h1out  = g_H1T + (p ^ 1) * (H2 * Bz);
        const float* h2prev = g_H2T + p * (H2 * Bz);
        float*       h2out  = g_H2T + (p ^ 1) * (H2 * Bz);

        // prefetch G1 gate rows (DRAM-resident) before the GEMM
        float pg[2][4];
#pragma unroll
        for (int r = 0; r < 2; r++) {
            const float* pb = g_G1 + ((size_t)t * Bz + r0 + r) * G8;
            pg[r][0] = __ldg(pb + 0 * H2 + jg);
            pg[r][1] = __ldg(pb + 1 * H2 + jg);
            pg[r][2] = __ldg(pb + 2 * H2 + jg);
            pg[r][3] = __ldg(pb + 3 * H2 + jg);
        }
        // ---- lstm1: whh1 @ h1prev, cell input = c2 (own cell discarded) ----
        u64 acc[2][2] = {{0ull, 0ull}, {0ull, 0ull}};
        l1_gemm(h1prev, whh1, j0, tid, acc, Hs, Ws);
#pragma unroll
        for (int r = 0; r < 2; r++) {
            int b = r0 + r;
            float2 if_ = upk2(acc[r][0]);
            float2 go_ = upk2(acc[r][1]);
            float gi = if_.x + pg[r][0];
            float gf = if_.y + pg[r][1];
            float gg = go_.x + pg[r][2];
            float go = go_.y + pg[r][3];
            float cc = sigf(gf) * c2[r] + sigf(gi) * tanhf(gg);
            h1out[(size_t)jg * Bz + b] = sigf(go) * tanhf(cc);
        }
        // single grid barrier per step: publishes h1out(t) and h2out(t-1)
        gbar(&g_bar1, 128u * (t + 1));

        // ---- lstm2: whh2 @ h2prev + wih2 @ h1new (both post-barrier) ----
        acc[0][0] = acc[0][1] = acc[1][0] = acc[1][1] = 0ull;
        l1_gemm(h2prev, whh2, j0, tid, acc, Hs, Ws);
        l1_gemm(h1out,  wih2, j0, tid, acc, Hs, Ws);
#pragma unroll
        for (int r = 0; r < 2; r++) {
            int b = r0 + r;
            float2 if_ = upk2(acc[r][0]);
            float2 go_ = upk2(acc[r][1]);
            float gi = if_.x + bs[0];
            float gf = if_.y + bs[1];
            float gg = go_.x + bs[2];
            float go = go_.y + bs[3];
            float cn = sigf(gf) * c2[r] + sigf(gi) * tanhf(gg);
            c2[r] = cn;
            float h2v = sigf(go) * tanhf(cn);
            h2out[(size_t)jg * Bz + b] = h2v;
            if (t == S - 1) g_H2R[(size_t)b * H2 + jg] = h2v;
        }
    }
}

// ---------------- launch -----------------------------------------------------
extern "C" void kernel_launch(void* const* d_in, const int* in_sizes, int n_in,
                              void* d_out, int out_size) {
    const int*   x     = (const int*)  d_in[0];
    const float* emb   = (const float*)d_in[1];
    const float* h0f   = (const float*)d_in[2];
    const float* c0f   = (const float*)d_in[3];
    const float* h0b   = (const float*)d_in[4];
    const float* c0b   = (const float*)d_in[5];
    const float* h01   = (const float*)d_in[6];
    const float* h02   = (const float*)d_in[7];
    const float* c02   = (const float*)d_in[8];
    const float* wih_f = (const float*)d_in[9];
    const float* whh_f = (const float*)d_in[10];
    const float* bih_f = (const float*)d_in[11];
    const float* bhh_f = (const float*)d_in[12];
    const float* wih_b = (const float*)d_in[13];
    const float* whh_b = (const float*)d_in[14];
    const float* bih_b = (const float*)d_in[15];
    const float* bhh_b = (const float*)d_in[16];
    const float* wih1  = (const float*)d_in[17];
    const float* whh1  = (const float*)d_in[18];
    const float* bih1  = (const float*)d_in[19];
    const float* bhh1  = (const float*)d_in[20];
    const float* wih2  = (const float*)d_in[21];
    const float* whh2  = (const float*)d_in[22];
    const float* bih2  = (const float*)d_in[23];
    const float* bhh2  = (const float*)d_in[24];
    const float* wlin  = (const float*)d_in[25];
    const float* blin  = (const float*)d_in[26];
    float* out = (float*)d_out;

    float *pX, *pGF, *pGB, *pXIN, *pG1, *pH2R;
    cudaGetSymbolAddress((void**)&pX,   g_X);
    cudaGetSymbolAddress((void**)&pGF,  g_GF);
    cudaGetSymbolAddress((void**)&pGB,  g_GB);
    cudaGetSymbolAddress((void**)&pXIN, g_XIN);
    cudaGetSymbolAddress((void**)&pG1,  g_G1);
    cudaGetSymbolAddress((void**)&pH2R, g_H2R);

    const int L0_SM = (512 * 32 + 2 * 64 * 68) * 4;          // 100352 B
    const int L1_SM = (2 * 64 * 32 + 2 * 64 * 68) * 4;       // 51200 B
    cudaFuncSetAttribute(k_l0_persist, cudaFuncAttributeMaxDynamicSharedMemorySize, L0_SM);
    cudaFuncSetAttribute(k_l1_persist, cudaFuncAttributeMaxDynamicSharedMemorySize, L1_SM);

    // A: gather + init (also zeroes barrier counters each replay)
    k_embed<<<R, 128>>>(x, emb);
    k_init<<<768, 256>>>(h01, h02, h0f, h0b);

    // B: hoisted input-side gate GEMMs for layer 0
    k_gemm_bias<128><<<dim3(G4 / 64, R / 128), 256>>>(pX, wih_f, bih_f, bhh_f, pGF, H, G4);
    k_gemm_bias<128><<<dim3(G4 / 64, R / 128), 256>>>(pX, wih_b, bih_b, bhh_b, pGB, H, G4);

    // C: persistent bidirectional layer-0 recurrence (one launch)
    k_l0_persist<<<128, 256, L0_SM>>>(c0f, c0b, whh_f, whh_b);

    // D: hoisted input-side GEMM for lstm1
    k_gemm_bias<128><<<dim3(G8 / 64, R / 128), 256>>>(pXIN, wih1, bih1, bhh1, pG1, H2, G8);

    // E: persistent layer-1 recurrence (one launch)
    k_l1_persist<<<128, 256, L1_SM>>>(c02, whh1, wih2, whh2, bih2, bhh2);

    // F: logits
    k_gemm_bias<64><<<dim3(V / 64, 1), 256>>>(pH2R, wlin, blin, nullptr, out, H2, V);
}

// round 12
// speedup vs baseline: 2.9092x; 1.9114x over previous
#include <cuda_runtime.h>
#include <cuda_bf16.h>
#include <cstdint>

#define DEV_INLINE __device__ __forceinline__
typedef unsigned long long u64;

static constexpr int V  = 32000;
static constexpr int H  = 512;
static constexpr int Bz = 64;
static constexpr int S  = 128;
static constexpr int H2 = 1024;
static constexpr int G4 = 2048;
static constexpr int G8 = 4096;
static constexpr int R  = S * Bz;

// ---------------- scratch ---------------------------------------------------
__device__ float g_X   [R * H];
__device__ float g_GF  [R * G4];
__device__ float g_GB  [R * G4];
__device__ float g_XIN [R * H2];
__device__ float g_XINT[R * H2];
__device__ float g_G1  [R * G8];
__device__ float g_H0T [2 * H * Bz];
__device__ float g_H2R [Bz * H2];
// bf16 split weights: [mat][block][hi|lo][32 gate-rows][1024 k]
__device__ __nv_bfloat16 g_Wb [3][128][2][32][1024];
// bf16 split states, ping-pong: [pp][hi|lo][64 b][1024 k]
__device__ __nv_bfloat16 g_H1s[2][2][Bz][H2];
__device__ __nv_bfloat16 g_H2s[2][2][Bz][H2];
__device__ unsigned g_bar0[2];
__device__ unsigned g_bar1;

// ---------------- helpers ---------------------------------------------------
DEV_INLINE u64 pk2(float x, float y) {
    u64 r; asm("mov.b64 %0, {%1, %2};" : "=l"(r) : "f"(x), "f"(y)); return r;
}
DEV_INLINE float2 upk2(u64 v) {
    float2 r; asm("mov.b64 {%0, %1}, %2;" : "=f"(r.x), "=f"(r.y) : "l"(v)); return r;
}
#define FMA2(d, a, b) asm("fma.rn.f32x2 %0, %1, %2, %0;" : "+l"(d) : "l"(a), "l"(b))
DEV_INLINE float sigf(float x) { return 1.f / (1.f + expf(-x)); }
DEV_INLINE float4 ldcg4(const float* p) { return __ldcg((const float4*)p); }

DEV_INLINE void gbar(unsigned* cnt, unsigned target) {
    __threadfence();
    __syncthreads();
    if (threadIdx.x == 0) {
        atomicAdd(cnt, 1u);
        while (*(volatile unsigned*)cnt < target) __nanosleep(32);
    }
    __syncthreads();
}

DEV_INLINE uint32_t smem_u32(const void* p) {
    uint32_t a;
    asm("{ .reg .u64 t; cvta.to.shared.u64 t, %1; cvt.u32.u64 %0, t; }" : "=r"(a) : "l"(p));
    return a;
}
DEV_INLINE void cpa16(uint32_t dst, const void* src) {
    asm volatile("cp.async.cg.shared.global [%0], [%1], 16;" :: "r"(dst), "l"(src) : "memory");
}
#define CP_COMMIT() asm volatile("cp.async.commit_group;" ::: "memory")
template <int N> DEV_INLINE void cp_wait() {
    asm volatile("cp.async.wait_group %0;" :: "n"(N) : "memory");
}
DEV_INLINE void ldsm_x4(uint32_t& a0, uint32_t& a1, uint32_t& a2, uint32_t& a3, uint32_t ad) {
    asm volatile("ldmatrix.sync.aligned.m8n8.x4.shared.b16 {%0,%1,%2,%3}, [%4];"
                 : "=r"(a0), "=r"(a1), "=r"(a2), "=r"(a3) : "r"(ad));
}
DEV_INLINE void ldsm_x2(uint32_t& b0, uint32_t& b1, uint32_t ad) {
    asm volatile("ldmatrix.sync.aligned.m8n8.x2.shared.b16 {%0,%1}, [%2];"
                 : "=r"(b0), "=r"(b1) : "r"(ad));
}
DEV_INLINE void mma16816(float* c, uint32_t a0, uint32_t a1, uint32_t a2, uint32_t a3,
                         uint32_t b0, uint32_t b1) {
    asm volatile("mma.sync.aligned.m16n8k16.row.col.f32.bf16.bf16.f32 "
                 "{%0,%1,%2,%3}, {%4,%5,%6,%7}, {%8,%9}, {%0,%1,%2,%3};"
                 : "+f"(c[0]), "+f"(c[1]), "+f"(c[2]), "+f"(c[3])
                 : "r"(a0), "r"(a1), "r"(a2), "r"(a3), "r"(b0), "r"(b1));
}

// ---------------- small kernels ----------------------------------------------
__global__ void k_embed(const int* __restrict__ x, const float* __restrict__ emb) {
    int r = blockIdx.x;
    int tok = x[r];
    float4 v = make_float4(0.f, 0.f, 0.f, 0.f);
    if (tok != 0) v = *(const float4*)(emb + (size_t)tok * H + threadIdx.x * 4);
    *(float4*)(g_X + (size_t)r * H + threadIdx.x * 4) = v;
}

__global__ void k_init(const float* __restrict__ h0f, const float* __restrict__ h0b) {
    int i = blockIdx.x * blockDim.x + threadIdx.x;   // 256*256 = 65536
    if (i == 0) { g_bar0[0] = 0u; g_bar0[1] = 0u; g_bar1 = 0u; }
    int d = i >> 15, r = i & 32767;
    int b = r >> 9, k = r & 511;
    g_H0T[d * (H * Bz) + k * Bz + b] = (d ? h0b : h0f)[r];
}

__global__ void k_prep_w(const float* __restrict__ whh1, const float* __restrict__ whh2,
                         const float* __restrict__ wih2) {
    int mr = blockIdx.x;                     // [0, 3*4096)
    int mat = mr >> 12, r = mr & 4095;
    const float* W = mat == 0 ? whh1 : (mat == 1 ? whh2 : wih2);
    int g = r >> 10, jglob = r & 1023;
    int bx = jglob >> 3, gr = g * 8 + (jglob & 7);
    const float* src = W + (size_t)r * H2;
#pragma unroll
    for (int q = 0; q < 4; q++) {
        int k = threadIdx.x + q * 256;
        float w = src[k];
        __nv_bfloat16 hi = __float2bfloat16(w);
        __nv_bfloat16 lo = __float2bfloat16(w - __bfloat162float(hi));
        g_Wb[mat][bx][0][gr][k] = hi;
        g_Wb[mat][bx][1][gr][k] = lo;
    }
}

__global__ void k_prep_h(const float* __restrict__ h01, const float* __restrict__ h02) {
    int i = blockIdx.x * 256 + threadIdx.x;  // [0, 131072)
    int which = i >> 16, e = i & 65535;
    int b = e >> 10, k = e & 1023;
    float v = (which ? h02 : h01)[e];
    __nv_bfloat16 hi = __float2bfloat16(v);
    __nv_bfloat16 lo = __float2bfloat16(v - __bfloat162float(hi));
    if (which) { g_H2s[0][0][b][k] = hi; g_H2s[0][1][b][k] = lo; }
    else       { g_H1s[0][0][b][k] = hi; g_H1s[0][1][b][k] = lo; }
}

// ---------------- big batched GEMM (proven) ----------------------------------
template <int BM>
__global__ void k_gemm_bias(const float* __restrict__ A, const float* __restrict__ Wt,
                            const float* __restrict__ b1, const float* __restrict__ b2,
                            float* __restrict__ C, int K, int N) {
    constexpr int BN = 64, BK = 16, RPT = BM / 16;
    __shared__ float As[BK][BM + 4];
    __shared__ float Bs[BK][BN + 4];
    const int tid = threadIdx.x;
    const int bm = blockIdx.y * BM, bn = blockIdx.x * BN;
    const int tx = tid & 15, ty = tid >> 4;
    u64 acc[RPT][2];
#pragma unroll
    for (int r = 0; r < RPT; r++) { acc[r][0] = 0ull; acc[r][1] = 0ull; }
    for (int k0 = 0; k0 < K; k0 += BK) {
#pragma unroll
        for (int i = tid; i < BM * 4; i += 256) {
            int m = i >> 2, kq = i & 3;
            float4 v = *(const float4*)(A + (size_t)(bm + m) * K + k0 + kq * 4);
            As[kq * 4 + 0][m] = v.x; As[kq * 4 + 1][m] = v.y;
            As[kq * 4 + 2][m] = v.z; As[kq * 4 + 3][m] = v.w;
        }
        {
            int n = tid >> 2, kq = tid & 3;
            float4 v = *(const float4*)(Wt + (size_t)(bn + n) * K + k0 + kq * 4);
            Bs[kq * 4 + 0][n] = v.x; Bs[kq * 4 + 1][n] = v.y;
            Bs[kq * 4 + 2][n] = v.z; Bs[kq * 4 + 3][n] = v.w;
        }
        __syncthreads();
#pragma unroll
        for (int kk = 0; kk < BK; kk++) {
            float2 bv0 = *(const float2*)&Bs[kk][tx * 4];
            float2 bv1 = *(const float2*)&Bs[kk][tx * 4 + 2];
            u64 bp0 = pk2(bv0.x, bv0.y), bp1 = pk2(bv1.x, bv1.y);
#pragma unroll
            for (int r = 0; r < RPT; r++) {
                float a = As[kk][ty * RPT + r];
                u64 ap = pk2(a, a);
                FMA2(acc[r][0], ap, bp0);
                FMA2(acc[r][1], ap, bp1);
            }
        }
        __syncthreads();
    }
    const int ncol = bn + tx * 4;
    float bb0 = b1[ncol + 0] + (b2 ? b2[ncol + 0] : 0.f);
    float bb1 = b1[ncol + 1] + (b2 ? b2[ncol + 1] : 0.f);
    float bb2 = b1[ncol + 2] + (b2 ? b2[ncol + 2] : 0.f);
    float bb3 = b1[ncol + 3] + (b2 ? b2[ncol + 3] : 0.f);
#pragma unroll
    for (int r = 0; r < RPT; r++) {
        float2 v0 = upk2(acc[r][0]);
        float2 v1 = upk2(acc[r][1]);
        float4 o = make_float4(v0.x + bb0, v0.y + bb1, v1.x + bb2, v1.y + bb3);
        *(float4*)(C + (size_t)(bm + ty * RPT + r) * N + ncol) = o;
    }
}

// ---------------- persistent layer-0 (proven R9) -----------------------------
__global__ void __launch_bounds__(256, 1) k_l0_persist(
        const float* __restrict__ c0f, const float* __restrict__ c0b,
        const float* __restrict__ whh_f, const float* __restrict__ whh_b) {
    extern __shared__ float sm[];
    float* Ws = sm;                 // [512][32]
    float* Hs = sm + 512 * 32;      // [2][64][68]
    const int tid = threadIdx.x;
    const int dir = blockIdx.x >> 6;
    const int j0  = (blockIdx.x & 63) * 8;
    const int tx = tid & 7, r0 = (tid >> 3) * 2;
    const int jg = j0 + tx;
    const float* Whh  = dir ? whh_b : whh_f;
    const float* preB = dir ? g_GB  : g_GF;
    const float* c0   = dir ? c0b   : c0f;
    {
        const int gj = tid & 31, kq = tid >> 5;
        const float* wr = Whh + (size_t)((gj & 3) * H + j0 + (gj >> 2)) * H + kq * 64;
#pragma unroll
        for (int i = 0; i < 16; i++) {
            float4 v = __ldg((const float4*)(wr + i * 4));
            int k = kq * 64 + i * 4;
            Ws[(k + 0) * 32 + gj] = v.x; Ws[(k + 1) * 32 + gj] = v.y;
            Ws[(k + 2) * 32 + gj] = v.z; Ws[(k + 3) * 32 + gj] = v.w;
        }
    }
    float cst[2] = { c0[(r0 + 0) * H + jg], c0[(r0 + 1) * H + jg] };
    __syncthreads();
    for (int t = 0; t < S; t++) {
        const float* hT = (t == 0) ? (g_H0T + dir * (H * Bz))
                                   : (g_XINT + ((size_t)(t - 1) * H2 + dir * H) * Bz);
        const float* pre = preB + (size_t)(dir ? (S - 1 - t) : t) * Bz * G4;
        float pg[2][4];
#pragma unroll
        for (int r = 0; r < 2; r++) {
            const float* pb = pre + (size_t)(r0 + r) * G4;
            pg[r][0] = __ldg(pb + 0 * H + jg); pg[r][1] = __ldg(pb + 1 * H + jg);
            pg[r][2] = __ldg(pb + 2 * H + jg); pg[r][3] = __ldg(pb + 3 * H + jg);
        }
        u64 acc[2][2] = {{0ull, 0ull}, {0ull, 0ull}};
        float4 hv[4];
#pragma unroll
        for (int i = 0; i < 4; i++) hv[i] = ldcg4(hT + (i * 256 + tid) * 4);
#pragma unroll
        for (int i = 0; i < 4; i++) {
            int f4 = i * 256 + tid;
            *(float4*)&Hs[(f4 >> 4) * 68 + (f4 & 15) * 4] = hv[i];
        }
        __syncthreads();
        for (int kt = 0; kt < 8; kt++) {
            int cur = kt & 1;
            if (kt < 7) {
#pragma unroll
                for (int i = 0; i < 4; i++)
                    hv[i] = ldcg4(hT + ((kt + 1) * 1024 + i * 256 + tid) * 4);
            }
            const float* Hc = Hs + cur * (64 * 68);
            const float* Wk = Ws + kt * 64 * 32;
#pragma unroll 8
            for (int kk = 0; kk < 64; kk++) {
                float2 a = *(const float2*)&Hc[kk * 68 + r0];
                ulonglong2 w = *(const ulonglong2*)&Wk[kk * 32 + tx * 4];
                u64 a0 = pk2(a.x, a.x), a1 = pk2(a.y, a.y);
                FMA2(acc[0][0], a0, w.x); FMA2(acc[0][1], a0, w.y);
                FMA2(acc[1][0], a1, w.x); FMA2(acc[1][1], a1, w.y);
            }
            if (kt < 7) {
                float* Hn = Hs + (cur ^ 1) * (64 * 68);
#pragma unroll
                for (int i = 0; i < 4; i++) {
                    int f4 = i * 256 + tid;
                    *(float4*)&Hn[(f4 >> 4) * 68 + (f4 & 15) * 4] = hv[i];
                }
            }
            __syncthreads();
        }
#pragma unroll
        for (int r = 0; r < 2; r++) {
            int b = r0 + r;
            float2 if_ = upk2(acc[r][0]);
            float2 go_ = upk2(acc[r][1]);
            float gi = if_.x + pg[r][0];
            float gf = if_.y + pg[r][1];
            float gg = go_.x + pg[r][2];
            float go = go_.y + pg[r][3];
            float c2 = sigf(gf) * cst[r] + sigf(gi) * tanhf(gg);
            cst[r] = c2;
            float h = sigf(go) * tanhf(c2);
            g_XIN [((size_t)t * Bz + b) * H2 + dir * H + jg] = h;
            g_XINT[((size_t)t * H2 + dir * H + jg) * Bz + b] = h;
        }
        gbar(&g_bar0[dir], 64u * (t + 1));
    }
}

// ---------------- HMMA layer-1 ------------------------------------------------
// SMEM: H buffers [2 buf][2 split][64 rows][72 bf16] = 36864 B at 0,
//       W buffers [2 buf][2 split][32 rows][72 bf16] = 18432 B at 36864,
//       Ex [64][36] fp32 = 9216 B at 55296.  Total 64512 B.
DEV_INLINE void load_chunk(uint32_t smb, int buf, const char* Wsrc, const char* Hsrc,
                           int c, int tid) {
#pragma unroll
    for (int q = 0; q < 6; q++) {
        int i = tid + q * 256;
        if (i < 1024) {
            int sp = i >> 9, rem = i & 511, row = rem >> 3, sg = rem & 7;
            cpa16(smb + buf * 18432 + sp * 9216 + row * 144 + sg * 16,
                  Hsrc + (size_t)sp * 131072 + row * 2048 + c * 128 + sg * 16);
        } else {
            int jj = i - 1024, sp = jj >> 8, rem = jj & 255, row = rem >> 3, sg = rem & 7;
            cpa16(smb + 36864 + buf * 9216 + sp * 4608 + row * 144 + sg * 16,
                  Wsrc + (size_t)sp * 65536 + row * 2048 + c * 128 + sg * 16);
        }
    }
    CP_COMMIT();
}

DEV_INLINE void hmma_gemm(uint32_t smb, const char* Wsrc, const char* Hsrc,
                          float* acc0, float* acc1, int tid,
                          uint32_t aoff, int n0, int brow, uint32_t bko) {
    load_chunk(smb, 0, Wsrc, Hsrc, 0, tid);
    for (int c = 0; c < 16; c++) {
        if (c < 15) { load_chunk(smb, (c + 1) & 1, Wsrc, Hsrc, c + 1, tid); cp_wait<1>(); }
        else cp_wait<0>();
        __syncthreads();
        uint32_t hb = smb + (c & 1) * 18432;
        uint32_t wb = smb + 36864 + (c & 1) * 9216;
#pragma unroll
        for (int ks = 0; ks < 4; ks++) {
            uint32_t a0, a1, a2, a3, l0, l1, l2, l3;
            ldsm_x4(a0, a1, a2, a3, hb + aoff + ks * 32);
            ldsm_x4(l0, l1, l2, l3, hb + 9216 + aoff + ks * 32);
#pragma unroll
            for (int nt = 0; nt < 2; nt++) {
                uint32_t bh0, bh1, bl0, bl1;
                uint32_t bb = wb + (uint32_t)(n0 + nt * 8 + brow) * 144 + bko + ks * 32;
                ldsm_x2(bh0, bh1, bb);
                ldsm_x2(bl0, bl1, bb + 4608);
                float* ac = nt ? acc1 : acc0;
                mma16816(ac, a0, a1, a2, a3, bh0, bh1);
                mma16816(ac, l0, l1, l2, l3, bh0, bh1);
                mma16816(ac, a0, a1, a2, a3, bl0, bl1);
            }
        }
        __syncthreads();
    }
}

DEV_INLINE void store_frag(float* Ex, int m0, int n0, int l, const float* ac0, const float* ac1) {
#pragma unroll
    for (int nt = 0; nt < 2; nt++) {
        const float* ac = nt ? ac1 : ac0;
        int er = m0 + (l >> 2), ec = n0 + nt * 8 + (l & 3) * 2;
        Ex[er * 36 + ec] = ac[0];       Ex[er * 36 + ec + 1] = ac[1];
        Ex[(er + 8) * 36 + ec] = ac[2]; Ex[(er + 8) * 36 + ec + 1] = ac[3];
    }
}

__global__ void __launch_bounds__(256, 1) k_l1_hmma(
        const float* __restrict__ c02,
        const float* __restrict__ bih2, const float* __restrict__ bhh2) {
    extern __shared__ char smc[];
    uint32_t smb = smem_u32(smc);
    float* Ex = (float*)(smc + 55296);
    const int tid = threadIdx.x, w = tid >> 5, l = tid & 31, bx = blockIdx.x;
    const int m0 = (w & 3) * 16, n0 = (w >> 2) * 16;
    const uint32_t aoff = (uint32_t)((m0 + (l & 15)) * 144 + (l >> 4) * 16);
    const int brow = l & 7;
    const uint32_t bko = (uint32_t)(((l >> 3) & 1) * 16);
    const int j = tid & 7, b0 = tid >> 3;
    const int jglob = bx * 8 + j;

    float c2[2] = { c02[b0 * H2 + jglob], c02[(b0 + 32) * H2 + jglob] };
    float bsr[4];
#pragma unroll
    for (int g = 0; g < 4; g++) bsr[g] = bih2[g * H2 + jglob] + bhh2[g * H2 + jglob];

    for (int t = 0; t < S; t++) {
        int p = t & 1;
        // ---- lstm1: whh1 @ h1prev ----
        float acc0[4] = {0, 0, 0, 0}, acc1[4] = {0, 0, 0, 0};
        hmma_gemm(smb, (const char*)&g_Wb[0][bx][0][0][0],
                  (const char*)&g_H1s[p][0][0][0], acc0, acc1, tid, aoff, n0, brow, bko);
        store_frag(Ex, m0, n0, l, acc0, acc1);
        __syncthreads();
#pragma unroll
        for (int r = 0; r < 2; r++) {
            int b = b0 + r * 32;
            const float* pb = g_G1 + ((size_t)t * Bz + b) * G8;
            float gi = Ex[b * 36 + j]      + __ldg(pb + 0 * H2 + jglob);
            float gf = Ex[b * 36 + 8 + j]  + __ldg(pb + 1 * H2 + jglob);
            float gg = Ex[b * 36 + 16 + j] + __ldg(pb + 2 * H2 + jglob);
            float go = Ex[b * 36 + 24 + j] + __ldg(pb + 3 * H2 + jglob);
            float cc = sigf(gf) * c2[r] + sigf(gi) * tanhf(gg);
            float h1 = sigf(go) * tanhf(cc);
            __nv_bfloat16 hi = __float2bfloat16(h1);
            g_H1s[p ^ 1][0][b][jglob] = hi;
            g_H1s[p ^ 1][1][b][jglob] = __float2bfloat16(h1 - __bfloat162float(hi));
        }
        gbar(&g_bar1, 128u * (t + 1));   // publish h1new (and h2new of t-1 ordering)

        // ---- lstm2: whh2 @ h2prev + wih2 @ h1new ----
        acc0[0] = acc0[1] = acc0[2] = acc0[3] = 0.f;
        acc1[0] = acc1[1] = acc1[2] = acc1[3] = 0.f;
        hmma_gemm(smb, (const char*)&g_Wb[1][bx][0][0][0],
                  (const char*)&g_H2s[p][0][0][0], acc0, acc1, tid, aoff, n0, brow, bko);
        hmma_gemm(smb, (const char*)&g_Wb[2][bx][0][0][0],
                  (const char*)&g_H1s[p ^ 1][0][0][0], acc0, acc1, tid, aoff, n0, brow, bko);
        store_frag(Ex, m0, n0, l, acc0, acc1);
        __syncthreads();
#pragma unroll
        for (int r = 0; r < 2; r++) {
            int b = b0 + r * 32;
            float gi = Ex[b * 36 + j]      + bsr[0];
            float gf = Ex[b * 36 + 8 + j]  + bsr[1];
            float gg = Ex[b * 36 + 16 + j] + bsr[2];
            float go = Ex[b * 36 + 24 + j] + bsr[3];
            float cn = sigf(gf) * c2[r] + sigf(gi) * tanhf(gg);
            c2[r] = cn;
            float h2 = sigf(go) * tanhf(cn);
            __nv_bfloat16 hi = __float2bfloat16(h2);
            g_H2s[p ^ 1][0][b][jglob] = hi;
            g_H2s[p ^ 1][1][b][jglob] = __float2bfloat16(h2 - __bfloat162float(hi));
            if (t == S - 1) g_H2R[(size_t)b * H2 + jglob] = h2;
        }
        __syncthreads();
    }
}

// ---------------- launch -----------------------------------------------------
extern "C" void kernel_launch(void* const* d_in, const int* in_sizes, int n_in,
                              void* d_out, int out_size) {
    const int*   x     = (const int*)  d_in[0];
    const float* emb   = (const float*)d_in[1];
    const float* h0f   = (const float*)d_in[2];
    const float* c0f   = (const float*)d_in[3];
    const float* h0b   = (const float*)d_in[4];
    const float* c0b   = (const float*)d_in[5];
    const float* h01   = (const float*)d_in[6];
    const float* h02   = (const float*)d_in[7];
    const float* c02   = (const float*)d_in[8];
    const float* wih_f = (const float*)d_in[9];
    const float* whh_f = (const float*)d_in[10];
    const float* bih_f = (const float*)d_in[11];
    const float* bhh_f = (const float*)d_in[12];
    const float* wih_b = (const float*)d_in[13];
    const float* whh_b = (const float*)d_in[14];
    const float* bih_b = (const float*)d_in[15];
    const float* bhh_b = (const float*)d_in[16];
    const float* wih1  = (const float*)d_in[17];
    const float* whh1  = (const float*)d_in[18];
    const float* bih1  = (const float*)d_in[19];
    const float* bhh1  = (const float*)d_in[20];
    const float* wih2  = (const float*)d_in[21];
    const float* whh2  = (const float*)d_in[22];
    const float* bih2  = (const float*)d_in[23];
    const float* bhh2  = (const float*)d_in[24];
    const float* wlin  = (const float*)d_in[25];
    const float* blin  = (const float*)d_in[26];
    float* out = (float*)d_out;

    float *pX, *pGF, *pGB, *pXIN, *pG1, *pH2R;
    cudaGetSymbolAddress((void**)&pX,   g_X);
    cudaGetSymbolAddress((void**)&pGF,  g_GF);
    cudaGetSymbolAddress((void**)&pGB,  g_GB);
    cudaGetSymbolAddress((void**)&pXIN, g_XIN);
    cudaGetSymbolAddress((void**)&pG1,  g_G1);
    cudaGetSymbolAddress((void**)&pH2R, g_H2R);

    const int L0_SM = (512 * 32 + 2 * 64 * 68) * 4;   // 100352 B
    const int L1_SM = 64512;
    cudaFuncSetAttribute(k_l0_persist, cudaFuncAttributeMaxDynamicSharedMemorySize, L0_SM);
    cudaFuncSetAttribute(k_l1_hmma,    cudaFuncAttributeMaxDynamicSharedMemorySize, L1_SM);

    // A: gather + init + bf16-split prep
    k_embed<<<R, 128>>>(x, emb);
    k_init<<<256, 256>>>(h0f, h0b);
    k_prep_h<<<512, 256>>>(h01, h02);
    k_prep_w<<<3 * 4096, 256>>>(whh1, whh2, wih2);

    // B: hoisted input-side gate GEMMs for layer 0
    k_gemm_bias<128><<<dim3(G4 / 64, R / 128), 256>>>(pX, wih_f, bih_f, bhh_f, pGF, H, G4);
    k_gemm_bias<128><<<dim3(G4 / 64, R / 128), 256>>>(pX, wih_b, bih_b, bhh_b, pGB, H, G4);

    // C: persistent bidirectional layer-0 recurrence
    k_l0_persist<<<128, 256, L0_SM>>>(c0f, c0b, whh_f, whh_b);

    // D: hoisted input-side GEMM for lstm1
    k_gemm_bias<128><<<dim3(G8 / 64, R / 128), 256>>>(pXIN, wih1, bih1, bhh1, pG1, H2, G8);

    // E: HMMA persistent layer-1 recurrence
    k_l1_hmma<<<128, 256, L1_SM>>>(c02, bih2, bhh2);

    // F: logits
    k_gemm_bias<64><<<dim3(V / 64, 1), 256>>>(pH2R, wlin, blin, nullptr, out, H2, V);
}

// round 13
// speedup vs baseline: 3.2789x; 1.1271x over previous
#include <cuda_runtime.h>
#include <cuda_bf16.h>
#include <cstdint>

#define DEV_INLINE __device__ __forceinline__
typedef unsigned long long u64;

static constexpr int V  = 32000;
static constexpr int H  = 512;
static constexpr int Bz = 64;
static constexpr int S  = 128;
static constexpr int H2 = 1024;
static constexpr int G4 = 2048;
static constexpr int G8 = 4096;
static constexpr int R  = S * Bz;

// ---------------- scratch ---------------------------------------------------
__device__ float g_X   [R * H];
__device__ float g_GF  [R * G4];
__device__ float g_GB  [R * G4];
__device__ float g_XIN [R * H2];
__device__ float g_G1  [R * G8];
__device__ float g_H2R [Bz * H2];
// layer-1 bf16 split weights: [mat][block][hi|lo][32 gate-rows][1024 k]
__device__ __nv_bfloat16 g_Wb [3][128][2][32][1024];
// layer-0 bf16 split weights: [dir][block][hi|lo][32 gate-rows][512 k]
__device__ __nv_bfloat16 g_Wb0[2][64][2][32][512];
// layer-1 split states ping-pong: [pp][hi|lo][64 b][1024 k]
__device__ __nv_bfloat16 g_H1s[2][2][Bz][H2];
__device__ __nv_bfloat16 g_H2s[2][2][Bz][H2];
// layer-0 split states: [dir][pp][hi|lo][64 b][512 k]
__device__ __nv_bfloat16 g_L0s[2][2][2][Bz][H];
__device__ unsigned g_bar0[2];
__device__ unsigned g_bar1;

// ---------------- helpers ---------------------------------------------------
DEV_INLINE u64 pk2(float x, float y) {
    u64 r; asm("mov.b64 %0, {%1, %2};" : "=l"(r) : "f"(x), "f"(y)); return r;
}
DEV_INLINE float2 upk2(u64 v) {
    float2 r; asm("mov.b64 {%0, %1}, %2;" : "=f"(r.x), "=f"(r.y) : "l"(v)); return r;
}
#define FMA2(d, a, b) asm("fma.rn.f32x2 %0, %1, %2, %0;" : "+l"(d) : "l"(a), "l"(b))
DEV_INLINE float sigf(float x) { return 1.f / (1.f + expf(-x)); }

DEV_INLINE void gbar(unsigned* cnt, unsigned target) {
    __threadfence();
    __syncthreads();
    if (threadIdx.x == 0) {
        atomicAdd(cnt, 1u);
        while (*(volatile unsigned*)cnt < target) __nanosleep(32);
    }
    __syncthreads();
}

DEV_INLINE uint32_t smem_u32(const void* p) {
    uint32_t a;
    asm("{ .reg .u64 t; cvta.to.shared.u64 t, %1; cvt.u32.u64 %0, t; }" : "=r"(a) : "l"(p));
    return a;
}
DEV_INLINE void cpa16(uint32_t dst, const void* src) {
    asm volatile("cp.async.cg.shared.global [%0], [%1], 16;" :: "r"(dst), "l"(src) : "memory");
}
#define CP_COMMIT() asm volatile("cp.async.commit_group;" ::: "memory")
template <int N> DEV_INLINE void cp_wait() {
    asm volatile("cp.async.wait_group %0;" :: "n"(N) : "memory");
}
DEV_INLINE void ldsm_x4(uint32_t& a0, uint32_t& a1, uint32_t& a2, uint32_t& a3, uint32_t ad) {
    asm volatile("ldmatrix.sync.aligned.m8n8.x4.shared.b16 {%0,%1,%2,%3}, [%4];"
                 : "=r"(a0), "=r"(a1), "=r"(a2), "=r"(a3) : "r"(ad));
}
DEV_INLINE void ldsm_x2(uint32_t& b0, uint32_t& b1, uint32_t ad) {
    asm volatile("ldmatrix.sync.aligned.m8n8.x2.shared.b16 {%0,%1}, [%2];"
                 : "=r"(b0), "=r"(b1) : "r"(ad));
}
DEV_INLINE void mma16816(float* c, uint32_t a0, uint32_t a1, uint32_t a2, uint32_t a3,
                         uint32_t b0, uint32_t b1) {
    asm volatile("mma.sync.aligned.m16n8k16.row.col.f32.bf16.bf16.f32 "
                 "{%0,%1,%2,%3}, {%4,%5,%6,%7}, {%8,%9}, {%0,%1,%2,%3};"
                 : "+f"(c[0]), "+f"(c[1]), "+f"(c[2]), "+f"(c[3])
                 : "r"(a0), "r"(a1), "r"(a2), "r"(a3), "r"(b0), "r"(b1));
}

// ---------------- small kernels ----------------------------------------------
__global__ void k_embed(const int* __restrict__ x, const float* __restrict__ emb) {
    int r = blockIdx.x;
    int tok = x[r];
    float4 v = make_float4(0.f, 0.f, 0.f, 0.f);
    if (tok != 0) v = *(const float4*)(emb + (size_t)tok * H + threadIdx.x * 4);
    *(float4*)(g_X + (size_t)r * H + threadIdx.x * 4) = v;
}

// split layer-1 weights
__global__ void k_prep_w(const float* __restrict__ whh1, const float* __restrict__ whh2,
                         const float* __restrict__ wih2) {
    int mr = blockIdx.x;                     // [0, 3*4096)
    int mat = mr >> 12, r = mr & 4095;
    const float* W = mat == 0 ? whh1 : (mat == 1 ? whh2 : wih2);
    int g = r >> 10, jglob = r & 1023;
    int bx = jglob >> 3, gr = g * 8 + (jglob & 7);
    const float* src = W + (size_t)r * H2;
#pragma unroll
    for (int q = 0; q < 4; q++) {
        int k = threadIdx.x + q * 256;
        float w = src[k];
        __nv_bfloat16 hi = __float2bfloat16(w);
        __nv_bfloat16 lo = __float2bfloat16(w - __bfloat162float(hi));
        g_Wb[mat][bx][0][gr][k] = hi;
        g_Wb[mat][bx][1][gr][k] = lo;
    }
}

// split layer-0 weights
__global__ void k_prep_w0(const float* __restrict__ whh_f, const float* __restrict__ whh_b) {
    int mr = blockIdx.x;                     // [0, 2*2048)
    int dir = mr >> 11, r = mr & 2047;
    const float* W = dir ? whh_b : whh_f;
    int g = r >> 9, j = r & 511;
    int bx = j >> 3, gr = g * 8 + (j & 7);
    const float* src = W + (size_t)r * H;
#pragma unroll
    for (int q = 0; q < 2; q++) {
        int k = threadIdx.x + q * 256;
        float w = src[k];
        __nv_bfloat16 hi = __float2bfloat16(w);
        __nv_bfloat16 lo = __float2bfloat16(w - __bfloat162float(hi));
        g_Wb0[dir][bx][0][gr][k] = hi;
        g_Wb0[dir][bx][1][gr][k] = lo;
    }
}

// split layer-1 initial states
__global__ void k_prep_h(const float* __restrict__ h01, const float* __restrict__ h02) {
    int i = blockIdx.x * 256 + threadIdx.x;  // [0, 131072)
    int which = i >> 16, e = i & 65535;
    int b = e >> 10, k = e & 1023;
    float v = (which ? h02 : h01)[e];
    __nv_bfloat16 hi = __float2bfloat16(v);
    __nv_bfloat16 lo = __float2bfloat16(v - __bfloat162float(hi));
    if (which) { g_H2s[0][0][b][k] = hi; g_H2s[0][1][b][k] = lo; }
    else       { g_H1s[0][0][b][k] = hi; g_H1s[0][1][b][k] = lo; }
}

// split layer-0 initial states + zero barriers
__global__ void k_prep_h0(const float* __restrict__ h0f, const float* __restrict__ h0b) {
    int i = blockIdx.x * 256 + threadIdx.x;  // [0, 65536)
    if (i == 0) { g_bar0[0] = 0u; g_bar0[1] = 0u; g_bar1 = 0u; }
    int dir = i >> 15, e = i & 32767;
    int b = e >> 9, k = e & 511;
    float v = (dir ? h0b : h0f)[e];
    __nv_bfloat16 hi = __float2bfloat16(v);
    __nv_bfloat16 lo = __float2bfloat16(v - __bfloat162float(hi));
    g_L0s[dir][0][0][b][k] = hi;
    g_L0s[dir][0][1][b][k] = lo;
}

// ---------------- big batched GEMM (proven) ----------------------------------
template <int BM>
__global__ void k_gemm_bias(const float* __restrict__ A, const float* __restrict__ Wt,
                            const float* __restrict__ b1, const float* __restrict__ b2,
                            float* __restrict__ C, int K, int N) {
    constexpr int BN = 64, BK = 16, RPT = BM / 16;
    __shared__ float As[BK][BM + 4];
    __shared__ float Bs[BK][BN + 4];
    const int tid = threadIdx.x;
    const int bm = blockIdx.y * BM, bn = blockIdx.x * BN;
    const int tx = tid & 15, ty = tid >> 4;
    u64 acc[RPT][2];
#pragma unroll
    for (int r = 0; r < RPT; r++) { acc[r][0] = 0ull; acc[r][1] = 0ull; }
    for (int k0 = 0; k0 < K; k0 += BK) {
#pragma unroll
        for (int i = tid; i < BM * 4; i += 256) {
            int m = i >> 2, kq = i & 3;
            float4 v = *(const float4*)(A + (size_t)(bm + m) * K + k0 + kq * 4);
            As[kq * 4 + 0][m] = v.x; As[kq * 4 + 1][m] = v.y;
            As[kq * 4 + 2][m] = v.z; As[kq * 4 + 3][m] = v.w;
        }
        {
            int n = tid >> 2, kq = tid & 3;
            float4 v = *(const float4*)(Wt + (size_t)(bn + n) * K + k0 + kq * 4);
            Bs[kq * 4 + 0][n] = v.x; Bs[kq * 4 + 1][n] = v.y;
            Bs[kq * 4 + 2][n] = v.z; Bs[kq * 4 + 3][n] = v.w;
        }
        __syncthreads();
#pragma unroll
        for (int kk = 0; kk < BK; kk++) {
            float2 bv0 = *(const float2*)&Bs[kk][tx * 4];
            float2 bv1 = *(const float2*)&Bs[kk][tx * 4 + 2];
            u64 bp0 = pk2(bv0.x, bv0.y), bp1 = pk2(bv1.x, bv1.y);
#pragma unroll
            for (int r = 0; r < RPT; r++) {
                float a = As[kk][ty * RPT + r];
                u64 ap = pk2(a, a);
                FMA2(acc[r][0], ap, bp0);
                FMA2(acc[r][1], ap, bp1);
            }
        }
        __syncthreads();
    }
    const int ncol = bn + tx * 4;
    float bb0 = b1[ncol + 0] + (b2 ? b2[ncol + 0] : 0.f);
    float bb1 = b1[ncol + 1] + (b2 ? b2[ncol + 1] : 0.f);
    float bb2 = b1[ncol + 2] + (b2 ? b2[ncol + 2] : 0.f);
    float bb3 = b1[ncol + 3] + (b2 ? b2[ncol + 3] : 0.f);
#pragma unroll
    for (int r = 0; r < RPT; r++) {
        float2 v0 = upk2(acc[r][0]);
        float2 v1 = upk2(acc[r][1]);
        float4 o = make_float4(v0.x + bb0, v0.y + bb1, v1.x + bb2, v1.y + bb3);
        *(float4*)(C + (size_t)(bm + ty * RPT + r) * N + ncol) = o;
    }
}

// ---------------- shared HMMA machinery ---------------------------------------
// SMEM: H buffers [2 buf][2 split][64 rows][72 bf16] = 36864 B at 0,
//       W buffers [2 buf][2 split][32 rows][72 bf16] = 18432 B at 36864,
//       Ex [64][36] fp32 = 9216 B at 55296.  Total 64512 B.
template <int HROWB, int WROWB>
DEV_INLINE void load_chunk(uint32_t smb, int buf, const char* Wsrc, const char* Hsrc,
                           int c, int tid) {
#pragma unroll
    for (int q = 0; q < 6; q++) {
        int i = tid + q * 256;
        if (i < 1024) {
            int sp = i >> 9, rem = i & 511, row = rem >> 3, sg = rem & 7;
            cpa16(smb + buf * 18432 + sp * 9216 + row * 144 + sg * 16,
                  Hsrc + (size_t)sp * (64 * HROWB) + row * HROWB + c * 128 + sg * 16);
        } else {
            int jj = i - 1024, sp = jj >> 8, rem = jj & 255, row = rem >> 3, sg = rem & 7;
            cpa16(smb + 36864 + buf * 9216 + sp * 4608 + row * 144 + sg * 16,
                  Wsrc + (size_t)sp * (32 * WROWB) + row * WROWB + c * 128 + sg * 16);
        }
    }
    CP_COMMIT();
}

template <int NCH, int HROWB, int WROWB>
DEV_INLINE void hmma_gemm(uint32_t smb, const char* Wsrc, const char* Hsrc,
                          float* acc0, float* acc1, int tid,
                          uint32_t aoff, int n0, int brow, uint32_t bko) {
    load_chunk<HROWB, WROWB>(smb, 0, Wsrc, Hsrc, 0, tid);
    for (int c = 0; c < NCH; c++) {
        if (c < NCH - 1) {
            load_chunk<HROWB, WROWB>(smb, (c + 1) & 1, Wsrc, Hsrc, c + 1, tid);
            cp_wait<1>();
        } else cp_wait<0>();
        __syncthreads();
        uint32_t hb = smb + (c & 1) * 18432;
        uint32_t wb = smb + 36864 + (c & 1) * 9216;
#pragma unroll
        for (int ks = 0; ks < 4; ks++) {
            uint32_t a0, a1, a2, a3, l0, l1, l2, l3;
            ldsm_x4(a0, a1, a2, a3, hb + aoff + ks * 32);
            ldsm_x4(l0, l1, l2, l3, hb + 9216 + aoff + ks * 32);
#pragma unroll
            for (int nt = 0; nt < 2; nt++) {
                uint32_t bh0, bh1, bl0, bl1;
                uint32_t bb = wb + (uint32_t)(n0 + nt * 8 + brow) * 144 + bko + ks * 32;
                ldsm_x2(bh0, bh1, bb);
                ldsm_x2(bl0, bl1, bb + 4608);
                float* ac = nt ? acc1 : acc0;
                mma16816(ac, a0, a1, a2, a3, bh0, bh1);
                mma16816(ac, l0, l1, l2, l3, bh0, bh1);
                mma16816(ac, a0, a1, a2, a3, bl0, bl1);
            }
        }
        __syncthreads();
    }
}

DEV_INLINE void store_frag(float* Ex, int m0, int n0, int l, const float* ac0, const float* ac1) {
#pragma unroll
    for (int nt = 0; nt < 2; nt++) {
        const float* ac = nt ? ac1 : ac0;
        int er = m0 + (l >> 2), ec = n0 + nt * 8 + (l & 3) * 2;
        Ex[er * 36 + ec] = ac[0];       Ex[er * 36 + ec + 1] = ac[1];
        Ex[(er + 8) * 36 + ec] = ac[2]; Ex[(er + 8) * 36 + ec + 1] = ac[3];
    }
}

// ---------------- HMMA layer-0 ------------------------------------------------
__global__ void __launch_bounds__(256, 1) k_l0_hmma(
        const float* __restrict__ c0f, const float* __restrict__ c0b) {
    extern __shared__ char smc[];
    uint32_t smb = smem_u32(smc);
    float* Ex = (float*)(smc + 55296);
    const int tid = threadIdx.x, w = tid >> 5, l = tid & 31;
    const int dir = blockIdx.x >> 6, jb = blockIdx.x & 63;
    const int m0 = (w & 3) * 16, n0 = (w >> 2) * 16;
    const uint32_t aoff = (uint32_t)((m0 + (l & 15)) * 144 + (l >> 4) * 16);
    const int brow = l & 7;
    const uint32_t bko = (uint32_t)(((l >> 3) & 1) * 16);
    const int j = tid & 7, b0 = tid >> 3;
    const int jglob = jb * 8 + j;          // [0, 512)
    const float* preB = dir ? g_GB : g_GF;
    const float* c0   = dir ? c0b  : c0f;
    const char* Wsrc = (const char*)&g_Wb0[dir][jb][0][0][0];

    float cst[2] = { c0[b0 * H + jglob], c0[(b0 + 32) * H + jglob] };

    for (int t = 0; t < S; t++) {
        int p = t & 1;
        // prefetch input-side gates
        const float* pre = preB + (size_t)(dir ? (S - 1 - t) : t) * Bz * G4;
        float pg[2][4];
#pragma unroll
        for (int r = 0; r < 2; r++) {
            const float* pb = pre + (size_t)(b0 + r * 32) * G4;
            pg[r][0] = __ldg(pb + 0 * H + jglob);
            pg[r][1] = __ldg(pb + 1 * H + jglob);
            pg[r][2] = __ldg(pb + 2 * H + jglob);
            pg[r][3] = __ldg(pb + 3 * H + jglob);
        }
        float acc0[4] = {0, 0, 0, 0}, acc1[4] = {0, 0, 0, 0};
        hmma_gemm<8, 1024, 1024>(smb, Wsrc, (const char*)&g_L0s[dir][p][0][0][0],
                                 acc0, acc1, tid, aoff, n0, brow, bko);
        store_frag(Ex, m0, n0, l, acc0, acc1);
        __syncthreads();
#pragma unroll
        for (int r = 0; r < 2; r++) {
            int b = b0 + r * 32;
            float gi = Ex[b * 36 + j]      + pg[r][0];
            float gf = Ex[b * 36 + 8 + j]  + pg[r][1];
            float gg = Ex[b * 36 + 16 + j] + pg[r][2];
            float go = Ex[b * 36 + 24 + j] + pg[r][3];
            float c2 = sigf(gf) * cst[r] + sigf(gi) * tanhf(gg);
            cst[r] = c2;
            float h = sigf(go) * tanhf(c2);
            g_XIN[((size_t)t * Bz + b) * H2 + dir * H + jglob] = h;
            __nv_bfloat16 hi = __float2bfloat16(h);
            g_L0s[dir][p ^ 1][0][b][jglob] = hi;
            g_L0s[dir][p ^ 1][1][b][jglob] = __float2bfloat16(h - __bfloat162float(hi));
        }
        __syncthreads();
        gbar(&g_bar0[dir], 64u * (t + 1));
    }
}

// ---------------- HMMA layer-1 (proven R12) -----------------------------------
__global__ void __launch_bounds__(256, 1) k_l1_hmma(
        const float* __restrict__ c02,
        const float* __restrict__ bih2, const float* __restrict__ bhh2) {
    extern __shared__ char smc[];
    uint32_t smb = smem_u32(smc);
    float* Ex = (float*)(smc + 55296);
    const int tid = threadIdx.x, w = tid >> 5, l = tid & 31, bx = blockIdx.x;
    const int m0 = (w & 3) * 16, n0 = (w >> 2) * 16;
    const uint32_t aoff = (uint32_t)((m0 + (l & 15)) * 144 + (l >> 4) * 16);
    const int brow = l & 7;
    const uint32_t bko = (uint32_t)(((l >> 3) & 1) * 16);
    const int j = tid & 7, b0 = tid >> 3;
    const int jglob = bx * 8 + j;

    float c2[2] = { c02[b0 * H2 + jglob], c02[(b0 + 32) * H2 + jglob] };
    float bsr[4];
#pragma unroll
    for (int g = 0; g < 4; g++) bsr[g] = bih2[g * H2 + jglob] + bhh2[g * H2 + jglob];

    for (int t = 0; t < S; t++) {
        int p = t & 1;
        float acc0[4] = {0, 0, 0, 0}, acc1[4] = {0, 0, 0, 0};
        hmma_gemm<16, 2048, 2048>(smb, (const char*)&g_Wb[0][bx][0][0][0],
                                  (const char*)&g_H1s[p][0][0][0],
                                  acc0, acc1, tid, aoff, n0, brow, bko);
        store_frag(Ex, m0, n0, l, acc0, acc1);
        __syncthreads();
#pragma unroll
        for (int r = 0; r < 2; r++) {
            int b = b0 + r * 32;
            const float* pb = g_G1 + ((size_t)t * Bz + b) * G8;
            float gi = Ex[b * 36 + j]      + __ldg(pb + 0 * H2 + jglob);
            float gf = Ex[b * 36 + 8 + j]  + __ldg(pb + 1 * H2 + jglob);
            float gg = Ex[b * 36 + 16 + j] + __ldg(pb + 2 * H2 + jglob);
            float go = Ex[b * 36 + 24 + j] + __ldg(pb + 3 * H2 + jglob);
            float cc = sigf(gf) * c2[r] + sigf(gi) * tanhf(gg);
            float h1 = sigf(go) * tanhf(cc);
            __nv_bfloat16 hi = __float2bfloat16(h1);
            g_H1s[p ^ 1][0][b][jglob] = hi;
            g_H1s[p ^ 1][1][b][jglob] = __float2bfloat16(h1 - __bfloat162float(hi));
        }
        gbar(&g_bar1, 128u * (t + 1));

        acc0[0] = acc0[1] = acc0[2] = acc0[3] = 0.f;
        acc1[0] = acc1[1] = acc1[2] = acc1[3] = 0.f;
        hmma_gemm<16, 2048, 2048>(smb, (const char*)&g_Wb[1][bx][0][0][0],
                                  (const char*)&g_H2s[p][0][0][0],
                                  acc0, acc1, tid, aoff, n0, brow, bko);
        hmma_gemm<16, 2048, 2048>(smb, (const char*)&g_Wb[2][bx][0][0][0],
                                  (const char*)&g_H1s[p ^ 1][0][0][0],
                                  acc0, acc1, tid, aoff, n0, brow, bko);
        store_frag(Ex, m0, n0, l, acc0, acc1);
        __syncthreads();
#pragma unroll
        for (int r = 0; r < 2; r++) {
            int b = b0 + r * 32;
            float gi = Ex[b * 36 + j]      + bsr[0];
            float gf = Ex[b * 36 + 8 + j]  + bsr[1];
            float gg = Ex[b * 36 + 16 + j] + bsr[2];
            float go = Ex[b * 36 + 24 + j] + bsr[3];
            float cn = sigf(gf) * c2[r] + sigf(gi) * tanhf(gg);
            c2[r] = cn;
            float h2 = sigf(go) * tanhf(cn);
            __nv_bfloat16 hi = __float2bfloat16(h2);
            g_H2s[p ^ 1][0][b][jglob] = hi;
            g_H2s[p ^ 1][1][b][jglob] = __float2bfloat16(h2 - __bfloat162float(hi));
            if (t == S - 1) g_H2R[(size_t)b * H2 + jglob] = h2;
        }
        __syncthreads();
    }
}

// ---------------- launch -----------------------------------------------------
extern "C" void kernel_launch(void* const* d_in, const int* in_sizes, int n_in,
                              void* d_out, int out_size) {
    const int*   x     = (const int*)  d_in[0];
    const float* emb   = (const float*)d_in[1];
    const float* h0f   = (const float*)d_in[2];
    const float* c0f   = (const float*)d_in[3];
    const float* h0b   = (const float*)d_in[4];
    const float* c0b   = (const float*)d_in[5];
    const float* h01   = (const float*)d_in[6];
    const float* h02   = (const float*)d_in[7];
    const float* c02   = (const float*)d_in[8];
    const float* wih_f = (const float*)d_in[9];
    const float* whh_f = (const float*)d_in[10];
    const float* bih_f = (const float*)d_in[11];
    const float* bhh_f = (const float*)d_in[12];
    const float* wih_b = (const float*)d_in[13];
    const float* whh_b = (const float*)d_in[14];
    const float* bih_b = (const float*)d_in[15];
    const float* bhh_b = (const float*)d_in[16];
    const float* wih1  = (const float*)d_in[17];
    const float* whh1  = (const float*)d_in[18];
    const float* bih1  = (const float*)d_in[19];
    const float* bhh1  = (const float*)d_in[20];
    const float* wih2  = (const float*)d_in[21];
    const float* whh2  = (const float*)d_in[22];
    const float* bih2  = (const float*)d_in[23];
    const float* bhh2  = (const float*)d_in[24];
    const float* wlin  = (const float*)d_in[25];
    const float* blin  = (const float*)d_in[26];
    float* out = (float*)d_out;

    float *pX, *pGF, *pGB, *pXIN, *pG1, *pH2R;
    cudaGetSymbolAddress((void**)&pX,   g_X);
    cudaGetSymbolAddress((void**)&pGF,  g_GF);
    cudaGetSymbolAddress((void**)&pGB,  g_GB);
    cudaGetSymbolAddress((void**)&pXIN, g_XIN);
    cudaGetSymbolAddress((void**)&pG1,  g_G1);
    cudaGetSymbolAddress((void**)&pH2R, g_H2R);

    const int HM_SM = 64512;
    cudaFuncSetAttribute(k_l0_hmma, cudaFuncAttributeMaxDynamicSharedMemorySize, HM_SM);
    cudaFuncSetAttribute(k_l1_hmma, cudaFuncAttributeMaxDynamicSharedMemorySize, HM_SM);

    // A: gather + bf16-split prep (also zeroes barrier counters each replay)
    k_embed<<<R, 128>>>(x, emb);
    k_prep_h0<<<256, 256>>>(h0f, h0b);
    k_prep_h<<<512, 256>>>(h01, h02);
    k_prep_w0<<<2 * 2048, 256>>>(whh_f, whh_b);
    k_prep_w<<<3 * 4096, 256>>>(whh1, whh2, wih2);

    // B: hoisted input-side gate GEMMs for layer 0
    k_gemm_bias<128><<<dim3(G4 / 64, R / 128), 256>>>(pX, wih_f, bih_f, bhh_f, pGF, H, G4);
    k_gemm_bias<128><<<dim3(G4 / 64, R / 128), 256>>>(pX, wih_b, bih_b, bhh_b, pGB, H, G4);

    // C: HMMA persistent bidirectional layer-0 recurrence
    k_l0_hmma<<<128, 256, HM_SM>>>(c0f, c0b);

    // D: hoisted input-side GEMM for lstm1
    k_gemm_bias<128><<<dim3(G8 / 64, R / 128), 256>>>(pXIN, wih1, bih1, bhh1, pG1, H2, G8);

    // E: HMMA persistent layer-1 recurrence
    k_l1_hmma<<<128, 256, HM_SM>>>(c02, bih2, bhh2);

    // F: logits
    k_gemm_bias<64><<<dim3(V / 64, 1), 256>>>(pH2R, wlin, blin, nullptr, out, H2, V);
}

// round 14
// speedup vs baseline: 4.0139x; 1.2242x over previous
#include <cuda_runtime.h>
#include <cuda_bf16.h>
#include <cstdint>

#define DEV_INLINE __device__ __forceinline__
typedef unsigned long long u64;

static constexpr int V  = 32000;
static constexpr int H  = 512;
static constexpr int Bz = 64;
static constexpr int S  = 128;
static constexpr int H2 = 1024;
static constexpr int G4 = 2048;
static constexpr int G8 = 4096;
static constexpr int R  = S * Bz;

// ---------------- scratch ---------------------------------------------------
__device__ float g_GF  [R * G4];
__device__ float g_GB  [R * G4];
__device__ float g_G1  [R * G8];
__device__ float g_H2R [Bz * H2];
// split embeddings / XIN (A-operands of phases B and D)
__device__ __align__(16) __nv_bfloat16 g_Xs  [2][R * H];
__device__ __align__(16) __nv_bfloat16 g_XINs[2][R * H2];
// split input-side weights
__device__ __align__(16) __nv_bfloat16 g_WFs[2][G4 * H];
__device__ __align__(16) __nv_bfloat16 g_WBs[2][G4 * H];
__device__ __align__(16) __nv_bfloat16 g_W1s[2][G8 * H2];
// layer-1 split weights: [mat][block][hi|lo][32 gate-rows][1024 k]
__device__ __align__(16) __nv_bfloat16 g_Wb [3][128][2][32][1024];
// layer-0 split weights: [dir][block][hi|lo][32 gate-rows][512 k]
__device__ __align__(16) __nv_bfloat16 g_Wb0[2][64][2][32][512];
// recurrent split states
__device__ __align__(16) __nv_bfloat16 g_H1s[2][2][Bz][H2];
__device__ __align__(16) __nv_bfloat16 g_H2s[2][2][Bz][H2];
__device__ __align__(16) __nv_bfloat16 g_L0s[2][2][2][Bz][H];
__device__ unsigned g_bar0[2];
__device__ unsigned g_bar1;

// ---------------- helpers ---------------------------------------------------
DEV_INLINE u64 pk2(float x, float y) {
    u64 r; asm("mov.b64 %0, {%1, %2};" : "=l"(r) : "f"(x), "f"(y)); return r;
}
DEV_INLINE float2 upk2(u64 v) {
    float2 r; asm("mov.b64 {%0, %1}, %2;" : "=f"(r.x), "=f"(r.y) : "l"(v)); return r;
}
#define FMA2(d, a, b) asm("fma.rn.f32x2 %0, %1, %2, %0;" : "+l"(d) : "l"(a), "l"(b))
DEV_INLINE float sigf(float x) { return 1.f / (1.f + expf(-x)); }

DEV_INLINE void gbar(unsigned* cnt, unsigned target) {
    __threadfence();
    __syncthreads();
    if (threadIdx.x == 0) {
        atomicAdd(cnt, 1u);
        while (*(volatile unsigned*)cnt < target) __nanosleep(32);
    }
    __syncthreads();
}

DEV_INLINE uint32_t smem_u32(const void* p) {
    uint32_t a;
    asm("{ .reg .u64 t; cvta.to.shared.u64 t, %1; cvt.u32.u64 %0, t; }" : "=r"(a) : "l"(p));
    return a;
}
DEV_INLINE void cpa16(uint32_t dst, const void* src) {
    asm volatile("cp.async.cg.shared.global [%0], [%1], 16;" :: "r"(dst), "l"(src) : "memory");
}
#define CP_COMMIT() asm volatile("cp.async.commit_group;" ::: "memory")
template <int N> DEV_INLINE void cp_wait() {
    asm volatile("cp.async.wait_group %0;" :: "n"(N) : "memory");
}
DEV_INLINE void ldsm_x4(uint32_t& a0, uint32_t& a1, uint32_t& a2, uint32_t& a3, uint32_t ad) {
    asm volatile("ldmatrix.sync.aligned.m8n8.x4.shared.b16 {%0,%1,%2,%3}, [%4];"
                 : "=r"(a0), "=r"(a1), "=r"(a2), "=r"(a3) : "r"(ad));
}
DEV_INLINE void ldsm_x2(uint32_t& b0, uint32_t& b1, uint32_t ad) {
    asm volatile("ldmatrix.sync.aligned.m8n8.x2.shared.b16 {%0,%1}, [%2];"
                 : "=r"(b0), "=r"(b1) : "r"(ad));
}
DEV_INLINE void mma16816(float* c, uint32_t a0, uint32_t a1, uint32_t a2, uint32_t a3,
                         uint32_t b0, uint32_t b1) {
    asm volatile("mma.sync.aligned.m16n8k16.row.col.f32.bf16.bf16.f32 "
                 "{%0,%1,%2,%3}, {%4,%5,%6,%7}, {%8,%9}, {%0,%1,%2,%3};"
                 : "+f"(c[0]), "+f"(c[1]), "+f"(c[2]), "+f"(c[3])
                 : "r"(a0), "r"(a1), "r"(a2), "r"(a3), "r"(b0), "r"(b1));
}
DEV_INLINE void splitw(float v, __nv_bfloat16& hi, __nv_bfloat16& lo) {
    hi = __float2bfloat16(v);
    lo = __float2bfloat16(v - __bfloat162float(hi));
}

// ---------------- small kernels ----------------------------------------------
// embedding gather, written directly as bf16 hi/lo split
__global__ void k_embed(const int* __restrict__ x, const float* __restrict__ emb) {
    int r = blockIdx.x;
    int tok = x[r];
    float4 v = make_float4(0.f, 0.f, 0.f, 0.f);
    if (tok != 0) v = *(const float4*)(emb + (size_t)tok * H + threadIdx.x * 4);
    size_t base = (size_t)r * H + threadIdx.x * 4;
    float vv[4] = {v.x, v.y, v.z, v.w};
#pragma unroll
    for (int i = 0; i < 4; i++) {
        __nv_bfloat16 hi, lo; splitw(vv[i], hi, lo);
        g_Xs[0][base + i] = hi;
        g_Xs[1][base + i] = lo;
    }
}

// split input-side weights (wih_f | wih_b | wih1)
__global__ void k_prep_wih(const float* __restrict__ wih_f, const float* __restrict__ wih_b,
                           const float* __restrict__ wih1) {
    int r = blockIdx.x;                       // [0, 8192)
    const float* src; __nv_bfloat16 *dh, *dl; int K;
    if (r < 2048)      { src = wih_f + (size_t)r * H;  dh = &g_WFs[0][(size_t)r * H];  dl = &g_WFs[1][(size_t)r * H];  K = H; }
    else if (r < 4096) { int q = r - 2048; src = wih_b + (size_t)q * H;  dh = &g_WBs[0][(size_t)q * H];  dl = &g_WBs[1][(size_t)q * H];  K = H; }
    else               { int q = r - 4096; src = wih1 + (size_t)q * H2; dh = &g_W1s[0][(size_t)q * H2]; dl = &g_W1s[1][(size_t)q * H2]; K = H2; }
    for (int k = threadIdx.x; k < K; k += 256) {
        __nv_bfloat16 hi, lo; splitw(src[k], hi, lo);
        dh[k] = hi; dl[k] = lo;
    }
}

// split layer-1 recurrent weights
__global__ void k_prep_w(const float* __restrict__ whh1, const float* __restrict__ whh2,
                         const float* __restrict__ wih2) {
    int mr = blockIdx.x;                      // [0, 3*4096)
    int mat = mr >> 12, r = mr & 4095;
    const float* W = mat == 0 ? whh1 : (mat == 1 ? whh2 : wih2);
    int g = r >> 10, jglob = r & 1023;
    int bx = jglob >> 3, gr = g * 8 + (jglob & 7);
    const float* src = W + (size_t)r * H2;
#pragma unroll
    for (int q = 0; q < 4; q++) {
        int k = threadIdx.x + q * 256;
        __nv_bfloat16 hi, lo; splitw(src[k], hi, lo);
        g_Wb[mat][bx][0][gr][k] = hi;
        g_Wb[mat][bx][1][gr][k] = lo;
    }
}

// split layer-0 recurrent weights
__global__ void k_prep_w0(const float* __restrict__ whh_f, const float* __restrict__ whh_b) {
    int mr = blockIdx.x;                      // [0, 2*2048)
    int dir = mr >> 11, r = mr & 2047;
    const float* W = dir ? whh_b : whh_f;
    int g = r >> 9, j = r & 511;
    int bx = j >> 3, gr = g * 8 + (j & 7);
    const float* src = W + (size_t)r * H;
#pragma unroll
    for (int q = 0; q < 2; q++) {
        int k = threadIdx.x + q * 256;
        __nv_bfloat16 hi, lo; splitw(src[k], hi, lo);
        g_Wb0[dir][bx][0][gr][k] = hi;
        g_Wb0[dir][bx][1][gr][k] = lo;
    }
}

// split layer-1 initial states
__global__ void k_prep_h(const float* __restrict__ h01, const float* __restrict__ h02) {
    int i = blockIdx.x * 256 + threadIdx.x;   // [0, 131072)
    int which = i >> 16, e = i & 65535;
    int b = e >> 10, k = e & 1023;
    __nv_bfloat16 hi, lo; splitw((which ? h02 : h01)[e], hi, lo);
    if (which) { g_H2s[0][0][b][k] = hi; g_H2s[0][1][b][k] = lo; }
    else       { g_H1s[0][0][b][k] = hi; g_H1s[0][1][b][k] = lo; }
}

// split layer-0 initial states + zero barriers
__global__ void k_prep_h0(const float* __restrict__ h0f, const float* __restrict__ h0b) {
    int i = blockIdx.x * 256 + threadIdx.x;   // [0, 65536)
    if (i == 0) { g_bar0[0] = 0u; g_bar0[1] = 0u; g_bar1 = 0u; }
    int dir = i >> 15, e = i & 32767;
    int b = e >> 9, k = e & 511;
    __nv_bfloat16 hi, lo; splitw((dir ? h0b : h0f)[e], hi, lo);
    g_L0s[dir][0][0][b][k] = hi;
    g_L0s[dir][0][1][b][k] = lo;
}

// ---------------- fp32 GEMM (kept for logits) ---------------------------------
template <int BM>
__global__ void k_gemm_bias(const float* __restrict__ A, const float* __restrict__ Wt,
                            const float* __restrict__ b1, const float* __restrict__ b2,
                            float* __restrict__ C, int K, int N) {
    constexpr int BN = 64, BK = 16, RPT = BM / 16;
    __shared__ float As[BK][BM + 4];
    __shared__ float Bs[BK][BN + 4];
    const int tid = threadIdx.x;
    const int bm = blockIdx.y * BM, bn = blockIdx.x * BN;
    const int tx = tid & 15, ty = tid >> 4;
    u64 acc[RPT][2];
#pragma unroll
    for (int r = 0; r < RPT; r++) { acc[r][0] = 0ull; acc[r][1] = 0ull; }
    for (int k0 = 0; k0 < K; k0 += BK) {
#pragma unroll
        for (int i = tid; i < BM * 4; i += 256) {
            int m = i >> 2, kq = i & 3;
            float4 v = *(const float4*)(A + (size_t)(bm + m) * K + k0 + kq * 4);
            As[kq * 4 + 0][m] = v.x; As[kq * 4 + 1][m] = v.y;
            As[kq * 4 + 2][m] = v.z; As[kq * 4 + 3][m] = v.w;
        }
        {
            int n = tid >> 2, kq = tid & 3;
            float4 v = *(const float4*)(Wt + (size_t)(bn + n) * K + k0 + kq * 4);
            Bs[kq * 4 + 0][n] = v.x; Bs[kq * 4 + 1][n] = v.y;
            Bs[kq * 4 + 2][n] = v.z; Bs[kq * 4 + 3][n] = v.w;
        }
        __syncthreads();
#pragma unroll
        for (int kk = 0; kk < BK; kk++) {
            float2 bv0 = *(const float2*)&Bs[kk][tx * 4];
            float2 bv1 = *(const float2*)&Bs[kk][tx * 4 + 2];
            u64 bp0 = pk2(bv0.x, bv0.y), bp1 = pk2(bv1.x, bv1.y);
#pragma unroll
            for (int r = 0; r < RPT; r++) {
                float a = As[kk][ty * RPT + r];
                u64 ap = pk2(a, a);
                FMA2(acc[r][0], ap, bp0);
                FMA2(acc[r][1], ap, bp1);
            }
        }
        __syncthreads();
    }
    const int ncol = bn + tx * 4;
    float bb0 = b1[ncol + 0] + (b2 ? b2[ncol + 0] : 0.f);
    float bb1 = b1[ncol + 1] + (b2 ? b2[ncol + 1] : 0.f);
    float bb2 = b1[ncol + 2] + (b2 ? b2[ncol + 2] : 0.f);
    float bb3 = b1[ncol + 3] + (b2 ? b2[ncol + 3] : 0.f);
#pragma unroll
    for (int r = 0; r < RPT; r++) {
        float2 v0 = upk2(acc[r][0]);
        float2 v1 = upk2(acc[r][1]);
        float4 o = make_float4(v0.x + bb0, v0.y + bb1, v1.x + bb2, v1.y + bb3);
        *(float4*)(C + (size_t)(bm + ty * RPT + r) * N + ncol) = o;
    }
}

// ---------------- batched split-bf16 HMMA GEMM (phases B, D) ------------------
// C[M,N] = A@W^T + b1 + b2.  Block tile 128x128, K-chunk 32.
// SMEM: A [2 buf][2 split][128][80B] at 0 (40960), W same at 40960, bsum at 81920.
template <int K>
DEV_INLINE void ldc_g(uint32_t smb, int buf,
                      const char* Ahi, const char* Alo,
                      const char* Whi, const char* Wlo,
                      int bm, int bn, int c, int tid) {
#pragma unroll
    for (int q = 0; q < 8; q++) {
        int i = tid + q * 256;
        int sp = (i & 1023) >> 9, rem = i & 511, row = rem >> 2, sg = rem & 3;
        if (i < 1024) {
            const char* src = (sp ? Alo : Ahi) + (size_t)(bm + row) * (K * 2) + c * 64 + sg * 16;
            cpa16(smb + buf * 20480 + sp * 10240 + row * 80 + sg * 16, src);
        } else {
            const char* src = (sp ? Wlo : Whi) + (size_t)(bn + row) * (K * 2) + c * 64 + sg * 16;
            cpa16(smb + 40960 + buf * 20480 + sp * 10240 + row * 80 + sg * 16, src);
        }
    }
    CP_COMMIT();
}

template <int K>
__global__ void __launch_bounds__(256, 2) k_gemm_hmma(
        const __nv_bfloat16* __restrict__ Ahi, const __nv_bfloat16* __restrict__ Alo,
        const __nv_bfloat16* __restrict__ Whi, const __nv_bfloat16* __restrict__ Wlo,
        const float* __restrict__ b1, const float* __restrict__ b2,
        float* __restrict__ C, int N) {
    extern __shared__ char smc[];
    uint32_t smb = smem_u32(smc);
    float* bsum = (float*)(smc + 81920);
    const int tid = threadIdx.x, w = tid >> 5, l = tid & 31;
    const int bm = blockIdx.y * 128, bn = blockIdx.x * 128;
    const int m0w = (w & 3) * 32, n0w = (w >> 2) * 64;

    if (tid < 128) bsum[tid] = b1[bn + tid] + b2[bn + tid];

    float acc[2][8][4];
#pragma unroll
    for (int mt = 0; mt < 2; mt++)
#pragma unroll
        for (int nf = 0; nf < 8; nf++)
#pragma unroll
            for (int i = 0; i < 4; i++) acc[mt][nf][i] = 0.f;

    ldc_g<K>(smb, 0, (const char*)Ahi, (const char*)Alo,
             (const char*)Whi, (const char*)Wlo, bm, bn, 0, tid);
    constexpr int NCH = K / 32;
    for (int c = 0; c < NCH; c++) {
        if (c < NCH - 1) {
            ldc_g<K>(smb, (c + 1) & 1, (const char*)Ahi, (const char*)Alo,
                     (const char*)Whi, (const char*)Wlo, bm, bn, c + 1, tid);
            cp_wait<1>();
        } else cp_wait<0>();
        __syncthreads();
        uint32_t ab = smb + (c & 1) * 20480;
        uint32_t wb = smb + 40960 + (c & 1) * 20480;
#pragma unroll
        for (int ks = 0; ks < 2; ks++) {
            uint32_t ah[2][4], al[2][4];
#pragma unroll
            for (int mt = 0; mt < 2; mt++) {
                uint32_t aa = ab + (uint32_t)(m0w + mt * 16 + (l & 15)) * 80 + (l >> 4) * 16 + ks * 32;
                ldsm_x4(ah[mt][0], ah[mt][1], ah[mt][2], ah[mt][3], aa);
                ldsm_x4(al[mt][0], al[mt][1], al[mt][2], al[mt][3], aa + 10240);
            }
#pragma unroll
            for (int nf = 0; nf < 8; nf++) {
                uint32_t bb = wb + (uint32_t)(n0w + nf * 8 + (l & 7)) * 80 + ((l >> 3) & 1) * 16 + ks * 32;
                uint32_t bh0, bh1, bl0, bl1;
                ldsm_x2(bh0, bh1, bb);
                ldsm_x2(bl0, bl1, bb + 10240);
#pragma unroll
                for (int mt = 0; mt < 2; mt++) {
                    mma16816(acc[mt][nf], ah[mt][0], ah[mt][1], ah[mt][2], ah[mt][3], bh0, bh1);
                    mma16816(acc[mt][nf], al[mt][0], al[mt][1], al[mt][2], al[mt][3], bh0, bh1);
                    mma16816(acc[mt][nf], ah[mt][0], ah[mt][1], ah[mt][2], ah[mt][3], bl0, bl1);
                }
            }
        }
        __syncthreads();
    }
    // epilogue: bias + direct stores
#pragma unroll
    for (int mt = 0; mt < 2; mt++) {
        int row = bm + m0w + mt * 16 + (l >> 2);
#pragma unroll
        for (int nf = 0; nf < 8; nf++) {
            int lc = n0w + nf * 8 + (l & 3) * 2;
            float bs0 = bsum[lc], bs1 = bsum[lc + 1];
            float* p0 = C + (size_t)row * N + bn + lc;
            float* p1 = C + (size_t)(row + 8) * N + bn + lc;
            *(float2*)p0 = make_float2(acc[mt][nf][0] + bs0, acc[mt][nf][1] + bs1);
            *(float2*)p1 = make_float2(acc[mt][nf][2] + bs0, acc[mt][nf][3] + bs1);
        }
    }
}

// ---------------- shared recurrent HMMA machinery ------------------------------
template <int HROWB, int WROWB>
DEV_INLINE void load_chunk(uint32_t smb, int buf, const char* Wsrc, const char* Hsrc,
                           int c, int tid) {
#pragma unroll
    for (int q = 0; q < 6; q++) {
        int i = tid + q * 256;
        if (i < 1024) {
            int sp = i >> 9, rem = i & 511, row = rem >> 3, sg = rem & 7;
            cpa16(smb + buf * 18432 + sp * 9216 + row * 144 + sg * 16,
                  Hsrc + (size_t)sp * (64 * HROWB) + row * HROWB + c * 128 + sg * 16);
        } else {
            int jj = i - 1024, sp = jj >> 8, rem = jj & 255, row = rem >> 3, sg = rem & 7;
            cpa16(smb + 36864 + buf * 9216 + sp * 4608 + row * 144 + sg * 16,
                  Wsrc + (size_t)sp * (32 * WROWB) + row * WROWB + c * 128 + sg * 16);
        }
    }
    CP_COMMIT();
}

template <int NCH, int HROWB, int WROWB>
DEV_INLINE void hmma_gemm(uint32_t smb, const char* Wsrc, const char* Hsrc,
                          float* acc0, float* acc1, int tid,
                          uint32_t aoff, int n0, int brow, uint32_t bko) {
    load_chunk<HROWB, WROWB>(smb, 0, Wsrc, Hsrc, 0, tid);
    for (int c = 0; c < NCH; c++) {
        if (c < NCH - 1) {
            load_chunk<HROWB, WROWB>(smb, (c + 1) & 1, Wsrc, Hsrc, c + 1, tid);
            cp_wait<1>();
        } else cp_wait<0>();
        __syncthreads();
        uint32_t hb = smb + (c & 1) * 18432;
        uint32_t wb = smb + 36864 + (c & 1) * 9216;
#pragma unroll
        for (int ks = 0; ks < 4; ks++) {
            uint32_t a0, a1, a2, a3, l0, l1, l2, l3;
            ldsm_x4(a0, a1, a2, a3, hb + aoff + ks * 32);
            ldsm_x4(l0, l1, l2, l3, hb + 9216 + aoff + ks * 32);
#pragma unroll
            for (int nt = 0; nt < 2; nt++) {
                uint32_t bh0, bh1, bl0, bl1;
                uint32_t bb = wb + (uint32_t)(n0 + nt * 8 + brow) * 144 + bko + ks * 32;
                ldsm_x2(bh0, bh1, bb);
                ldsm_x2(bl0, bl1, bb + 4608);
                float* ac = nt ? acc1 : acc0;
                mma16816(ac, a0, a1, a2, a3, bh0, bh1);
                mma16816(ac, l0, l1, l2, l3, bh0, bh1);
                mma16816(ac, a0, a1, a2, a3, bl0, bl1);
            }
        }
        __syncthreads();
    }
}

DEV_INLINE void store_frag(float* Ex, int m0, int n0, int l, const float* ac0, const float* ac1) {
#pragma unroll
    for (int nt = 0; nt < 2; nt++) {
        const float* ac = nt ? ac1 : ac0;
        int er = m0 + (l >> 2), ec = n0 + nt * 8 + (l & 3) * 2;
        Ex[er * 36 + ec] = ac[0];       Ex[er * 36 + ec + 1] = ac[1];
        Ex[(er + 8) * 36 + ec] = ac[2]; Ex[(er + 8) * 36 + ec + 1] = ac[3];
    }
}

// ---------------- HMMA layer-0 ------------------------------------------------
__global__ void __launch_bounds__(256, 1) k_l0_hmma(
        const float* __restrict__ c0f, const float* __restrict__ c0b) {
    extern __shared__ char smc[];
    uint32_t smb = smem_u32(smc);
    float* Ex = (float*)(smc + 55296);
    const int tid = threadIdx.x, w = tid >> 5, l = tid & 31;
    const int dir = blockIdx.x >> 6, jb = blockIdx.x & 63;
    const int m0 = (w & 3) * 16, n0 = (w >> 2) * 16;
    const uint32_t aoff = (uint32_t)((m0 + (l & 15)) * 144 + (l >> 4) * 16);
    const int brow = l & 7;
    const uint32_t bko = (uint32_t)(((l >> 3) & 1) * 16);
    const int j = tid & 7, b0 = tid >> 3;
    const int jglob = jb * 8 + j;
    const float* preB = dir ? g_GB : g_GF;
    const float* c0   = dir ? c0b  : c0f;
    const char* Wsrc = (const char*)&g_Wb0[dir][jb][0][0][0];

    float cst[2] = { c0[b0 * H + jglob], c0[(b0 + 32) * H + jglob] };

    for (int t = 0; t < S; t++) {
        int p = t & 1;
        const float* pre = preB + (size_t)(dir ? (S - 1 - t) : t) * Bz * G4;
        float pg[2][4];
#pragma unroll
        for (int r = 0; r < 2; r++) {
            const float* pb = pre + (size_t)(b0 + r * 32) * G4;
            pg[r][0] = __ldg(pb + 0 * H + jglob);
            pg[r][1] = __ldg(pb + 1 * H + jglob);
            pg[r][2] = __ldg(pb + 2 * H + jglob);
            pg[r][3] = __ldg(pb + 3 * H + jglob);
        }
        float acc0[4] = {0, 0, 0, 0}, acc1[4] = {0, 0, 0, 0};
        hmma_gemm<8, 1024, 1024>(smb, Wsrc, (const char*)&g_L0s[dir][p][0][0][0],
                                 acc0, acc1, tid, aoff, n0, brow, bko);
        store_frag(Ex, m0, n0, l, acc0, acc1);
        __syncthreads();
#pragma unroll
        for (int r = 0; r < 2; r++) {
            int b = b0 + r * 32;
            float gi = Ex[b * 36 + j]      + pg[r][0];
            float gf = Ex[b * 36 + 8 + j]  + pg[r][1];
            float gg = Ex[b * 36 + 16 + j] + pg[r][2];
            float go = Ex[b * 36 + 24 + j] + pg[r][3];
            float c2 = sigf(gf) * cst[r] + sigf(gi) * tanhf(gg);
            cst[r] = c2;
            float h = sigf(go) * tanhf(c2);
            __nv_bfloat16 hi, lo; splitw(h, hi, lo);
            size_t xe = ((size_t)t * Bz + b) * H2 + dir * H + jglob;
            g_XINs[0][xe] = hi;
            g_XINs[1][xe] = lo;
            g_L0s[dir][p ^ 1][0][b][jglob] = hi;
            g_L0s[dir][p ^ 1][1][b][jglob] = lo;
        }
        __syncthreads();
        gbar(&g_bar0[dir], 64u * (t + 1));
    }
}

// ---------------- HMMA layer-1 (proven R12) -----------------------------------
__global__ void __launch_bounds__(256, 1) k_l1_hmma(
        const float* __restrict__ c02,
        const float* __restrict__ bih2, const float* __restrict__ bhh2) {
    extern __shared__ char smc[];
    uint32_t smb = smem_u32(smc);
    float* Ex = (float*)(smc + 55296);
    const int tid = threadIdx.x, w = tid >> 5, l = tid & 31, bx = blockIdx.x;
    const int m0 = (w & 3) * 16, n0 = (w >> 2) * 16;
    const uint32_t aoff = (uint32_t)((m0 + (l & 15)) * 144 + (l >> 4) * 16);
    const int brow = l & 7;
    const uint32_t bko = (uint32_t)(((l >> 3) & 1) * 16);
    const int j = tid & 7, b0 = tid >> 3;
    const int jglob = bx * 8 + j;

    float c2[2] = { c02[b0 * H2 + jglob], c02[(b0 + 32) * H2 + jglob] };
    float bsr[4];
#pragma unroll
    for (int g = 0; g < 4; g++) bsr[g] = bih2[g * H2 + jglob] + bhh2[g * H2 + jglob];

    for (int t = 0; t < S; t++) {
        int p = t & 1;
        float acc0[4] = {0, 0, 0, 0}, acc1[4] = {0, 0, 0, 0};
        hmma_gemm<16, 2048, 2048>(smb, (const char*)&g_Wb[0][bx][0][0][0],
                                  (const char*)&g_H1s[p][0][0][0],
                                  acc0, acc1, tid, aoff, n0, brow, bko);
        store_frag(Ex, m0, n0, l, acc0, acc1);
        __syncthreads();
#pragma unroll
        for (int r = 0; r < 2; r++) {
            int b = b0 + r * 32;
            const float* pb = g_G1 + ((size_t)t * Bz + b) * G8;
            float gi = Ex[b * 36 + j]      + __ldg(pb + 0 * H2 + jglob);
            float gf = Ex[b * 36 + 8 + j]  + __ldg(pb + 1 * H2 + jglob);
            float gg = Ex[b * 36 + 16 + j] + __ldg(pb + 2 * H2 + jglob);
            float go = Ex[b * 36 + 24 + j] + __ldg(pb + 3 * H2 + jglob);
            float cc = sigf(gf) * c2[r] + sigf(gi) * tanhf(gg);
            float h1 = sigf(go) * tanhf(cc);
            __nv_bfloat16 hi, lo; splitw(h1, hi, lo);
            g_H1s[p ^ 1][0][b][jglob] = hi;
            g_H1s[p ^ 1][1][b][jglob] = lo;
        }
        gbar(&g_bar1, 128u * (t + 1));

        acc0[0] = acc0[1] = acc0[2] = acc0[3] = 0.f;
        acc1[0] = acc1[1] = acc1[2] = acc1[3] = 0.f;
        hmma_gemm<16, 2048, 2048>(smb, (const char*)&g_Wb[1][bx][0][0][0],
                                  (const char*)&g_H2s[p][0][0][0],
                                  acc0, acc1, tid, aoff, n0, brow, bko);
        hmma_gemm<16, 2048, 2048>(smb, (const char*)&g_Wb[2][bx][0][0][0],
                                  (const char*)&g_H1s[p ^ 1][0][0][0],
                                  acc0, acc1, tid, aoff, n0, brow, bko);
        store_frag(Ex, m0, n0, l, acc0, acc1);
        __syncthreads();
#pragma unroll
        for (int r = 0; r < 2; r++) {
            int b = b0 + r * 32;
            float gi = Ex[b * 36 + j]      + bsr[0];
            float gf = Ex[b * 36 + 8 + j]  + bsr[1];
            float gg = Ex[b * 36 + 16 + j] + bsr[2];
            float go = Ex[b * 36 + 24 + j] + bsr[3];
            float cn = sigf(gf) * c2[r] + sigf(gi) * tanhf(gg);
            c2[r] = cn;
            float h2 = sigf(go) * tanhf(cn);
            __nv_bfloat16 hi, lo; splitw(h2, hi, lo);
            g_H2s[p ^ 1][0][b][jglob] = hi;
            g_H2s[p ^ 1][1][b][jglob] = lo;
            if (t == S - 1) g_H2R[(size_t)b * H2 + jglob] = h2;
        }
        __syncthreads();
    }
}

// ---------------- launch -----------------------------------------------------
extern "C" void kernel_launch(void* const* d_in, const int* in_sizes, int n_in,
                              void* d_out, int out_size) {
    const int*   x     = (const int*)  d_in[0];
    const float* emb   = (const float*)d_in[1];
    const float* h0f   = (const float*)d_in[2];
    const float* c0f   = (const float*)d_in[3];
    const float* h0b   = (const float*)d_in[4];
    const float* c0b   = (const float*)d_in[5];
    const float* h01   = (const float*)d_in[6];
    const float* h02   = (const float*)d_in[7];
    const float* c02   = (const float*)d_in[8];
    const float* wih_f = (const float*)d_in[9];
    const float* bih_f = (const float*)d_in[11];
    const float* bhh_f = (const float*)d_in[12];
    const float* wih_b = (const float*)d_in[13];
    const float* whh_f = (const float*)d_in[10];
    const float* whh_b = (const float*)d_in[14];
    const float* bih_b = (const float*)d_in[15];
    const float* bhh_b = (const float*)d_in[16];
    const float* wih1  = (const float*)d_in[17];
    const float* whh1  = (const float*)d_in[18];
    const float* bih1  = (const float*)d_in[19];
    const float* bhh1  = (const float*)d_in[20];
    const float* wih2  = (const float*)d_in[21];
    const float* whh2  = (const float*)d_in[22];
    const float* bih2  = (const float*)d_in[23];
    const float* bhh2  = (const float*)d_in[24];
    const float* wlin  = (const float*)d_in[25];
    const float* blin  = (const float*)d_in[26];
    float* out = (float*)d_out;

    float *pGF, *pGB, *pG1, *pH2R;
    cudaGetSymbolAddress((void**)&pGF,  g_GF);
    cudaGetSymbolAddress((void**)&pGB,  g_GB);
    cudaGetSymbolAddress((void**)&pG1,  g_G1);
    cudaGetSymbolAddress((void**)&pH2R, g_H2R);
    __nv_bfloat16 *pXs, *pXINs, *pWF, *pWB, *pW1;
    cudaGetSymbolAddress((void**)&pXs,   g_Xs);
    cudaGetSymbolAddress((void**)&pXINs, g_XINs);
    cudaGetSymbolAddress((void**)&pWF,   g_WFs);
    cudaGetSymbolAddress((void**)&pWB,   g_WBs);
    cudaGetSymbolAddress((void**)&pW1,   g_W1s);

    const int HM_SM = 64512;
    const int GM_SM = 82432;
    cudaFuncSetAttribute(k_l0_hmma, cudaFuncAttributeMaxDynamicSharedMemorySize, HM_SM);
    cudaFuncSetAttribute(k_l1_hmma, cudaFuncAttributeMaxDynamicSharedMemorySize, HM_SM);
    cudaFuncSetAttribute(k_gemm_hmma<512>,  cudaFuncAttributeMaxDynamicSharedMemorySize, GM_SM);
    cudaFuncSetAttribute(k_gemm_hmma<1024>, cudaFuncAttributeMaxDynamicSharedMemorySize, GM_SM);

    // A: gather (split) + prep splits (also zeroes barrier counters each replay)
    k_embed<<<R, 128>>>(x, emb);
    k_prep_h0<<<256, 256>>>(h0f, h0b);
    k_prep_h<<<512, 256>>>(h01, h02);
    k_prep_w0<<<2 * 2048, 256>>>(whh_f, whh_b);
    k_prep_w<<<3 * 4096, 256>>>(whh1, whh2, wih2);
    k_prep_wih<<<8192, 256>>>(wih_f, wih_b, wih1);

    // B: hoisted input-side gate GEMMs for layer 0 (HMMA)
    k_gemm_hmma<512><<<dim3(G4 / 128, R / 128), 256, GM_SM>>>(
        pXs, pXs + (size_t)R * H, pWF, pWF + (size_t)G4 * H, bih_f, bhh_f, pGF, G4);
    k_gemm_hmma<512><<<dim3(G4 / 128, R / 128), 256, GM_SM>>>(
        pXs, pXs + (size_t)R * H, pWB, pWB + (size_t)G4 * H, bih_b, bhh_b, pGB, G4);

    // C: HMMA persistent bidirectional layer-0 recurrence
    k_l0_hmma<<<128, 256, HM_SM>>>(c0f, c0b);

    // D: hoisted input-side GEMM for lstm1 (HMMA)
    k_gemm_hmma<1024><<<dim3(G8 / 128, R / 128), 256, GM_SM>>>(
        pXINs, pXINs + (size_t)R * H2, pW1, pW1 + (size_t)G8 * H2, bih1, bhh1, pG1, G8);

    // E: HMMA persistent layer-1 recurrence
    k_l1_hmma<<<128, 256, HM_SM>>>(c02, bih2, bhh2);

    // F: logits (fp32, memory-bound)
    k_gemm_bias<64><<<dim3(V / 64, 1), 256>>>(pH2R, wlin, blin, nullptr, out, H2, V);
}

// round 15
// speedup vs baseline: 4.3173x; 1.0756x over previous
#include <cuda_runtime.h>
#include <cuda_bf16.h>
#include <cstdint>

#define DEV_INLINE __device__ __forceinline__
typedef unsigned long long u64;

static constexpr int V  = 32000;
static constexpr int H  = 512;
static constexpr int Bz = 64;
static constexpr int S  = 128;
static constexpr int H2 = 1024;
static constexpr int G4 = 2048;
static constexpr int G8 = 4096;
static constexpr int R  = S * Bz;

// ---------------- scratch ---------------------------------------------------
__device__ float g_GF  [R * G4];
__device__ float g_GB  [R * G4];
__device__ float g_G1  [R * G8];
// split embeddings / XIN (A-operands of phases B and D)
__device__ __align__(16) __nv_bfloat16 g_Xs  [2][R * H];
__device__ __align__(16) __nv_bfloat16 g_XINs[2][R * H2];
// split input-side weights
__device__ __align__(16) __nv_bfloat16 g_WFs[2][G4 * H];
__device__ __align__(16) __nv_bfloat16 g_WBs[2][G4 * H];
__device__ __align__(16) __nv_bfloat16 g_W1s[2][G8 * H2];
// split logits weight + padded split h2 (A operand of phase F)
__device__ __align__(16) __nv_bfloat16 g_WLs[2][(size_t)V * H2];
__device__ __align__(16) __nv_bfloat16 g_H2Rs[2][128 * H2];
// layer-1 split weights: [mat][block][hi|lo][32 gate-rows][1024 k]
__device__ __align__(16) __nv_bfloat16 g_Wb [3][128][2][32][1024];
// layer-0 split weights: [dir][block][hi|lo][32 gate-rows][512 k]
__device__ __align__(16) __nv_bfloat16 g_Wb0[2][64][2][32][512];
// recurrent split states
__device__ __align__(16) __nv_bfloat16 g_H1s[2][2][Bz][H2];
__device__ __align__(16) __nv_bfloat16 g_H2s[2][2][Bz][H2];
__device__ __align__(16) __nv_bfloat16 g_L0s[2][2][2][Bz][H];
__device__ unsigned g_bar0[2];
__device__ unsigned g_bar1;

// ---------------- helpers ---------------------------------------------------
DEV_INLINE u64 pk2(float x, float y) {
    u64 r; asm("mov.b64 %0, {%1, %2};" : "=l"(r) : "f"(x), "f"(y)); return r;
}
DEV_INLINE float2 upk2(u64 v) {
    float2 r; asm("mov.b64 {%0, %1}, %2;" : "=f"(r.x), "=f"(r.y) : "l"(v)); return r;
}
#define FMA2(d, a, b) asm("fma.rn.f32x2 %0, %1, %2, %0;" : "+l"(d) : "l"(a), "l"(b))
DEV_INLINE float sigf(float x) { return 1.f / (1.f + expf(-x)); }

DEV_INLINE void gbar(unsigned* cnt, unsigned target) {
    __threadfence();
    __syncthreads();
    if (threadIdx.x == 0) {
        atomicAdd(cnt, 1u);
        while (*(volatile unsigned*)cnt < target) __nanosleep(32);
    }
    __syncthreads();
}

DEV_INLINE uint32_t smem_u32(const void* p) {
    uint32_t a;
    asm("{ .reg .u64 t; cvta.to.shared.u64 t, %1; cvt.u32.u64 %0, t; }" : "=r"(a) : "l"(p));
    return a;
}
DEV_INLINE void cpa16(uint32_t dst, const void* src) {
    asm volatile("cp.async.cg.shared.global [%0], [%1], 16;" :: "r"(dst), "l"(src) : "memory");
}
#define CP_COMMIT() asm volatile("cp.async.commit_group;" ::: "memory")
template <int N> DEV_INLINE void cp_wait() {
    asm volatile("cp.async.wait_group %0;" :: "n"(N) : "memory");
}
DEV_INLINE void ldsm_x4(uint32_t& a0, uint32_t& a1, uint32_t& a2, uint32_t& a3, uint32_t ad) {
    asm volatile("ldmatrix.sync.aligned.m8n8.x4.shared.b16 {%0,%1,%2,%3}, [%4];"
                 : "=r"(a0), "=r"(a1), "=r"(a2), "=r"(a3) : "r"(ad));
}
DEV_INLINE void ldsm_x2(uint32_t& b0, uint32_t& b1, uint32_t ad) {
    asm volatile("ldmatrix.sync.aligned.m8n8.x2.shared.b16 {%0,%1}, [%2];"
                 : "=r"(b0), "=r"(b1) : "r"(ad));
}
DEV_INLINE void mma16816(float* c, uint32_t a0, uint32_t a1, uint32_t a2, uint32_t a3,
                         uint32_t b0, uint32_t b1) {
    asm volatile("mma.sync.aligned.m16n8k16.row.col.f32.bf16.bf16.f32 "
                 "{%0,%1,%2,%3}, {%4,%5,%6,%7}, {%8,%9}, {%0,%1,%2,%3};"
                 : "+f"(c[0]), "+f"(c[1]), "+f"(c[2]), "+f"(c[3])
                 : "r"(a0), "r"(a1), "r"(a2), "r"(a3), "r"(b0), "r"(b1));
}
DEV_INLINE void splitw(float v, __nv_bfloat16& hi, __nv_bfloat16& lo) {
    hi = __float2bfloat16(v);
    lo = __float2bfloat16(v - __bfloat162float(hi));
}

// ---------------- small kernels ----------------------------------------------
__global__ void k_embed(const int* __restrict__ x, const float* __restrict__ emb) {
    int r = blockIdx.x;
    int tok = x[r];
    float4 v = make_float4(0.f, 0.f, 0.f, 0.f);
    if (tok != 0) v = *(const float4*)(emb + (size_t)tok * H + threadIdx.x * 4);
    size_t base = (size_t)r * H + threadIdx.x * 4;
    float vv[4] = {v.x, v.y, v.z, v.w};
#pragma unroll
    for (int i = 0; i < 4; i++) {
        __nv_bfloat16 hi, lo; splitw(vv[i], hi, lo);
        g_Xs[0][base + i] = hi;
        g_Xs[1][base + i] = lo;
    }
}

__global__ void k_prep_wih(const float* __restrict__ wih_f, const float* __restrict__ wih_b,
                           const float* __restrict__ wih1) {
    int r = blockIdx.x;                       // [0, 8192)
    const float* src; __nv_bfloat16 *dh, *dl; int K;
    if (r < 2048)      { src = wih_f + (size_t)r * H;  dh = &g_WFs[0][(size_t)r * H];  dl = &g_WFs[1][(size_t)r * H];  K = H; }
    else if (r < 4096) { int q = r - 2048; src = wih_b + (size_t)q * H;  dh = &g_WBs[0][(size_t)q * H];  dl = &g_WBs[1][(size_t)q * H];  K = H; }
    else               { int q = r - 4096; src = wih1 + (size_t)q * H2; dh = &g_W1s[0][(size_t)q * H2]; dl = &g_W1s[1][(size_t)q * H2]; K = H2; }
    for (int k = threadIdx.x; k < K; k += 256) {
        __nv_bfloat16 hi, lo; splitw(src[k], hi, lo);
        dh[k] = hi; dl[k] = lo;
    }
}

__global__ void k_prep_wlin(const float* __restrict__ wlin) {
    int r = blockIdx.x;                       // [0, 32000)
    const float* src = wlin + (size_t)r * H2;
    size_t o = (size_t)r * H2;
#pragma unroll
    for (int q = 0; q < 4; q++) {
        int k = threadIdx.x + q * 256;
        __nv_bfloat16 hi, lo; splitw(src[k], hi, lo);
        g_WLs[0][o + k] = hi;
        g_WLs[1][o + k] = lo;
    }
}

__global__ void k_prep_w(const float* __restrict__ whh1, const float* __restrict__ whh2,
                         const float* __restrict__ wih2) {
    int mr = blockIdx.x;                      // [0, 3*4096)
    int mat = mr >> 12, r = mr & 4095;
    const float* W = mat == 0 ? whh1 : (mat == 1 ? whh2 : wih2);
    int g = r >> 10, jglob = r & 1023;
    int bx = jglob >> 3, gr = g * 8 + (jglob & 7);
    const float* src = W + (size_t)r * H2;
#pragma unroll
    for (int q = 0; q < 4; q++) {
        int k = threadIdx.x + q * 256;
        __nv_bfloat16 hi, lo; splitw(src[k], hi, lo);
        g_Wb[mat][bx][0][gr][k] = hi;
        g_Wb[mat][bx][1][gr][k] = lo;
    }
}

__global__ void k_prep_w0(const float* __restrict__ whh_f, const float* __restrict__ whh_b) {
    int mr = blockIdx.x;                      // [0, 2*2048)
    int dir = mr >> 11, r = mr & 2047;
    const float* W = dir ? whh_b : whh_f;
    int g = r >> 9, j = r & 511;
    int bx = j >> 3, gr = g * 8 + (j & 7);
    const float* src = W + (size_t)r * H;
#pragma unroll
    for (int q = 0; q < 2; q++) {
        int k = threadIdx.x + q * 256;
        __nv_bfloat16 hi, lo; splitw(src[k], hi, lo);
        g_Wb0[dir][bx][0][gr][k] = hi;
        g_Wb0[dir][bx][1][gr][k] = lo;
    }
}

__global__ void k_prep_h(const float* __restrict__ h01, const float* __restrict__ h02) {
    int i = blockIdx.x * 256 + threadIdx.x;   // [0, 131072)
    int which = i >> 16, e = i & 65535;
    int b = e >> 10, k = e & 1023;
    __nv_bfloat16 hi, lo; splitw((which ? h02 : h01)[e], hi, lo);
    if (which) { g_H2s[0][0][b][k] = hi; g_H2s[0][1][b][k] = lo; }
    else       { g_H1s[0][0][b][k] = hi; g_H1s[0][1][b][k] = lo; }
}

// split layer-0 initial states + zero barriers + zero h2 pad rows
__global__ void k_prep_h0(const float* __restrict__ h0f, const float* __restrict__ h0b) {
    int i = blockIdx.x * 256 + threadIdx.x;   // [0, 65536)
    if (i == 0) { g_bar0[0] = 0u; g_bar0[1] = 0u; g_bar1 = 0u; }
    // zero rows 64..127 of the padded logits A operand
    g_H2Rs[0][65536 + i] = __float2bfloat16(0.f);
    g_H2Rs[1][65536 + i] = __float2bfloat16(0.f);
    int dir = i >> 15, e = i & 32767;
    int b = e >> 9, k = e & 511;
    __nv_bfloat16 hi, lo; splitw((dir ? h0b : h0f)[e], hi, lo);
    g_L0s[dir][0][0][b][k] = hi;
    g_L0s[dir][0][1][b][k] = lo;
}

// ---------------- batched split-bf16 HMMA GEMM (phases B, D, F) ---------------
// C[M,N] = A@W^T + b1 (+b2).  Block tile 128x128, K-chunk 32.
// SMEM: A [2 buf][2 split][128][80B] at 0 (40960), W same at 40960, bsum at 81920.
template <int K>
DEV_INLINE void ldc_g(uint32_t smb, int buf,
                      const char* Ahi, const char* Alo,
                      const char* Whi, const char* Wlo,
                      int bm, int bn, int c, int tid) {
#pragma unroll
    for (int q = 0; q < 8; q++) {
        int i = tid + q * 256;
        int sp = (i & 1023) >> 9, rem = i & 511, row = rem >> 2, sg = rem & 3;
        if (i < 1024) {
            const char* src = (sp ? Alo : Ahi) + (size_t)(bm + row) * (K * 2) + c * 64 + sg * 16;
            cpa16(smb + buf * 20480 + sp * 10240 + row * 80 + sg * 16, src);
        } else {
            const char* src = (sp ? Wlo : Whi) + (size_t)(bn + row) * (K * 2) + c * 64 + sg * 16;
            cpa16(smb + 40960 + buf * 20480 + sp * 10240 + row * 80 + sg * 16, src);
        }
    }
    CP_COMMIT();
}

template <int K>
__global__ void __launch_bounds__(256, 2) k_gemm_hmma(
        const __nv_bfloat16* __restrict__ Ahi, const __nv_bfloat16* __restrict__ Alo,
        const __nv_bfloat16* __restrict__ Whi, const __nv_bfloat16* __restrict__ Wlo,
        const float* __restrict__ b1, const float* __restrict__ b2,
        float* __restrict__ C, int N, int Mvalid) {
    extern __shared__ char smc[];
    uint32_t smb = smem_u32(smc);
    float* bsum = (float*)(smc + 81920);
    const int tid = threadIdx.x, w = tid >> 5, l = tid & 31;
    const int bm = blockIdx.y * 128, bn = blockIdx.x * 128;
    const int m0w = (w & 3) * 32, n0w = (w >> 2) * 64;

    if (tid < 128) bsum[tid] = b1[bn + tid] + (b2 ? b2[bn + tid] : 0.f);

    float acc[2][8][4];
#pragma unroll
    for (int mt = 0; mt < 2; mt++)
#pragma unroll
        for (int nf = 0; nf < 8; nf++)
#pragma unroll
            for (int i = 0; i < 4; i++) acc[mt][nf][i] = 0.f;

    ldc_g<K>(smb, 0, (const char*)Ahi, (const char*)Alo,
             (const char*)Whi, (const char*)Wlo, bm, bn, 0, tid);
    constexpr int NCH = K / 32;
    for (int c = 0; c < NCH; c++) {
        if (c < NCH - 1) {
            ldc_g<K>(smb, (c + 1) & 1, (const char*)Ahi, (const char*)Alo,
                     (const char*)Whi, (const char*)Wlo, bm, bn, c + 1, tid);
            cp_wait<1>();
        } else cp_wait<0>();
        __syncthreads();
        uint32_t ab = smb + (c & 1) * 20480;
        uint32_t wb = smb + 40960 + (c & 1) * 20480;
#pragma unroll
        for (int ks = 0; ks < 2; ks++) {
            uint32_t ah[2][4], al[2][4];
#pragma unroll
            for (int mt = 0; mt < 2; mt++) {
                uint32_t aa = ab + (uint32_t)(m0w + mt * 16 + (l & 15)) * 80 + (l >> 4) * 16 + ks * 32;
                ldsm_x4(ah[mt][0], ah[mt][1], ah[mt][2], ah[mt][3], aa);
                ldsm_x4(al[mt][0], al[mt][1], al[mt][2], al[mt][3], aa + 10240);
            }
#pragma unroll
            for (int nf = 0; nf < 8; nf++) {
                uint32_t bb = wb + (uint32_t)(n0w + nf * 8 + (l & 7)) * 80 + ((l >> 3) & 1) * 16 + ks * 32;
                uint32_t bh0, bh1, bl0, bl1;
                ldsm_x2(bh0, bh1, bb);
                ldsm_x2(bl0, bl1, bb + 10240);
#pragma unroll
                for (int mt = 0; mt < 2; mt++) {
                    mma16816(acc[mt][nf], ah[mt][0], ah[mt][1], ah[mt][2], ah[mt][3], bh0, bh1);
                    mma16816(acc[mt][nf], al[mt][0], al[mt][1], al[mt][2], al[mt][3], bh0, bh1);
                    mma16816(acc[mt][nf], ah[mt][0], ah[mt][1], ah[mt][2], ah[mt][3], bl0, bl1);
                }
            }
        }
        __syncthreads();
    }
#pragma unroll
    for (int mt = 0; mt < 2; mt++) {
        int row = bm + m0w + mt * 16 + (l >> 2);
#pragma unroll
        for (int nf = 0; nf < 8; nf++) {
            int lc = n0w + nf * 8 + (l & 3) * 2;
            float bs0 = bsum[lc], bs1 = bsum[lc + 1];
            if (row < Mvalid)
                *(float2*)(C + (size_t)row * N + bn + lc) =
                    make_float2(acc[mt][nf][0] + bs0, acc[mt][nf][1] + bs1);
            if (row + 8 < Mvalid)
                *(float2*)(C + (size_t)(row + 8) * N + bn + lc) =
                    make_float2(acc[mt][nf][2] + bs0, acc[mt][nf][3] + bs1);
        }
    }
}

// ---------------- shared recurrent HMMA machinery (chunk k=256) ----------------
// SMEM: H [2 buf][2 split][64 rows][528B]  = 135168 B at 0
//       W [2 buf][2 split][32 rows][528B]  = 67584 B at 135168
//       Ex [64][36] fp32 = 9216 B at 202752.  Total 211968 B.
static constexpr int RS   = 528;        // smem row stride bytes
static constexpr int HSPL = 64 * RS;    // 33792
static constexpr int HBUF = 2 * HSPL;   // 67584
static constexpr int WBASE = 2 * HBUF;  // 135168
static constexpr int WSPL = 32 * RS;    // 16896
static constexpr int WBUF = 2 * WSPL;   // 33792
static constexpr int EXOFF = WBASE + 2 * WBUF;  // 202752

template <int HROWB, int WROWB>
DEV_INLINE void load_chunk(uint32_t smb, int buf, const char* Wsrc, const char* Hsrc,
                           int c, int tid) {
#pragma unroll
    for (int q = 0; q < 24; q++) {
        int i = tid + q * 256;
        if (i < 4096) {
            int sp = i >> 11, rem = i & 2047, row = rem >> 5, sg = rem & 31;
            cpa16(smb + buf * HBUF + sp * HSPL + row * RS + sg * 16,
                  Hsrc + (size_t)sp * (64 * HROWB) + row * HROWB + c * 512 + sg * 16);
        } else {
            int jj = i - 4096, sp = jj >> 10, rem = jj & 1023, row = rem >> 5, sg = rem & 31;
            cpa16(smb + WBASE + buf * WBUF + sp * WSPL + row * RS + sg * 16,
                  Wsrc + (size_t)sp * (32 * WROWB) + row * WROWB + c * 512 + sg * 16);
        }
    }
    CP_COMMIT();
}

template <int NCH, int HROWB, int WROWB>
DEV_INLINE void hmma_gemm(uint32_t smb, const char* Wsrc, const char* Hsrc,
                          float* acc0, float* acc1, int tid,
                          uint32_t aoff, int n0, int brow, uint32_t bko) {
    load_chunk<HROWB, WROWB>(smb, 0, Wsrc, Hsrc, 0, tid);
    for (int c = 0; c < NCH; c++) {
        if (c < NCH - 1) {
            load_chunk<HROWB, WROWB>(smb, (c + 1) & 1, Wsrc, Hsrc, c + 1, tid);
            cp_wait<1>();
        } else cp_wait<0>();
        __syncthreads();
        uint32_t hb = smb + (c & 1) * HBUF;
        uint32_t wb = smb + WBASE + (c & 1) * WBUF;
#pragma unroll
        for (int ks = 0; ks < 16; ks++) {
            uint32_t a0, a1, a2, a3, l0, l1, l2, l3;
            ldsm_x4(a0, a1, a2, a3, hb + aoff + ks * 32);
            ldsm_x4(l0, l1, l2, l3, hb + HSPL + aoff + ks * 32);
#pragma unroll
            for (int nt = 0; nt < 2; nt++) {
                uint32_t bh0, bh1, bl0, bl1;
                uint32_t bb = wb + (uint32_t)(n0 + nt * 8 + brow) * RS + bko + ks * 32;
                ldsm_x2(bh0, bh1, bb);
                ldsm_x2(bl0, bl1, bb + WSPL);
                float* ac = nt ? acc1 : acc0;
                mma16816(ac, a0, a1, a2, a3, bh0, bh1);
                mma16816(ac, l0, l1, l2, l3, bh0, bh1);
                mma16816(ac, a0, a1, a2, a3, bl0, bl1);
            }
        }
        __syncthreads();
    }
}

DEV_INLINE void store_frag(float* Ex, int m0, int n0, int l, const float* ac0, const float* ac1) {
#pragma unroll
    for (int nt = 0; nt < 2; nt++) {
        const float* ac = nt ? ac1 : ac0;
        int er = m0 + (l >> 2), ec = n0 + nt * 8 + (l & 3) * 2;
        Ex[er * 36 + ec] = ac[0];       Ex[er * 36 + ec + 1] = ac[1];
        Ex[(er + 8) * 36 + ec] = ac[2]; Ex[(er + 8) * 36 + ec + 1] = ac[3];
    }
}

// ---------------- HMMA layer-0 ------------------------------------------------
__global__ void __launch_bounds__(256, 1) k_l0_hmma(
        const float* __restrict__ c0f, const float* __restrict__ c0b) {
    extern __shared__ char smc[];
    uint32_t smb = smem_u32(smc);
    float* Ex = (float*)(smc + EXOFF);
    const int tid = threadIdx.x, w = tid >> 5, l = tid & 31;
    const int dir = blockIdx.x >> 6, jb = blockIdx.x & 63;
    const int m0 = (w & 3) * 16, n0 = (w >> 2) * 16;
    const uint32_t aoff = (uint32_t)((m0 + (l & 15)) * RS + (l >> 4) * 16);
    const int brow = l & 7;
    const uint32_t bko = (uint32_t)(((l >> 3) & 1) * 16);
    const int j = tid & 7, b0 = tid >> 3;
    const int jglob = jb * 8 + j;
    const float* preB = dir ? g_GB : g_GF;
    const float* c0   = dir ? c0b  : c0f;
    const char* Wsrc = (const char*)&g_Wb0[dir][jb][0][0][0];

    float cst[2] = { c0[b0 * H + jglob], c0[(b0 + 32) * H + jglob] };

    for (int t = 0; t < S; t++) {
        int p = t & 1;
        const float* pre = preB + (size_t)(dir ? (S - 1 - t) : t) * Bz * G4;
        float pg[2][4];
#pragma unroll
        for (int r = 0; r < 2; r++) {
            const float* pb = pre + (size_t)(b0 + r * 32) * G4;
            pg[r][0] = __ldg(pb + 0 * H + jglob);
            pg[r][1] = __ldg(pb + 1 * H + jglob);
            pg[r][2] = __ldg(pb + 2 * H + jglob);
            pg[r][3] = __ldg(pb + 3 * H + jglob);
        }
        float acc0[4] = {0, 0, 0, 0}, acc1[4] = {0, 0, 0, 0};
        hmma_gemm<2, 1024, 1024>(smb, Wsrc, (const char*)&g_L0s[dir][p][0][0][0],
                                 acc0, acc1, tid, aoff, n0, brow, bko);
        store_frag(Ex, m0, n0, l, acc0, acc1);
        __syncthreads();
#pragma unroll
        for (int r = 0; r < 2; r++) {
            int b = b0 + r * 32;
            float gi = Ex[b * 36 + j]      + pg[r][0];
            float gf = Ex[b * 36 + 8 + j]  + pg[r][1];
            float gg = Ex[b * 36 + 16 + j] + pg[r][2];
            float go = Ex[b * 36 + 24 + j] + pg[r][3];
            float c2 = sigf(gf) * cst[r] + sigf(gi) * tanhf(gg);
            cst[r] = c2;
            float h = sigf(go) * tanhf(c2);
            __nv_bfloat16 hi, lo; splitw(h, hi, lo);
            size_t xe = ((size_t)t * Bz + b) * H2 + dir * H + jglob;
            g_XINs[0][xe] = hi;
            g_XINs[1][xe] = lo;
            g_L0s[dir][p ^ 1][0][b][jglob] = hi;
            g_L0s[dir][p ^ 1][1][b][jglob] = lo;
        }
        __syncthreads();
        gbar(&g_bar0[dir], 64u * (t + 1));
    }
}

// ---------------- HMMA layer-1 ------------------------------------------------
__global__ void __launch_bounds__(256, 1) k_l1_hmma(
        const float* __restrict__ c02,
        const float* __restrict__ bih2, const float* __restrict__ bhh2) {
    extern __shared__ char smc[];
    uint32_t smb = smem_u32(smc);
    float* Ex = (float*)(smc + EXOFF);
    const int tid = threadIdx.x, w = tid >> 5, l = tid & 31, bx = blockIdx.x;
    const int m0 = (w & 3) * 16, n0 = (w >> 2) * 16;
    const uint32_t aoff = (uint32_t)((m0 + (l & 15)) * RS + (l >> 4) * 16);
    const int brow = l & 7;
    const uint32_t bko = (uint32_t)(((l >> 3) & 1) * 16);
    const int j = tid & 7, b0 = tid >> 3;
    const int jglob = bx * 8 + j;

    float c2[2] = { c02[b0 * H2 + jglob], c02[(b0 + 32) * H2 + jglob] };
    float bsr[4];
#pragma unroll
    for (int g = 0; g < 4; g++) bsr[g] = bih2[g * H2 + jglob] + bhh2[g * H2 + jglob];

    for (int t = 0; t < S; t++) {
        int p = t & 1;
        float acc0[4] = {0, 0, 0, 0}, acc1[4] = {0, 0, 0, 0};
        hmma_gemm<4, 2048, 2048>(smb, (const char*)&g_Wb[0][bx][0][0][0],
                                 (const char*)&g_H1s[p][0][0][0],
                                 acc0, acc1, tid, aoff, n0, brow, bko);
        store_frag(Ex, m0, n0, l, acc0, acc1);
        __syncthreads();
#pragma unroll
        for (int r = 0; r < 2; r++) {
            int b = b0 + r * 32;
            const float* pb = g_G1 + ((size_t)t * Bz + b) * G8;
            float gi = Ex[b * 36 + j]      + __ldg(pb + 0 * H2 + jglob);
            float gf = Ex[b * 36 + 8 + j]  + __ldg(pb + 1 * H2 + jglob);
            float gg = Ex[b * 36 + 16 + j] + __ldg(pb + 2 * H2 + jglob);
            float go = Ex[b * 36 + 24 + j] + __ldg(pb + 3 * H2 + jglob);
            float cc = sigf(gf) * c2[r] + sigf(gi) * tanhf(gg);
            float h1 = sigf(go) * tanhf(cc);
            __nv_bfloat16 hi, lo; splitw(h1, hi, lo);
            g_H1s[p ^ 1][0][b][jglob] = hi;
            g_H1s[p ^ 1][1][b][jglob] = lo;
        }
        gbar(&g_bar1, 128u * (t + 1));

        acc0[0] = acc0[1] = acc0[2] = acc0[3] = 0.f;
        acc1[0] = acc1[1] = acc1[2] = acc1[3] = 0.f;
        hmma_gemm<4, 2048, 2048>(smb, (const char*)&g_Wb[1][bx][0][0][0],
                                 (const char*)&g_H2s[p][0][0][0],
                                 acc0, acc1, tid, aoff, n0, brow, bko);
        hmma_gemm<4, 2048, 2048>(smb, (const char*)&g_Wb[2][bx][0][0][0],
                                 (const char*)&g_H1s[p ^ 1][0][0][0],
                                 acc0, acc1, tid, aoff, n0, brow, bko);
        store_frag(Ex, m0, n0, l, acc0, acc1);
        __syncthreads();
#pragma unroll
        for (int r = 0; r < 2; r++) {
            int b = b0 + r * 32;
            float gi = Ex[b * 36 + j]      + bsr[0];
            float gf = Ex[b * 36 + 8 + j]  + bsr[1];
            float gg = Ex[b * 36 + 16 + j] + bsr[2];
            float go = Ex[b * 36 + 24 + j] + bsr[3];
            float cn = sigf(gf) * c2[r] + sigf(gi) * tanhf(gg);
            c2[r] = cn;
            float h2 = sigf(go) * tanhf(cn);
            __nv_bfloat16 hi, lo; splitw(h2, hi, lo);
            g_H2s[p ^ 1][0][b][jglob] = hi;
            g_H2s[p ^ 1][1][b][jglob] = lo;
            if (t == S - 1) {
                g_H2Rs[0][(size_t)b * H2 + jglob] = hi;
                g_H2Rs[1][(size_t)b * H2 + jglob] = lo;
            }
        }
        __syncthreads();
    }
}

// ---------------- launch -----------------------------------------------------
extern "C" void kernel_launch(void* const* d_in, const int* in_sizes, int n_in,
                              void* d_out, int out_size) {
    const int*   x     = (const int*)  d_in[0];
    const float* emb   = (const float*)d_in[1];
    const float* h0f   = (const float*)d_in[2];
    const float* c0f   = (const float*)d_in[3];
    const float* h0b   = (const float*)d_in[4];
    const float* c0b   = (const float*)d_in[5];
    const float* h01   = (const float*)d_in[6];
    const float* h02   = (const float*)d_in[7];
    const float* c02   = (const float*)d_in[8];
    const float* wih_f = (const float*)d_in[9];
    const float* whh_f = (const float*)d_in[10];
    const float* bih_f = (const float*)d_in[11];
    const float* bhh_f = (const float*)d_in[12];
    const float* wih_b = (const float*)d_in[13];
    const float* whh_b = (const float*)d_in[14];
    const float* bih_b = (const float*)d_in[15];
    const float* bhh_b = (const float*)d_in[16];
    const float* wih1  = (const float*)d_in[17];
    const float* whh1  = (const float*)d_in[18];
    const float* bih1  = (const float*)d_in[19];
    const float* bhh1  = (const float*)d_in[20];
    const float* wih2  = (const float*)d_in[21];
    const float* whh2  = (const float*)d_in[22];
    const float* bih2  = (const float*)d_in[23];
    const float* bhh2  = (const float*)d_in[24];
    const float* wlin  = (const float*)d_in[25];
    const float* blin  = (const float*)d_in[26];
    float* out = (float*)d_out;

    float *pGF, *pGB, *pG1;
    cudaGetSymbolAddress((void**)&pGF, g_GF);
    cudaGetSymbolAddress((void**)&pGB, g_GB);
    cudaGetSymbolAddress((void**)&pG1, g_G1);
    __nv_bfloat16 *pXs, *pXINs, *pWF, *pWB, *pW1, *pWL, *pH2Rs;
    cudaGetSymbolAddress((void**)&pXs,   g_Xs);
    cudaGetSymbolAddress((void**)&pXINs, g_XINs);
    cudaGetSymbolAddress((void**)&pWF,   g_WFs);
    cudaGetSymbolAddress((void**)&pWB,   g_WBs);
    cudaGetSymbolAddress((void**)&pW1,   g_W1s);
    cudaGetSymbolAddress((void**)&pWL,   g_WLs);
    cudaGetSymbolAddress((void**)&pH2Rs, g_H2Rs);

    const int HM_SM = 211968;
    const int GM_SM = 82432;
    cudaFuncSetAttribute(k_l0_hmma, cudaFuncAttributeMaxDynamicSharedMemorySize, HM_SM);
    cudaFuncSetAttribute(k_l1_hmma, cudaFuncAttributeMaxDynamicSharedMemorySize, HM_SM);
    cudaFuncSetAttribute(k_gemm_hmma<512>,  cudaFuncAttributeMaxDynamicSharedMemorySize, GM_SM);
    cudaFuncSetAttribute(k_gemm_hmma<1024>, cudaFuncAttributeMaxDynamicSharedMemorySize, GM_SM);

    // A: gather (split) + prep splits (also zeroes barriers + h2 pad each replay)
    k_embed<<<R, 128>>>(x, emb);
    k_prep_h0<<<256, 256>>>(h0f, h0b);
    k_prep_h<<<512, 256>>>(h01, h02);
    k_prep_w0<<<2 * 2048, 256>>>(whh_f, whh_b);
    k_prep_w<<<3 * 4096, 256>>>(whh1, whh2, wih2);
    k_prep_wih<<<8192, 256>>>(wih_f, wih_b, wih1);
    k_prep_wlin<<<V, 256>>>(wlin);

    // B: hoisted input-side gate GEMMs for layer 0 (HMMA)
    k_gemm_hmma<512><<<dim3(G4 / 128, R / 128), 256, GM_SM>>>(
        pXs, pXs + (size_t)R * H, pWF, pWF + (size_t)G4 * H, bih_f, bhh_f, pGF, G4, R);
    k_gemm_hmma<512><<<dim3(G4 / 128, R / 128), 256, GM_SM>>>(
        pXs, pXs + (size_t)R * H, pWB, pWB + (size_t)G4 * H, bih_b, bhh_b, pGB, G4, R);

    // C: HMMA persistent bidirectional layer-0 recurrence
    k_l0_hmma<<<128, 256, HM_SM>>>(c0f, c0b);

    // D: hoisted input-side GEMM for lstm1 (HMMA)
    k_gemm_hmma<1024><<<dim3(G8 / 128, R / 128), 256, GM_SM>>>(
        pXINs, pXINs + (size_t)R * H2, pW1, pW1 + (size_t)G8 * H2, bih1, bhh1, pG1, G8, R);

    // E: HMMA persistent layer-1 recurrence
    k_l1_hmma<<<128, 256, HM_SM>>>(c02, bih2, bhh2);

    // F: logits (HMMA, padded M=128, valid M=64)
    k_gemm_hmma<1024><<<dim3(V / 128, 1), 256, GM_SM>>>(
        pH2Rs, pH2Rs + (size_t)128 * H2, pWL, pWL + (size_t)V * H2,
        blin, nullptr, out, V, Bz);
}

// round 16
// speedup vs baseline: 4.3932x; 1.0176x over previous
#include <cuda_runtime.h>
#include <cuda_bf16.h>
#include <cstdint>

#define DEV_INLINE __device__ __forceinline__
typedef unsigned long long u64;

static constexpr int V  = 32000;
static constexpr int H  = 512;
static constexpr int Bz = 64;
static constexpr int S  = 128;
static constexpr int H2 = 1024;
static constexpr int G4 = 2048;
static constexpr int G8 = 4096;
static constexpr int R  = S * Bz;

// ---------------- scratch ---------------------------------------------------
__device__ float g_GF  [R * G4];
__device__ float g_GB  [R * G4];
__device__ float g_G1  [R * G8];
__device__ __align__(16) __nv_bfloat16 g_Xs  [2][R * H];
__device__ __align__(16) __nv_bfloat16 g_XINs[2][R * H2];
__device__ __align__(16) __nv_bfloat16 g_WFs[2][G4 * H];
__device__ __align__(16) __nv_bfloat16 g_WBs[2][G4 * H];
__device__ __align__(16) __nv_bfloat16 g_W1s[2][G8 * H2];
__device__ __align__(16) __nv_bfloat16 g_WLs[2][(size_t)V * H2];
__device__ __align__(16) __nv_bfloat16 g_H2Rs[2][128 * H2];
__device__ __align__(16) __nv_bfloat16 g_Wb [3][128][2][32][1024];
__device__ __align__(16) __nv_bfloat16 g_Wb0[2][64][2][32][512];
__device__ __align__(16) __nv_bfloat16 g_H1s[2][2][Bz][H2];
__device__ __align__(16) __nv_bfloat16 g_H2s[2][2][Bz][H2];
__device__ __align__(16) __nv_bfloat16 g_L0s[2][2][2][Bz][H];
__device__ unsigned g_bar0[2];
__device__ unsigned g_bar1;

// ---------------- helpers ---------------------------------------------------
DEV_INLINE u64 pk2(float x, float y) {
    u64 r; asm("mov.b64 %0, {%1, %2};" : "=l"(r) : "f"(x), "f"(y)); return r;
}
DEV_INLINE float2 upk2(u64 v) {
    float2 r; asm("mov.b64 {%0, %1}, %2;" : "=f"(r.x), "=f"(r.y) : "l"(v)); return r;
}
#define FMA2(d, a, b) asm("fma.rn.f32x2 %0, %1, %2, %0;" : "+l"(d) : "l"(a), "l"(b))
DEV_INLINE float sigf(float x) { return 1.f / (1.f + expf(-x)); }

DEV_INLINE void gbar(unsigned* cnt, unsigned target) {
    __threadfence();
    __syncthreads();
    if (threadIdx.x == 0) {
        atomicAdd(cnt, 1u);
        while (*(volatile unsigned*)cnt < target) __nanosleep(32);
    }
    __syncthreads();
}

DEV_INLINE uint32_t smem_u32(const void* p) {
    uint32_t a;
    asm("{ .reg .u64 t; cvta.to.shared.u64 t, %1; cvt.u32.u64 %0, t; }" : "=r"(a) : "l"(p));
    return a;
}
DEV_INLINE void cpa16(uint32_t dst, const void* src) {
    asm volatile("cp.async.cg.shared.global [%0], [%1], 16;" :: "r"(dst), "l"(src) : "memory");
}
#define CP_COMMIT() asm volatile("cp.async.commit_group;" ::: "memory")
template <int N> DEV_INLINE void cp_wait() {
    asm volatile("cp.async.wait_group %0;" :: "n"(N) : "memory");
}
DEV_INLINE void ldsm_x4(uint32_t& a0, uint32_t& a1, uint32_t& a2, uint32_t& a3, uint32_t ad) {
    asm volatile("ldmatrix.sync.aligned.m8n8.x4.shared.b16 {%0,%1,%2,%3}, [%4];"
                 : "=r"(a0), "=r"(a1), "=r"(a2), "=r"(a3) : "r"(ad));
}
DEV_INLINE void ldsm_x2(uint32_t& b0, uint32_t& b1, uint32_t ad) {
    asm volatile("ldmatrix.sync.aligned.m8n8.x2.shared.b16 {%0,%1}, [%2];"
                 : "=r"(b0), "=r"(b1) : "r"(ad));
}
DEV_INLINE void mma16816(float* c, uint32_t a0, uint32_t a1, uint32_t a2, uint32_t a3,
                         uint32_t b0, uint32_t b1) {
    asm volatile("mma.sync.aligned.m16n8k16.row.col.f32.bf16.bf16.f32 "
                 "{%0,%1,%2,%3}, {%4,%5,%6,%7}, {%8,%9}, {%0,%1,%2,%3};"
                 : "+f"(c[0]), "+f"(c[1]), "+f"(c[2]), "+f"(c[3])
                 : "r"(a0), "r"(a1), "r"(a2), "r"(a3), "r"(b0), "r"(b1));
}
DEV_INLINE void splitw(float v, __nv_bfloat16& hi, __nv_bfloat16& lo) {
    hi = __float2bfloat16(v);
    lo = __float2bfloat16(v - __bfloat162float(hi));
}

// ---------------- small kernels ----------------------------------------------
__global__ void k_embed(const int* __restrict__ x, const float* __restrict__ emb) {
    int r = blockIdx.x;
    int tok = x[r];
    float4 v = make_float4(0.f, 0.f, 0.f, 0.f);
    if (tok != 0) v = *(const float4*)(emb + (size_t)tok * H + threadIdx.x * 4);
    size_t base = (size_t)r * H + threadIdx.x * 4;
    float vv[4] = {v.x, v.y, v.z, v.w};
#pragma unroll
    for (int i = 0; i < 4; i++) {
        __nv_bfloat16 hi, lo; splitw(vv[i], hi, lo);
        g_Xs[0][base + i] = hi;
        g_Xs[1][base + i] = lo;
    }
}

__global__ void k_prep_wih(const float* __restrict__ wih_f, const float* __restrict__ wih_b,
                           const float* __restrict__ wih1) {
    int r = blockIdx.x;                       // [0, 8192)
    const float* src; __nv_bfloat16 *dh, *dl; int K;
    if (r < 2048)      { src = wih_f + (size_t)r * H;  dh = &g_WFs[0][(size_t)r * H];  dl = &g_WFs[1][(size_t)r * H];  K = H; }
    else if (r < 4096) { int q = r - 2048; src = wih_b + (size_t)q * H;  dh = &g_WBs[0][(size_t)q * H];  dl = &g_WBs[1][(size_t)q * H];  K = H; }
    else               { int q = r - 4096; src = wih1 + (size_t)q * H2; dh = &g_W1s[0][(size_t)q * H2]; dl = &g_W1s[1][(size_t)q * H2]; K = H2; }
    for (int k = threadIdx.x; k < K; k += 256) {
        __nv_bfloat16 hi, lo; splitw(src[k], hi, lo);
        dh[k] = hi; dl[k] = lo;
    }
}

__global__ void k_prep_wlin(const float* __restrict__ wlin) {
    int r = blockIdx.x;                       // [0, 32000)
    const float* src = wlin + (size_t)r * H2;
    size_t o = (size_t)r * H2;
#pragma unroll
    for (int q = 0; q < 4; q++) {
        int k = threadIdx.x + q * 256;
        __nv_bfloat16 hi, lo; splitw(src[k], hi, lo);
        g_WLs[0][o + k] = hi;
        g_WLs[1][o + k] = lo;
    }
}

__global__ void k_prep_w(const float* __restrict__ whh1, const float* __restrict__ whh2,
                         const float* __restrict__ wih2) {
    int mr = blockIdx.x;                      // [0, 3*4096)
    int mat = mr >> 12, r = mr & 4095;
    const float* W = mat == 0 ? whh1 : (mat == 1 ? whh2 : wih2);
    int g = r >> 10, jglob = r & 1023;
    int bx = jglob >> 3, gr = g * 8 + (jglob & 7);
    const float* src = W + (size_t)r * H2;
#pragma unroll
    for (int q = 0; q < 4; q++) {
        int k = threadIdx.x + q * 256;
        __nv_bfloat16 hi, lo; splitw(src[k], hi, lo);
        g_Wb[mat][bx][0][gr][k] = hi;
        g_Wb[mat][bx][1][gr][k] = lo;
    }
}

__global__ void k_prep_w0(const float* __restrict__ whh_f, const float* __restrict__ whh_b) {
    int mr = blockIdx.x;                      // [0, 2*2048)
    int dir = mr >> 11, r = mr & 2047;
    const float* W = dir ? whh_b : whh_f;
    int g = r >> 9, j = r & 511;
    int bx = j >> 3, gr = g * 8 + (j & 7);
    const float* src = W + (size_t)r * H;
#pragma unroll
    for (int q = 0; q < 2; q++) {
        int k = threadIdx.x + q * 256;
        __nv_bfloat16 hi, lo; splitw(src[k], hi, lo);
        g_Wb0[dir][bx][0][gr][k] = hi;
        g_Wb0[dir][bx][1][gr][k] = lo;
    }
}

__global__ void k_prep_h(const float* __restrict__ h01, const float* __restrict__ h02) {
    int i = blockIdx.x * 256 + threadIdx.x;   // [0, 131072)
    int which = i >> 16, e = i & 65535;
    int b = e >> 10, k = e & 1023;
    __nv_bfloat16 hi, lo; splitw((which ? h02 : h01)[e], hi, lo);
    if (which) { g_H2s[0][0][b][k] = hi; g_H2s[0][1][b][k] = lo; }
    else       { g_H1s[0][0][b][k] = hi; g_H1s[0][1][b][k] = lo; }
}

__global__ void k_prep_h0(const float* __restrict__ h0f, const float* __restrict__ h0b) {
    int i = blockIdx.x * 256 + threadIdx.x;   // [0, 65536)
    if (i == 0) { g_bar0[0] = 0u; g_bar0[1] = 0u; g_bar1 = 0u; }
    g_H2Rs[0][65536 + i] = __float2bfloat16(0.f);
    g_H2Rs[1][65536 + i] = __float2bfloat16(0.f);
    int dir = i >> 15, e = i & 32767;
    int b = e >> 9, k = e & 511;
    __nv_bfloat16 hi, lo; splitw((dir ? h0b : h0f)[e], hi, lo);
    g_L0s[dir][0][0][b][k] = hi;
    g_L0s[dir][0][1][b][k] = lo;
}

// ---------------- batched split-bf16 HMMA GEMM (phases B, D, F) ---------------
template <int K>
DEV_INLINE void ldc_g(uint32_t smb, int buf,
                      const char* Ahi, const char* Alo,
                      const char* Whi, const char* Wlo,
                      int bm, int bn, int c, int tid) {
#pragma unroll
    for (int q = 0; q < 8; q++) {
        int i = tid + q * 256;
        int sp = (i & 1023) >> 9, rem = i & 511, row = rem >> 2, sg = rem & 3;
        if (i < 1024) {
            const char* src = (sp ? Alo : Ahi) + (size_t)(bm + row) * (K * 2) + c * 64 + sg * 16;
            cpa16(smb + buf * 20480 + sp * 10240 + row * 80 + sg * 16, src);
        } else {
            const char* src = (sp ? Wlo : Whi) + (size_t)(bn + row) * (K * 2) + c * 64 + sg * 16;
            cpa16(smb + 40960 + buf * 20480 + sp * 10240 + row * 80 + sg * 16, src);
        }
    }
    CP_COMMIT();
}

template <int K>
__global__ void __launch_bounds__(256, 2) k_gemm_hmma(
        const __nv_bfloat16* __restrict__ Ahi, const __nv_bfloat16* __restrict__ Alo,
        const __nv_bfloat16* __restrict__ Whi, const __nv_bfloat16* __restrict__ Wlo,
        const float* __restrict__ b1, const float* __restrict__ b2,
        float* __restrict__ C, int N, int Mvalid) {
    extern __shared__ char smc[];
    uint32_t smb = smem_u32(smc);
    float* bsum = (float*)(smc + 81920);
    const int tid = threadIdx.x, w = tid >> 5, l = tid & 31;
    const int bm = blockIdx.y * 128, bn = blockIdx.x * 128;
    const int m0w = (w & 3) * 32, n0w = (w >> 2) * 64;

    if (tid < 128) bsum[tid] = b1[bn + tid] + (b2 ? b2[bn + tid] : 0.f);

    float acc[2][8][4];
#pragma unroll
    for (int mt = 0; mt < 2; mt++)
#pragma unroll
        for (int nf = 0; nf < 8; nf++)
#pragma unroll
            for (int i = 0; i < 4; i++) acc[mt][nf][i] = 0.f;

    ldc_g<K>(smb, 0, (const char*)Ahi, (const char*)Alo,
             (const char*)Whi, (const char*)Wlo, bm, bn, 0, tid);
    constexpr int NCH = K / 32;
    for (int c = 0; c < NCH; c++) {
        if (c < NCH - 1) {
            ldc_g<K>(smb, (c + 1) & 1, (const char*)Ahi, (const char*)Alo,
                     (const char*)Whi, (const char*)Wlo, bm, bn, c + 1, tid);
            cp_wait<1>();
        } else cp_wait<0>();
        __syncthreads();
        uint32_t ab = smb + (c & 1) * 20480;
        uint32_t wb = smb + 40960 + (c & 1) * 20480;
#pragma unroll
        for (int ks = 0; ks < 2; ks++) {
            uint32_t ah[2][4], al[2][4];
#pragma unroll
            for (int mt = 0; mt < 2; mt++) {
                uint32_t aa = ab + (uint32_t)(m0w + mt * 16 + (l & 15)) * 80 + (l >> 4) * 16 + ks * 32;
                ldsm_x4(ah[mt][0], ah[mt][1], ah[mt][2], ah[mt][3], aa);
                ldsm_x4(al[mt][0], al[mt][1], al[mt][2], al[mt][3], aa + 10240);
            }
#pragma unroll
            for (int nf = 0; nf < 8; nf++) {
                uint32_t bb = wb + (uint32_t)(n0w + nf * 8 + (l & 7)) * 80 + ((l >> 3) & 1) * 16 + ks * 32;
                uint32_t bh0, bh1, bl0, bl1;
                ldsm_x2(bh0, bh1, bb);
                ldsm_x2(bl0, bl1, bb + 10240);
#pragma unroll
                for (int mt = 0; mt < 2; mt++) {
                    mma16816(acc[mt][nf], ah[mt][0], ah[mt][1], ah[mt][2], ah[mt][3], bh0, bh1);
                    mma16816(acc[mt][nf], al[mt][0], al[mt][1], al[mt][2], al[mt][3], bh0, bh1);
                    mma16816(acc[mt][nf], ah[mt][0], ah[mt][1], ah[mt][2], ah[mt][3], bl0, bl1);
                }
            }
        }
        __syncthreads();
    }
#pragma unroll
    for (int mt = 0; mt < 2; mt++) {
        int row = bm + m0w + mt * 16 + (l >> 2);
#pragma unroll
        for (int nf = 0; nf < 8; nf++) {
            int lc = n0w + nf * 8 + (l & 3) * 2;
            float bs0 = bsum[lc], bs1 = bsum[lc + 1];
            if (row < Mvalid)
                *(float2*)(C + (size_t)row * N + bn + lc) =
                    make_float2(acc[mt][nf][0] + bs0, acc[mt][nf][1] + bs1);
            if (row + 8 < Mvalid)
                *(float2*)(C + (size_t)(row + 8) * N + bn + lc) =
                    make_float2(acc[mt][nf][2] + bs0, acc[mt][nf][3] + bs1);
        }
    }
}

// ---------------- shared recurrent HMMA constants (chunk k=256) ----------------
static constexpr int RS   = 528;
static constexpr int HSPL = 64 * RS;     // 33792
static constexpr int HBUF = 2 * HSPL;    // 67584
static constexpr int WBASE = 2 * HBUF;   // 135168
static constexpr int WSPL = 32 * RS;     // 16896
static constexpr int WBUF = 2 * WSPL;    // 33792
static constexpr int EXOFF = WBASE + 2 * WBUF;  // 202752; total 211968

// H-only chunk load (l0; W resident) -------------------------------------------
DEV_INLINE void load_h_l0(uint32_t smb, int buf, const char* Hsrc, int c, int tid) {
#pragma unroll
    for (int q = 0; q < 16; q++) {
        int i = tid + q * 256;
        int sp = i >> 11, rem = i & 2047, row = rem >> 5, sg = rem & 31;
        cpa16(smb + buf * HBUF + sp * HSPL + row * RS + sg * 16,
              Hsrc + (size_t)sp * (64 * 1024) + row * 1024 + c * 512 + sg * 16);
    }
    CP_COMMIT();
}

// combined W+H chunk load (l1) ---------------------------------------------------
DEV_INLINE void load_chunk_l1(uint32_t smb, int buf, const char* Wsrc, const char* Hsrc,
                              int c, int tid) {
#pragma unroll
    for (int q = 0; q < 24; q++) {
        int i = tid + q * 256;
        if (i < 4096) {
            int sp = i >> 11, rem = i & 2047, row = rem >> 5, sg = rem & 31;
            cpa16(smb + buf * HBUF + sp * HSPL + row * RS + sg * 16,
                  Hsrc + (size_t)sp * (64 * 2048) + row * 2048 + c * 512 + sg * 16);
        } else {
            int jj = i - 4096, sp = jj >> 10, rem = jj & 1023, row = rem >> 5, sg = rem & 31;
            cpa16(smb + WBASE + buf * WBUF + sp * WSPL + row * RS + sg * 16,
                  Wsrc + (size_t)sp * (32 * 2048) + row * 2048 + c * 512 + sg * 16);
        }
    }
    CP_COMMIT();
}

// l1 GEMM with per-chunk W/H source selection (fused multi-matrix pass)
template <int NCH>
DEV_INLINE void hmma_gemm_l1(uint32_t smb, const char* W0, const char* H0,
                             const char* W1, const char* H1,
                             float* acc0, float* acc1, int tid,
                             uint32_t aoff, int n0, int brow, uint32_t bko) {
    load_chunk_l1(smb, 0, W0, H0, 0, tid);
    for (int c = 0; c < NCH; c++) {
        if (c < NCH - 1) {
            int cn = c + 1;
            const char* Wn = (cn < 4) ? W0 : W1;
            const char* Hn = (cn < 4) ? H0 : H1;
            load_chunk_l1(smb, cn & 1, Wn, Hn, cn & 3, tid);
            cp_wait<1>();
        } else cp_wait<0>();
        __syncthreads();
        uint32_t hb = smb + (c & 1) * HBUF;
        uint32_t wb = smb + WBASE + (c & 1) * WBUF;
#pragma unroll
        for (int ks = 0; ks < 16; ks++) {
            uint32_t a0, a1, a2, a3, l0r, l1r, l2r, l3r;
            ldsm_x4(a0, a1, a2, a3, hb + aoff + ks * 32);
            ldsm_x4(l0r, l1r, l2r, l3r, hb + HSPL + aoff + ks * 32);
#pragma unroll
            for (int nt = 0; nt < 2; nt++) {
                uint32_t bh0, bh1, bl0, bl1;
                uint32_t bb = wb + (uint32_t)(n0 + nt * 8 + brow) * RS + bko + ks * 32;
                ldsm_x2(bh0, bh1, bb);
                ldsm_x2(bl0, bl1, bb + WSPL);
                float* ac = nt ? acc1 : acc0;
                mma16816(ac, a0, a1, a2, a3, bh0, bh1);
                mma16816(ac, l0r, l1r, l2r, l3r, bh0, bh1);
                mma16816(ac, a0, a1, a2, a3, bl0, bl1);
            }
        }
        __syncthreads();
    }
}

DEV_INLINE void store_frag(float* Ex, int m0, int n0, int l, const float* ac0, const float* ac1) {
#pragma unroll
    for (int nt = 0; nt < 2; nt++) {
        const float* ac = nt ? ac1 : ac0;
        int er = m0 + (l >> 2), ec = n0 + nt * 8 + (l & 3) * 2;
        Ex[er * 36 + ec] = ac[0];       Ex[er * 36 + ec + 1] = ac[1];
        Ex[(er + 8) * 36 + ec] = ac[2]; Ex[(er + 8) * 36 + ec + 1] = ac[3];
    }
}

// ---------------- HMMA layer-0 (W resident in SMEM) ----------------------------
__global__ void __launch_bounds__(256, 1) k_l0_hmma(
        const float* __restrict__ c0f, const float* __restrict__ c0b) {
    extern __shared__ char smc[];
    uint32_t smb = smem_u32(smc);
    float* Ex = (float*)(smc + EXOFF);
    const int tid = threadIdx.x, w = tid >> 5, l = tid & 31;
    const int dir = blockIdx.x >> 6, jb = blockIdx.x & 63;
    const int m0 = (w & 3) * 16, n0 = (w >> 2) * 16;
    const uint32_t aoff = (uint32_t)((m0 + (l & 15)) * RS + (l >> 4) * 16);
    const int brow = l & 7;
    const uint32_t bko = (uint32_t)(((l >> 3) & 1) * 16);
    const int j = tid & 7, b0 = tid >> 3;
    const int jglob = jb * 8 + j;
    const float* preB = dir ? g_GB : g_GF;
    const float* c0   = dir ? c0b  : c0f;
    const char* Wsrc = (const char*)&g_Wb0[dir][jb][0][0][0];

    // preload BOTH W chunk-images into resident SMEM (at WBASE, chunk c at +c*WBUF... reuse WBUF slots)
#pragma unroll
    for (int q = 0; q < 16; q++) {
        int i = tid + q * 256;                // [0, 4096)
        int c = i >> 11, rem = i & 2047;
        int sp = rem >> 10, r2 = rem & 1023, row = r2 >> 5, sg = r2 & 31;
        cpa16(smb + WBASE + c * WBUF + sp * WSPL + row * RS + sg * 16,
              Wsrc + (size_t)sp * (32 * 1024) + row * 1024 + c * 512 + sg * 16);
    }
    CP_COMMIT();
    cp_wait<0>();
    __syncthreads();

    float cst[2] = { c0[b0 * H + jglob], c0[(b0 + 32) * H + jglob] };

    for (int t = 0; t < S; t++) {
        int p = t & 1;
        const float* pre = preB + (size_t)(dir ? (S - 1 - t) : t) * Bz * G4;
        float pg[2][4];
#pragma unroll
        for (int r = 0; r < 2; r++) {
            const float* pb = pre + (size_t)(b0 + r * 32) * G4;
            pg[r][0] = __ldg(pb + 0 * H + jglob);
            pg[r][1] = __ldg(pb + 1 * H + jglob);
            pg[r][2] = __ldg(pb + 2 * H + jglob);
            pg[r][3] = __ldg(pb + 3 * H + jglob);
        }
        const char* Hsrc = (const char*)&g_L0s[dir][p][0][0][0];
        float acc0[4] = {0, 0, 0, 0}, acc1[4] = {0, 0, 0, 0};
        load_h_l0(smb, 0, Hsrc, 0, tid);
        for (int c = 0; c < 2; c++) {
            if (c == 0) { load_h_l0(smb, 1, Hsrc, 1, tid); cp_wait<1>(); }
            else cp_wait<0>();
            __syncthreads();
            uint32_t hb = smb + c * HBUF;
            uint32_t wb = smb + WBASE + c * WBUF;
#pragma unroll
            for (int ks = 0; ks < 16; ks++) {
                uint32_t a0, a1, a2, a3, l0r, l1r, l2r, l3r;
                ldsm_x4(a0, a1, a2, a3, hb + aoff + ks * 32);
                ldsm_x4(l0r, l1r, l2r, l3r, hb + HSPL + aoff + ks * 32);
#pragma unroll
                for (int nt = 0; nt < 2; nt++) {
                    uint32_t bh0, bh1, bl0, bl1;
                    uint32_t bb = wb + (uint32_t)(n0 + nt * 8 + brow) * RS + bko + ks * 32;
                    ldsm_x2(bh0, bh1, bb);
                    ldsm_x2(bl0, bl1, bb + WSPL);
                    float* ac = nt ? acc1 : acc0;
                    mma16816(ac, a0, a1, a2, a3, bh0, bh1);
                    mma16816(ac, l0r, l1r, l2r, l3r, bh0, bh1);
                    mma16816(ac, a0, a1, a2, a3, bl0, bl1);
                }
            }
            __syncthreads();
        }
        store_frag(Ex, m0, n0, l, acc0, acc1);
        __syncthreads();
#pragma unroll
        for (int r = 0; r < 2; r++) {
            int b = b0 + r * 32;
            float gi = Ex[b * 36 + j]      + pg[r][0];
            float gf = Ex[b * 36 + 8 + j]  + pg[r][1];
            float gg = Ex[b * 36 + 16 + j] + pg[r][2];
            float go = Ex[b * 36 + 24 + j] + pg[r][3];
            float c2 = sigf(gf) * cst[r] + sigf(gi) * tanhf(gg);
            cst[r] = c2;
            float h = sigf(go) * tanhf(c2);
            __nv_bfloat16 hi, lo; splitw(h, hi, lo);
            size_t xe = ((size_t)t * Bz + b) * H2 + dir * H + jglob;
            g_XINs[0][xe] = hi;
            g_XINs[1][xe] = lo;
            g_L0s[dir][p ^ 1][0][b][jglob] = hi;
            g_L0s[dir][p ^ 1][1][b][jglob] = lo;
        }
        __syncthreads();
        gbar(&g_bar0[dir], 64u * (t + 1));
    }
}

// ---------------- HMMA layer-1 (fused lstm2 pass, prefetched pre-gates) --------
__global__ void __launch_bounds__(256, 1) k_l1_hmma(
        const float* __restrict__ c02,
        const float* __restrict__ bih2, const float* __restrict__ bhh2) {
    extern __shared__ char smc[];
    uint32_t smb = smem_u32(smc);
    float* Ex = (float*)(smc + EXOFF);
    const int tid = threadIdx.x, w = tid >> 5, l = tid & 31, bx = blockIdx.x;
    const int m0 = (w & 3) * 16, n0 = (w >> 2) * 16;
    const uint32_t aoff = (uint32_t)((m0 + (l & 15)) * RS + (l >> 4) * 16);
    const int brow = l & 7;
    const uint32_t bko = (uint32_t)(((l >> 3) & 1) * 16);
    const int j = tid & 7, b0 = tid >> 3;
    const int jglob = bx * 8 + j;

    float c2[2] = { c02[b0 * H2 + jglob], c02[(b0 + 32) * H2 + jglob] };
    float bsr[4];
#pragma unroll
    for (int g = 0; g < 4; g++) bsr[g] = bih2[g * H2 + jglob] + bhh2[g * H2 + jglob];

    for (int t = 0; t < S; t++) {
        int p = t & 1;
        // prefetch DRAM-resident G1 pre-gates before the GEMM
        float pg[2][4];
#pragma unroll
        for (int r = 0; r < 2; r++) {
            const float* pb = g_G1 + ((size_t)t * Bz + b0 + r * 32) * G8;
            pg[r][0] = __ldg(pb + 0 * H2 + jglob);
            pg[r][1] = __ldg(pb + 1 * H2 + jglob);
            pg[r][2] = __ldg(pb + 2 * H2 + jglob);
            pg[r][3] = __ldg(pb + 3 * H2 + jglob);
        }
        // ---- lstm1: whh1 @ h1prev ----
        float acc0[4] = {0, 0, 0, 0}, acc1[4] = {0, 0, 0, 0};
        hmma_gemm_l1<4>(smb, (const char*)&g_Wb[0][bx][0][0][0],
                        (const char*)&g_H1s[p][0][0][0],
                        nullptr, nullptr,
                        acc0, acc1, tid, aoff, n0, brow, bko);
        store_frag(Ex, m0, n0, l, acc0, acc1);
        __syncthreads();
#pragma unroll
        for (int r = 0; r < 2; r++) {
            int b = b0 + r * 32;
            float gi = Ex[b * 36 + j]      + pg[r][0];
            float gf = Ex[b * 36 + 8 + j]  + pg[r][1];
            float gg = Ex[b * 36 + 16 + j] + pg[r][2];
            float go = Ex[b * 36 + 24 + j] + pg[r][3];
            float cc = sigf(gf) * c2[r] + sigf(gi) * tanhf(gg);
            float h1 = sigf(go) * tanhf(cc);
            __nv_bfloat16 hi, lo; splitw(h1, hi, lo);
            g_H1s[p ^ 1][0][b][jglob] = hi;
            g_H1s[p ^ 1][1][b][jglob] = lo;
        }
        gbar(&g_bar1, 128u * (t + 1));

        // ---- lstm2: fused 8-chunk pass (whh2@h2prev then wih2@h1new) ----
        acc0[0] = acc0[1] = acc0[2] = acc0[3] = 0.f;
        acc1[0] = acc1[1] = acc1[2] = acc1[3] = 0.f;
        hmma_gemm_l1<8>(smb, (const char*)&g_Wb[1][bx][0][0][0],
                        (const char*)&g_H2s[p][0][0][0],
                        (const char*)&g_Wb[2][bx][0][0][0],
                        (const char*)&g_H1s[p ^ 1][0][0][0],
                        acc0, acc1, tid, aoff, n0, brow, bko);
        store_frag(Ex, m0, n0, l, acc0, acc1);
        __syncthreads();
#pragma unroll
        for (int r = 0; r < 2; r++) {
            int b = b0 + r * 32;
            float gi = Ex[b * 36 + j]      + bsr[0];
            float gf = Ex[b * 36 + 8 + j]  + bsr[1];
            float gg = Ex[b * 36 + 16 + j] + bsr[2];
            float go = Ex[b * 36 + 24 + j] + bsr[3];
            float cn = sigf(gf) * c2[r] + sigf(gi) * tanhf(gg);
            c2[r] = cn;
            float h2 = sigf(go) * tanhf(cn);
            __nv_bfloat16 hi, lo; splitw(h2, hi, lo);
            g_H2s[p ^ 1][0][b][jglob] = hi;
            g_H2s[p ^ 1][1][b][jglob] = lo;
            if (t == S - 1) {
                g_H2Rs[0][(size_t)b * H2 + jglob] = hi;
                g_H2Rs[1][(size_t)b * H2 + jglob] = lo;
            }
        }
        __syncthreads();
    }
}

// ---------------- launch -----------------------------------------------------
extern "C" void kernel_launch(void* const* d_in, const int* in_sizes, int n_in,
                              void* d_out, int out_size) {
    const int*   x     = (const int*)  d_in[0];
    const float* emb   = (const float*)d_in[1];
    const float* h0f   = (const float*)d_in[2];
    const float* c0f   = (const float*)d_in[3];
    const float* h0b   = (const float*)d_in[4];
    const float* c0b   = (const float*)d_in[5];
    const float* h01   = (const float*)d_in[6];
    const float* h02   = (const float*)d_in[7];
    const float* c02   = (const float*)d_in[8];
    const float* wih_f = (const float*)d_in[9];
    const float* whh_f = (const float*)d_in[10];
    const float* bih_f = (const float*)d_in[11];
    const float* bhh_f = (const float*)d_in[12];
    const float* wih_b = (const float*)d_in[13];
    const float* whh_b = (const float*)d_in[14];
    const float* bih_b = (const float*)d_in[15];
    const float* bhh_b = (const float*)d_in[16];
    const float* wih1  = (const float*)d_in[17];
    const float* whh1  = (const float*)d_in[18];
    const float* bih1  = (const float*)d_in[19];
    const float* bhh1  = (const float*)d_in[20];
    const float* wih2  = (const float*)d_in[21];
    const float* whh2  = (const float*)d_in[22];
    const float* bih2  = (const float*)d_in[23];
    const float* bhh2  = (const float*)d_in[24];
    const float* wlin  = (const float*)d_in[25];
    const float* blin  = (const float*)d_in[26];
    float* out = (float*)d_out;

    float *pGF, *pGB, *pG1;
    cudaGetSymbolAddress((void**)&pGF, g_GF);
    cudaGetSymbolAddress((void**)&pGB, g_GB);
    cudaGetSymbolAddress((void**)&pG1, g_G1);
    __nv_bfloat16 *pXs, *pXINs, *pWF, *pWB, *pW1, *pWL, *pH2Rs;
    cudaGetSymbolAddress((void**)&pXs,   g_Xs);
    cudaGetSymbolAddress((void**)&pXINs, g_XINs);
    cudaGetSymbolAddress((void**)&pWF,   g_WFs);
    cudaGetSymbolAddress((void**)&pWB,   g_WBs);
    cudaGetSymbolAddress((void**)&pW1,   g_W1s);
    cudaGetSymbolAddress((void**)&pWL,   g_WLs);
    cudaGetSymbolAddress((void**)&pH2Rs, g_H2Rs);

    const int HM_SM = 211968;
    const int GM_SM = 82432;
    cudaFuncSetAttribute(k_l0_hmma, cudaFuncAttributeMaxDynamicSharedMemorySize, HM_SM);
    cudaFuncSetAttribute(k_l1_hmma, cudaFuncAttributeMaxDynamicSharedMemorySize, HM_SM);
    cudaFuncSetAttribute(k_gemm_hmma<512>,  cudaFuncAttributeMaxDynamicSharedMemorySize, GM_SM);
    cudaFuncSetAttribute(k_gemm_hmma<1024>, cudaFuncAttributeMaxDynamicSharedMemorySize, GM_SM);

    // A: gather (split) + prep splits (also zeroes barriers + h2 pad each replay)
    k_embed<<<R, 128>>>(x, emb);
    k_prep_h0<<<256, 256>>>(h0f, h0b);
    k_prep_h<<<512, 256>>>(h01, h02);
    k_prep_w0<<<2 * 2048, 256>>>(whh_f, whh_b);
    k_prep_w<<<3 * 4096, 256>>>(whh1, whh2, wih2);
    k_prep_wih<<<8192, 256>>>(wih_f, wih_b, wih1);
    k_prep_wlin<<<V, 256>>>(wlin);

    // B: hoisted input-side gate GEMMs for layer 0 (HMMA)
    k_gemm_hmma<512><<<dim3(G4 / 128, R / 128), 256, GM_SM>>>(
        pXs, pXs + (size_t)R * H, pWF, pWF + (size_t)G4 * H, bih_f, bhh_f, pGF, G4, R);
    k_gemm_hmma<512><<<dim3(G4 / 128, R / 128), 256, GM_SM>>>(
        pXs, pXs + (size_t)R * H, pWB, pWB + (size_t)G4 * H, bih_b, bhh_b, pGB, G4, R);

    // C: HMMA persistent bidirectional layer-0 recurrence (W resident)
    k_l0_hmma<<<128, 256, HM_SM>>>(c0f, c0b);

    // D: hoisted input-side GEMM for lstm1 (HMMA)
    k_gemm_hmma<1024><<<dim3(G8 / 128, R / 128), 256, GM_SM>>>(
        pXINs, pXINs + (size_t)R * H2, pW1, pW1 + (size_t)G8 * H2, bih1, bhh1, pG1, G8, R);

    // E: HMMA persistent layer-1 recurrence (fused lstm2 pass)
    k_l1_hmma<<<128, 256, HM_SM>>>(c02, bih2, bhh2);

    // F: logits (HMMA, padded M=128, valid M=64)
    k_gemm_hmma<1024><<<dim3(V / 128, 1), 256, GM_SM>>>(
        pH2Rs, pH2Rs + (size_t)128 * H2, pWL, pWL + (size_t)V * H2,
        blin, nullptr, out, V, Bz);
}